// round 1
// baseline (speedup 1.0000x reference)
#include <cuda_runtime.h>
#include <cuda_bf16.h>
#include <math.h>

// Problem dims (fixed)
#define BB 2
#define SS 2048
#define HH 1024
#define NHH 16
#define DHH 64
#define FFF 4096
#define MM (BB*SS)   // 4096 tokens

// ---------------- scratch (device globals; no allocation allowed) ----------
__device__ float g_ln1 [MM*HH];
__device__ float g_q   [MM*HH];
__device__ float g_k   [MM*HH];
__device__ float g_v   [MM*HH];
__device__ float g_attn[MM*HH];
__device__ float g_xatt[MM*HH];
__device__ float g_ln2 [MM*HH];
__device__ float g_mid [MM*FFF];

// ---------------- layernorm ------------------------------------------------
__device__ __forceinline__ float block_reduce_sum(float v) {
    __shared__ float sh[8];
    int lane = threadIdx.x & 31, w = threadIdx.x >> 5;
    #pragma unroll
    for (int o = 16; o > 0; o >>= 1) v += __shfl_xor_sync(0xffffffffu, v, o);
    if (lane == 0) sh[w] = v;
    __syncthreads();
    float t = (threadIdx.x < 8) ? sh[threadIdx.x] : 0.0f;
    if (w == 0) {
        #pragma unroll
        for (int o = 4; o > 0; o >>= 1) t += __shfl_xor_sync(0xffffffffu, t, o);
        if (lane == 0) sh[0] = t;
    }
    __syncthreads();
    float r = sh[0];
    __syncthreads();   // allow safe reuse of sh by a following reduction
    return r;
}

__global__ void ln_kernel(const float* __restrict__ x,
                          const float* __restrict__ g,
                          const float* __restrict__ be,
                          float* __restrict__ out) {
    int row = blockIdx.x;                 // 0..4095
    int t = threadIdx.x;                  // 256 threads, 4 floats each
    const float4* xr = (const float4*)(x + (size_t)row * HH);
    float4 v = xr[t];
    float s = v.x + v.y + v.z + v.w;
    float mu = block_reduce_sum(s) * (1.0f / HH);
    float dx = v.x - mu, dy = v.y - mu, dz = v.z - mu, dw = v.w - mu;
    float ss = dx*dx + dy*dy + dz*dz + dw*dw;
    float var = block_reduce_sum(ss) * (1.0f / HH);
    float rstd = rsqrtf(var + 1e-5f);
    float4 gg = ((const float4*)g)[t];
    float4 bb = ((const float4*)be)[t];
    float4 o;
    o.x = dx * rstd * gg.x + bb.x;
    o.y = dy * rstd * gg.y + bb.y;
    o.z = dz * rstd * gg.z + bb.z;
    o.w = dw * rstd * gg.w + bb.w;
    ((float4*)(out + (size_t)row * HH))[t] = o;
}

// ---------------- GEMM: C[M,N] = A[M,K] @ W[K,N] + bias (+epilogue) --------
// EPI: 0 none, 1 exact GELU, 2 residual add
__device__ __forceinline__ float gelu_exact(float v) {
    return 0.5f * v * (1.0f + erff(v * 0.70710678118654752f));
}

template<int EPI>
__global__ void __launch_bounds__(256, 2)
gemm_kernel(const float* __restrict__ A, const float* __restrict__ W,
            const float* __restrict__ bias, const float* __restrict__ res,
            float* __restrict__ C, int M, int N, int K) {
    __shared__ float As[16][128];   // [k][m]
    __shared__ float Bs[16][128];   // [k][n]
    int tid = threadIdx.x;
    int tm = tid >> 4, tn = tid & 15;
    int m0 = blockIdx.y * 128, n0 = blockIdx.x * 128;

    float acc[8][8];
    #pragma unroll
    for (int i = 0; i < 8; i++)
        #pragma unroll
        for (int j = 0; j < 8; j++) acc[i][j] = 0.0f;

    for (int k0 = 0; k0 < K; k0 += 16) {
        #pragma unroll
        for (int q = 0; q < 2; q++) {
            int fid = tid + q * 256;
            // A tile: 128 rows x 16 cols, float4 along K
            int arow = fid >> 2;
            int ac4  = fid & 3;
            float4 a = *(const float4*)(A + (size_t)(m0 + arow) * K + k0 + ac4 * 4);
            As[ac4*4+0][arow] = a.x; As[ac4*4+1][arow] = a.y;
            As[ac4*4+2][arow] = a.z; As[ac4*4+3][arow] = a.w;
            // B tile: 16 rows x 128 cols, float4 along N
            int brow = fid >> 5;
            int bc   = fid & 31;
            *(float4*)(&Bs[brow][bc*4]) =
                *(const float4*)(W + (size_t)(k0 + brow) * N + n0 + bc * 4);
        }
        __syncthreads();
        #pragma unroll
        for (int kk = 0; kk < 16; kk++) {
            float a[8], b[8];
            #pragma unroll
            for (int i = 0; i < 4; i++) {
                a[i]   = As[kk][tm*4 + i];
                a[4+i] = As[kk][64 + tm*4 + i];
                b[i]   = Bs[kk][tn*4 + i];
                b[4+i] = Bs[kk][64 + tn*4 + i];
            }
            #pragma unroll
            for (int i = 0; i < 8; i++)
                #pragma unroll
                for (int j = 0; j < 8; j++)
                    acc[i][j] += a[i] * b[j];
        }
        __syncthreads();
    }

    #pragma unroll
    for (int i = 0; i < 8; i++) {
        int row = m0 + ((i < 4) ? (tm*4 + i) : (64 + tm*4 + (i - 4)));
        #pragma unroll
        for (int j = 0; j < 8; j++) {
            int col = n0 + ((j < 4) ? (tn*4 + j) : (64 + tn*4 + (j - 4)));
            float v = acc[i][j] + bias[col];
            if (EPI == 1) v = gelu_exact(v);
            if (EPI == 2) v += res[(size_t)row * N + col];
            C[(size_t)row * N + col] = v;
        }
    }
}

// ---------------- flash attention (causal, fp32) ---------------------------
// grid: (S/64, B*NH), block 256. Q,K,V are [B*S, H] with head h at cols h*64.
__global__ void __launch_bounds__(256)
flash_kernel(const float* __restrict__ Q, const float* __restrict__ K,
             const float* __restrict__ V, float* __restrict__ O) {
    __shared__ float Qs[64][64];   // [q][d]
    __shared__ float KPs[64][64];  // K transposed [d][kv]; later P [q][kv]
    __shared__ float Vs[64][64];   // [kv][d]

    int tid = threadIdx.x;
    int ty = tid >> 4, tx = tid & 15;
    int qt = blockIdx.x;
    int bh = blockIdx.y;
    int b = bh >> 4, h = bh & 15;
    size_t headoff = (size_t)b * SS * HH + (size_t)h * DHH;

    // load Q tile
    #pragma unroll
    for (int q = 0; q < 4; q++) {
        int fid = tid + q * 256;
        int r = fid >> 4, d4 = fid & 15;
        *(float4*)(&Qs[r][d4*4]) =
            *(const float4*)(Q + headoff + (size_t)(qt*64 + r) * HH + d4 * 4);
    }

    float acc[4][4];
    float m[4], l[4];
    #pragma unroll
    for (int r = 0; r < 4; r++) {
        m[r] = -1e30f; l[r] = 0.0f;
        #pragma unroll
        for (int c = 0; c < 4; c++) acc[r][c] = 0.0f;
    }

    for (int j = 0; j <= qt; j++) {
        __syncthreads();  // prior PV reads done; Qs visible (first iter)
        #pragma unroll
        for (int q = 0; q < 4; q++) {
            int fid = tid + q * 256;
            int r = fid >> 4, d4 = fid & 15;   // r = kv index
            const float* kp = K + headoff + (size_t)(j*64 + r) * HH + d4 * 4;
            float4 kk = *(const float4*)kp;
            KPs[d4*4+0][r] = kk.x; KPs[d4*4+1][r] = kk.y;
            KPs[d4*4+2][r] = kk.z; KPs[d4*4+3][r] = kk.w;
            *(float4*)(&Vs[r][d4*4]) =
                *(const float4*)(V + headoff + (size_t)(j*64 + r) * HH + d4 * 4);
        }
        __syncthreads();

        // S = Q K^T for this thread's 4x4
        float s[4][4];
        #pragma unroll
        for (int r = 0; r < 4; r++)
            #pragma unroll
            for (int c = 0; c < 4; c++) s[r][c] = 0.0f;

        #pragma unroll 4
        for (int d = 0; d < 64; d++) {
            float qv[4], kv[4];
            #pragma unroll
            for (int r = 0; r < 4; r++) qv[r] = Qs[ty*4 + r][d];
            #pragma unroll
            for (int c = 0; c < 4; c++) kv[c] = KPs[d][tx*4 + c];
            #pragma unroll
            for (int r = 0; r < 4; r++)
                #pragma unroll
                for (int c = 0; c < 4; c++)
                    s[r][c] += qv[r] * kv[c];
        }
        __syncthreads();  // everyone done reading KPs before P overwrites it

        // online softmax per q-row; write P into KPs
        #pragma unroll
        for (int r = 0; r < 4; r++) {
            int qi = qt*64 + ty*4 + r;
            float mt = -1e30f;
            #pragma unroll
            for (int c = 0; c < 4; c++) {
                int kj = j*64 + tx*4 + c;
                float sv = s[r][c] * 0.125f;       // DH^-0.5
                if (kj > qi) sv = -1e30f;          // causal mask
                s[r][c] = sv;
                mt = fmaxf(mt, sv);
            }
            #pragma unroll
            for (int o = 1; o < 16; o <<= 1)
                mt = fmaxf(mt, __shfl_xor_sync(0xffffffffu, mt, o));
            float nm = fmaxf(m[r], mt);
            float corr = __expf(m[r] - nm);
            m[r] = nm;
            float rs = 0.0f;
            #pragma unroll
            for (int c = 0; c < 4; c++) {
                float p = __expf(s[r][c] - nm);
                s[r][c] = p;
                rs += p;
            }
            #pragma unroll
            for (int o = 1; o < 16; o <<= 1)
                rs += __shfl_xor_sync(0xffffffffu, rs, o);
            l[r] = l[r] * corr + rs;
            #pragma unroll
            for (int c = 0; c < 4; c++) acc[r][c] *= corr;
            *(float4*)(&KPs[ty*4 + r][tx*4]) =
                make_float4(s[r][0], s[r][1], s[r][2], s[r][3]);
        }
        __syncthreads();

        // acc += P @ V  (thread owns rows ty*4+r, d-cols tx*4+c)
        #pragma unroll 4
        for (int kc = 0; kc < 64; kc++) {
            float pr[4];
            #pragma unroll
            for (int r = 0; r < 4; r++) pr[r] = KPs[ty*4 + r][kc];
            float4 vv = *(float4*)(&Vs[kc][tx*4]);
            #pragma unroll
            for (int r = 0; r < 4; r++) {
                acc[r][0] += pr[r] * vv.x;
                acc[r][1] += pr[r] * vv.y;
                acc[r][2] += pr[r] * vv.z;
                acc[r][3] += pr[r] * vv.w;
            }
        }
    }

    #pragma unroll
    for (int r = 0; r < 4; r++) {
        float inv = 1.0f / l[r];
        float4 o = make_float4(acc[r][0]*inv, acc[r][1]*inv,
                               acc[r][2]*inv, acc[r][3]*inv);
        *(float4*)(O + headoff + (size_t)(qt*64 + ty*4 + r) * HH + tx * 4) = o;
    }
}

// ---------------- launch ----------------------------------------------------
extern "C" void kernel_launch(void* const* d_in, const int* in_sizes, int n_in,
                              void* d_out, int out_size) {
    const float* x   = (const float*)d_in[0];
    const float* Wq  = (const float*)d_in[1];
    const float* bq  = (const float*)d_in[2];
    const float* Wk  = (const float*)d_in[3];
    const float* bk  = (const float*)d_in[4];
    const float* Wv  = (const float*)d_in[5];
    const float* bv  = (const float*)d_in[6];
    const float* Wo  = (const float*)d_in[7];
    const float* bo  = (const float*)d_in[8];
    const float* W1  = (const float*)d_in[9];
    const float* b1  = (const float*)d_in[10];
    const float* W2  = (const float*)d_in[11];
    const float* b2  = (const float*)d_in[12];
    const float* g1  = (const float*)d_in[13];
    const float* be1 = (const float*)d_in[14];
    const float* g2  = (const float*)d_in[15];
    const float* be2 = (const float*)d_in[16];
    float* out = (float*)d_out;

    float *p_ln1, *p_q, *p_k, *p_v, *p_attn, *p_xatt, *p_ln2, *p_mid;
    cudaGetSymbolAddress((void**)&p_ln1,  g_ln1);
    cudaGetSymbolAddress((void**)&p_q,    g_q);
    cudaGetSymbolAddress((void**)&p_k,    g_k);
    cudaGetSymbolAddress((void**)&p_v,    g_v);
    cudaGetSymbolAddress((void**)&p_attn, g_attn);
    cudaGetSymbolAddress((void**)&p_xatt, g_xatt);
    cudaGetSymbolAddress((void**)&p_ln2,  g_ln2);
    cudaGetSymbolAddress((void**)&p_mid,  g_mid);

    // 1) LN1
    ln_kernel<<<MM, 256>>>(x, g1, be1, p_ln1);

    // 2) QKV projections
    dim3 gqkv(HH/128, MM/128);
    gemm_kernel<0><<<gqkv, 256>>>(p_ln1, Wq, bq, nullptr, p_q, MM, HH, HH);
    gemm_kernel<0><<<gqkv, 256>>>(p_ln1, Wk, bk, nullptr, p_k, MM, HH, HH);
    gemm_kernel<0><<<gqkv, 256>>>(p_ln1, Wv, bv, nullptr, p_v, MM, HH, HH);

    // 3) causal flash attention
    flash_kernel<<<dim3(SS/64, BB*NHH), 256>>>(p_q, p_k, p_v, p_attn);

    // 4) O projection + residual (x)
    gemm_kernel<2><<<gqkv, 256>>>(p_attn, Wo, bo, x, p_xatt, MM, HH, HH);

    // 5) LN2
    ln_kernel<<<MM, 256>>>(p_xatt, g2, be2, p_ln2);

    // 6) FFN up + exact GELU
    gemm_kernel<1><<<dim3(FFF/128, MM/128), 256>>>(p_ln2, W1, b1, nullptr, p_mid, MM, FFF, HH);

    // 7) FFN down + residual
    gemm_kernel<2><<<dim3(HH/128, MM/128), 256>>>(p_mid, W2, b2, p_xatt, out, MM, HH, FFF);
}

// round 2
// speedup vs baseline: 1.9682x; 1.9682x over previous
#include <cuda_runtime.h>
#include <cuda_bf16.h>
#include <math.h>

// Problem dims (fixed)
#define BB 2
#define SS 2048
#define HH 1024
#define NHH 16
#define DHH 64
#define FFF 4096
#define MM (BB*SS)   // 4096 tokens

// ---------------- scratch (device globals; no allocation allowed) ----------
__device__ float g_ln1 [MM*HH];
__device__ float g_q   [MM*HH];
__device__ float g_k   [MM*HH];
__device__ float g_v   [MM*HH];
__device__ float g_attn[MM*HH];
__device__ float g_xatt[MM*HH];
__device__ float g_ln2 [MM*HH];
__device__ float g_mid [MM*FFF];

// ---------------- layernorm ------------------------------------------------
__device__ __forceinline__ float block_reduce_sum(float v) {
    __shared__ float sh[8];
    int lane = threadIdx.x & 31, w = threadIdx.x >> 5;
    #pragma unroll
    for (int o = 16; o > 0; o >>= 1) v += __shfl_xor_sync(0xffffffffu, v, o);
    if (lane == 0) sh[w] = v;
    __syncthreads();
    float t = (threadIdx.x < 8) ? sh[threadIdx.x] : 0.0f;
    if (w == 0) {
        #pragma unroll
        for (int o = 4; o > 0; o >>= 1) t += __shfl_xor_sync(0xffffffffu, t, o);
        if (lane == 0) sh[0] = t;
    }
    __syncthreads();
    float r = sh[0];
    __syncthreads();
    return r;
}

__global__ void ln_kernel(const float* __restrict__ x,
                          const float* __restrict__ g,
                          const float* __restrict__ be,
                          float* __restrict__ out) {
    int row = blockIdx.x;
    int t = threadIdx.x;
    const float4* xr = (const float4*)(x + (size_t)row * HH);
    float4 v = xr[t];
    float s = v.x + v.y + v.z + v.w;
    float mu = block_reduce_sum(s) * (1.0f / HH);
    float dx = v.x - mu, dy = v.y - mu, dz = v.z - mu, dw = v.w - mu;
    float ss = dx*dx + dy*dy + dz*dz + dw*dw;
    float var = block_reduce_sum(ss) * (1.0f / HH);
    float rstd = rsqrtf(var + 1e-5f);
    float4 gg = ((const float4*)g)[t];
    float4 bb = ((const float4*)be)[t];
    float4 o;
    o.x = dx * rstd * gg.x + bb.x;
    o.y = dy * rstd * gg.y + bb.y;
    o.z = dz * rstd * gg.z + bb.z;
    o.w = dw * rstd * gg.w + bb.w;
    ((float4*)(out + (size_t)row * HH))[t] = o;
}

// ---------------- tf32 tensor-core GEMM -------------------------------------
// C[M,N] = A[M,K] @ W[K,N] + bias (+epilogue). EPI: 0 none, 1 GELU, 2 residual
__device__ __forceinline__ float gelu_exact(float v) {
    return 0.5f * v * (1.0f + erff(v * 0.70710678118654752f));
}

__device__ __forceinline__ unsigned f2tf(float f) {
    unsigned u;
    asm("cvt.rna.tf32.f32 %0, %1;" : "=r"(u) : "f"(f));
    return u;
}

__device__ __forceinline__ void mma_tf32(float* d, const unsigned* a,
                                         unsigned b0, unsigned b1) {
    asm volatile(
        "mma.sync.aligned.m16n8k8.row.col.f32.tf32.tf32.f32 "
        "{%0,%1,%2,%3}, {%4,%5,%6,%7}, {%8,%9}, {%0,%1,%2,%3};\n"
        : "+f"(d[0]), "+f"(d[1]), "+f"(d[2]), "+f"(d[3])
        : "r"(a[0]), "r"(a[1]), "r"(a[2]), "r"(a[3]), "r"(b0), "r"(b1));
}

#define BKC 32
#define APAD 36    // A smem row stride (uints): (4m + k) % 32 distinct -> no conflicts
#define BPAD 136   // B smem row stride (uints): (8k + n) % 32 distinct -> no conflicts

template<int EPI>
__global__ void __launch_bounds__(256, 2)
gemm_tc(const float* __restrict__ A, const float* __restrict__ W,
        const float* __restrict__ bias, const float* __restrict__ res,
        float* __restrict__ C, int M, int N, int K) {
    __shared__ unsigned As[128][APAD];   // [m][k]  (tf32 bits)
    __shared__ unsigned Bs[BKC][BPAD];   // [k][n]  (tf32 bits)

    int tid = threadIdx.x;
    int warp = tid >> 5, lane = tid & 31;
    int g = lane >> 2, t4 = lane & 3;
    int wm = warp & 3, wn = warp >> 2;        // warp tile: rows wm*32, cols wn*64
    int m0 = blockIdx.y * 128, n0 = blockIdx.x * 128;

    float acc[2][8][4];
    #pragma unroll
    for (int mi = 0; mi < 2; mi++)
        #pragma unroll
        for (int nj = 0; nj < 8; nj++)
            #pragma unroll
            for (int e = 0; e < 4; e++) acc[mi][nj][e] = 0.0f;

    int nc = K / BKC;
    float4 ar[4], br[4];

    // prologue: stage chunk 0
    #pragma unroll
    for (int q = 0; q < 4; q++) {
        int fid = tid + q * 256;
        int arow = fid >> 3, ac4 = fid & 7;           // A: 128 rows x 8 float4
        ar[q] = *(const float4*)(A + (size_t)(m0 + arow) * K + ac4 * 4);
        int brow = fid >> 5, bc4 = fid & 31;          // B: 32 rows x 32 float4
        br[q] = *(const float4*)(W + (size_t)brow * N + n0 + bc4 * 4);
    }

    for (int c = 0; c < nc; c++) {
        __syncthreads();   // previous mma done reading smem
        #pragma unroll
        for (int q = 0; q < 4; q++) {
            int fid = tid + q * 256;
            int arow = fid >> 3, ac4 = fid & 7;
            uint4 ua;
            ua.x = f2tf(ar[q].x); ua.y = f2tf(ar[q].y);
            ua.z = f2tf(ar[q].z); ua.w = f2tf(ar[q].w);
            *(uint4*)&As[arow][ac4 * 4] = ua;
            int brow = fid >> 5, bc4 = fid & 31;
            uint4 ub;
            ub.x = f2tf(br[q].x); ub.y = f2tf(br[q].y);
            ub.z = f2tf(br[q].z); ub.w = f2tf(br[q].w);
            *(uint4*)&Bs[brow][bc4 * 4] = ub;
        }
        __syncthreads();

        // prefetch next chunk into registers (hidden under mma)
        if (c + 1 < nc) {
            int k0 = (c + 1) * BKC;
            #pragma unroll
            for (int q = 0; q < 4; q++) {
                int fid = tid + q * 256;
                int arow = fid >> 3, ac4 = fid & 7;
                ar[q] = *(const float4*)(A + (size_t)(m0 + arow) * K + k0 + ac4 * 4);
                int brow = fid >> 5, bc4 = fid & 31;
                br[q] = *(const float4*)(W + (size_t)(k0 + brow) * N + n0 + bc4 * 4);
            }
        }

        #pragma unroll
        for (int ks = 0; ks < 4; ks++) {
            int kk = ks * 8;
            unsigned a[2][4];
            #pragma unroll
            for (int mi = 0; mi < 2; mi++) {
                int rm = wm * 32 + mi * 16;
                a[mi][0] = As[rm + g    ][kk + t4];
                a[mi][1] = As[rm + g + 8][kk + t4];
                a[mi][2] = As[rm + g    ][kk + t4 + 4];
                a[mi][3] = As[rm + g + 8][kk + t4 + 4];
            }
            #pragma unroll
            for (int nj = 0; nj < 8; nj++) {
                int cn = wn * 64 + nj * 8 + g;
                unsigned b0 = Bs[kk + t4    ][cn];
                unsigned b1 = Bs[kk + t4 + 4][cn];
                mma_tf32(acc[0][nj], a[0], b0, b1);
                mma_tf32(acc[1][nj], a[1], b0, b1);
            }
        }
    }

    // epilogue
    #pragma unroll
    for (int mi = 0; mi < 2; mi++) {
        int row = m0 + wm * 32 + mi * 16 + g;
        #pragma unroll
        for (int nj = 0; nj < 8; nj++) {
            int col = n0 + wn * 64 + nj * 8 + 2 * t4;
            float b0 = bias[col], b1 = bias[col + 1];
            float v0 = acc[mi][nj][0] + b0;
            float v1 = acc[mi][nj][1] + b1;
            float v2 = acc[mi][nj][2] + b0;
            float v3 = acc[mi][nj][3] + b1;
            if (EPI == 1) {
                v0 = gelu_exact(v0); v1 = gelu_exact(v1);
                v2 = gelu_exact(v2); v3 = gelu_exact(v3);
            }
            if (EPI == 2) {
                v0 += res[(size_t)row * N + col];
                v1 += res[(size_t)row * N + col + 1];
                v2 += res[(size_t)(row + 8) * N + col];
                v3 += res[(size_t)(row + 8) * N + col + 1];
            }
            *(float2*)(C + (size_t)row * N + col)       = make_float2(v0, v1);
            *(float2*)(C + (size_t)(row + 8) * N + col) = make_float2(v2, v3);
        }
    }
}

// ---------------- flash attention (causal, fp32) ---------------------------
__global__ void __launch_bounds__(256)
flash_kernel(const float* __restrict__ Q, const float* __restrict__ K,
             const float* __restrict__ V, float* __restrict__ O) {
    __shared__ float Qs[64][64];
    __shared__ float KPs[64][64];
    __shared__ float Vs[64][64];

    int tid = threadIdx.x;
    int ty = tid >> 4, tx = tid & 15;
    int qt = blockIdx.x;
    int bh = blockIdx.y;
    int b = bh >> 4, h = bh & 15;
    size_t headoff = (size_t)b * SS * HH + (size_t)h * DHH;

    #pragma unroll
    for (int q = 0; q < 4; q++) {
        int fid = tid + q * 256;
        int r = fid >> 4, d4 = fid & 15;
        *(float4*)(&Qs[r][d4*4]) =
            *(const float4*)(Q + headoff + (size_t)(qt*64 + r) * HH + d4 * 4);
    }

    float acc[4][4];
    float m[4], l[4];
    #pragma unroll
    for (int r = 0; r < 4; r++) {
        m[r] = -1e30f; l[r] = 0.0f;
        #pragma unroll
        for (int c = 0; c < 4; c++) acc[r][c] = 0.0f;
    }

    for (int j = 0; j <= qt; j++) {
        __syncthreads();
        #pragma unroll
        for (int q = 0; q < 4; q++) {
            int fid = tid + q * 256;
            int r = fid >> 4, d4 = fid & 15;
            const float* kp = K + headoff + (size_t)(j*64 + r) * HH + d4 * 4;
            float4 kk = *(const float4*)kp;
            KPs[d4*4+0][r] = kk.x; KPs[d4*4+1][r] = kk.y;
            KPs[d4*4+2][r] = kk.z; KPs[d4*4+3][r] = kk.w;
            *(float4*)(&Vs[r][d4*4]) =
                *(const float4*)(V + headoff + (size_t)(j*64 + r) * HH + d4 * 4);
        }
        __syncthreads();

        float s[4][4];
        #pragma unroll
        for (int r = 0; r < 4; r++)
            #pragma unroll
            for (int c = 0; c < 4; c++) s[r][c] = 0.0f;

        #pragma unroll 4
        for (int d = 0; d < 64; d++) {
            float qv[4], kv[4];
            #pragma unroll
            for (int r = 0; r < 4; r++) qv[r] = Qs[ty*4 + r][d];
            #pragma unroll
            for (int c = 0; c < 4; c++) kv[c] = KPs[d][tx*4 + c];
            #pragma unroll
            for (int r = 0; r < 4; r++)
                #pragma unroll
                for (int c = 0; c < 4; c++)
                    s[r][c] += qv[r] * kv[c];
        }
        __syncthreads();

        #pragma unroll
        for (int r = 0; r < 4; r++) {
            int qi = qt*64 + ty*4 + r;
            float mt = -1e30f;
            #pragma unroll
            for (int c = 0; c < 4; c++) {
                int kj = j*64 + tx*4 + c;
                float sv = s[r][c] * 0.125f;
                if (kj > qi) sv = -1e30f;
                s[r][c] = sv;
                mt = fmaxf(mt, sv);
            }
            #pragma unroll
            for (int o = 1; o < 16; o <<= 1)
                mt = fmaxf(mt, __shfl_xor_sync(0xffffffffu, mt, o));
            float nm = fmaxf(m[r], mt);
            float corr = __expf(m[r] - nm);
            m[r] = nm;
            float rs = 0.0f;
            #pragma unroll
            for (int c = 0; c < 4; c++) {
                float p = __expf(s[r][c] - nm);
                s[r][c] = p;
                rs += p;
            }
            #pragma unroll
            for (int o = 1; o < 16; o <<= 1)
                rs += __shfl_xor_sync(0xffffffffu, rs, o);
            l[r] = l[r] * corr + rs;
            #pragma unroll
            for (int c = 0; c < 4; c++) acc[r][c] *= corr;
            *(float4*)(&KPs[ty*4 + r][tx*4]) =
                make_float4(s[r][0], s[r][1], s[r][2], s[r][3]);
        }
        __syncthreads();

        #pragma unroll 4
        for (int kc = 0; kc < 64; kc++) {
            float pr[4];
            #pragma unroll
            for (int r = 0; r < 4; r++) pr[r] = KPs[ty*4 + r][kc];
            float4 vv = *(float4*)(&Vs[kc][tx*4]);
            #pragma unroll
            for (int r = 0; r < 4; r++) {
                acc[r][0] += pr[r] * vv.x;
                acc[r][1] += pr[r] * vv.y;
                acc[r][2] += pr[r] * vv.z;
                acc[r][3] += pr[r] * vv.w;
            }
        }
    }

    #pragma unroll
    for (int r = 0; r < 4; r++) {
        float inv = 1.0f / l[r];
        float4 o = make_float4(acc[r][0]*inv, acc[r][1]*inv,
                               acc[r][2]*inv, acc[r][3]*inv);
        *(float4*)(O + headoff + (size_t)(qt*64 + ty*4 + r) * HH + tx * 4) = o;
    }
}

// ---------------- launch ----------------------------------------------------
extern "C" void kernel_launch(void* const* d_in, const int* in_sizes, int n_in,
                              void* d_out, int out_size) {
    const float* x   = (const float*)d_in[0];
    const float* Wq  = (const float*)d_in[1];
    const float* bq  = (const float*)d_in[2];
    const float* Wk  = (const float*)d_in[3];
    const float* bk  = (const float*)d_in[4];
    const float* Wv  = (const float*)d_in[5];
    const float* bv  = (const float*)d_in[6];
    const float* Wo  = (const float*)d_in[7];
    const float* bo  = (const float*)d_in[8];
    const float* W1  = (const float*)d_in[9];
    const float* b1  = (const float*)d_in[10];
    const float* W2  = (const float*)d_in[11];
    const float* b2  = (const float*)d_in[12];
    const float* g1  = (const float*)d_in[13];
    const float* be1 = (const float*)d_in[14];
    const float* g2  = (const float*)d_in[15];
    const float* be2 = (const float*)d_in[16];
    float* out = (float*)d_out;

    float *p_ln1, *p_q, *p_k, *p_v, *p_attn, *p_xatt, *p_ln2, *p_mid;
    cudaGetSymbolAddress((void**)&p_ln1,  g_ln1);
    cudaGetSymbolAddress((void**)&p_q,    g_q);
    cudaGetSymbolAddress((void**)&p_k,    g_k);
    cudaGetSymbolAddress((void**)&p_v,    g_v);
    cudaGetSymbolAddress((void**)&p_attn, g_attn);
    cudaGetSymbolAddress((void**)&p_xatt, g_xatt);
    cudaGetSymbolAddress((void**)&p_ln2,  g_ln2);
    cudaGetSymbolAddress((void**)&p_mid,  g_mid);

    // 1) LN1
    ln_kernel<<<MM, 256>>>(x, g1, be1, p_ln1);

    // 2) QKV projections (tf32 tensor cores)
    dim3 gqkv(HH/128, MM/128);
    gemm_tc<0><<<gqkv, 256>>>(p_ln1, Wq, bq, nullptr, p_q, MM, HH, HH);
    gemm_tc<0><<<gqkv, 256>>>(p_ln1, Wk, bk, nullptr, p_k, MM, HH, HH);
    gemm_tc<0><<<gqkv, 256>>>(p_ln1, Wv, bv, nullptr, p_v, MM, HH, HH);

    // 3) causal flash attention
    flash_kernel<<<dim3(SS/64, BB*NHH), 256>>>(p_q, p_k, p_v, p_attn);

    // 4) O projection + residual (x)
    gemm_tc<2><<<gqkv, 256>>>(p_attn, Wo, bo, x, p_xatt, MM, HH, HH);

    // 5) LN2
    ln_kernel<<<MM, 256>>>(p_xatt, g2, be2, p_ln2);

    // 6) FFN up + exact GELU
    gemm_tc<1><<<dim3(FFF/128, MM/128), 256>>>(p_ln2, W1, b1, nullptr, p_mid, MM, FFF, HH);

    // 7) FFN down + residual
    gemm_tc<2><<<dim3(HH/128, MM/128), 256>>>(p_mid, W2, b2, p_xatt, out, MM, HH, FFF);
}

// round 3
// speedup vs baseline: 2.8715x; 1.4589x over previous
#include <cuda_runtime.h>
#include <math.h>

// Problem dims (fixed)
#define BB 2
#define SS 2048
#define HH 1024
#define NHH 16
#define DHH 64
#define FFF 4096
#define MM (BB*SS)   // 4096 tokens

// ---------------- scratch (device globals; no allocation allowed) ----------
__device__ float g_ln1 [MM*HH];
__device__ float g_q   [MM*HH];
__device__ float g_k   [MM*HH];
__device__ float g_v   [MM*HH];
__device__ float g_attn[MM*HH];
__device__ float g_xatt[MM*HH];
__device__ float g_ln2 [MM*HH];
__device__ float g_mid [MM*FFF];
// tf32-rounded weight copies
__device__ float g_wq[HH*HH];
__device__ float g_wk[HH*HH];
__device__ float g_wv[HH*HH];
__device__ float g_wo[HH*HH];
__device__ float g_w1[HH*FFF];
__device__ float g_w2[FFF*HH];

// ---------------- helpers ---------------------------------------------------
__device__ __forceinline__ unsigned f2tf(float f) {
    unsigned u;
    asm("cvt.rna.tf32.f32 %0, %1;" : "=r"(u) : "f"(f));
    return u;
}
__device__ __forceinline__ float rtf(float f) { return __uint_as_float(f2tf(f)); }

__device__ __forceinline__ void mma_tf32(float* d, const unsigned* a,
                                         unsigned b0, unsigned b1) {
    asm volatile(
        "mma.sync.aligned.m16n8k8.row.col.f32.tf32.tf32.f32 "
        "{%0,%1,%2,%3}, {%4,%5,%6,%7}, {%8,%9}, {%0,%1,%2,%3};\n"
        : "+f"(d[0]), "+f"(d[1]), "+f"(d[2]), "+f"(d[3])
        : "r"(a[0]), "r"(a[1]), "r"(a[2]), "r"(a[3]), "r"(b0), "r"(b1));
}

__device__ __forceinline__ void cpasync16(float* dst, const float* src) {
    unsigned s = (unsigned)__cvta_generic_to_shared(dst);
    asm volatile("cp.async.cg.shared.global [%0], [%1], 16;\n" :: "r"(s), "l"(src));
}

__device__ __forceinline__ float gelu_exact(float v) {
    return 0.5f * v * (1.0f + erff(v * 0.70710678118654752f));
}

// ---------------- weight rounding (once per launch) -------------------------
__global__ void round_w(const float* __restrict__ in, float* __restrict__ out, int n4) {
    int i = blockIdx.x * 256 + threadIdx.x;
    if (i < n4) {
        float4 v = ((const float4*)in)[i];
        v.x = rtf(v.x); v.y = rtf(v.y); v.z = rtf(v.z); v.w = rtf(v.w);
        ((float4*)out)[i] = v;
    }
}

// ---------------- layernorm (tf32-rounded output) ----------------------------
__device__ __forceinline__ float block_reduce_sum(float v) {
    __shared__ float sh[8];
    int lane = threadIdx.x & 31, w = threadIdx.x >> 5;
    #pragma unroll
    for (int o = 16; o > 0; o >>= 1) v += __shfl_xor_sync(0xffffffffu, v, o);
    if (lane == 0) sh[w] = v;
    __syncthreads();
    float t = (threadIdx.x < 8) ? sh[threadIdx.x] : 0.0f;
    if (w == 0) {
        #pragma unroll
        for (int o = 4; o > 0; o >>= 1) t += __shfl_xor_sync(0xffffffffu, t, o);
        if (lane == 0) sh[0] = t;
    }
    __syncthreads();
    float r = sh[0];
    __syncthreads();
    return r;
}

__global__ void ln_kernel(const float* __restrict__ x,
                          const float* __restrict__ g,
                          const float* __restrict__ be,
                          float* __restrict__ out) {
    int row = blockIdx.x;
    int t = threadIdx.x;
    const float4* xr = (const float4*)(x + (size_t)row * HH);
    float4 v = xr[t];
    float s = v.x + v.y + v.z + v.w;
    float mu = block_reduce_sum(s) * (1.0f / HH);
    float dx = v.x - mu, dy = v.y - mu, dz = v.z - mu, dw = v.w - mu;
    float ss = dx*dx + dy*dy + dz*dz + dw*dw;
    float var = block_reduce_sum(ss) * (1.0f / HH);
    float rstd = rsqrtf(var + 1e-5f);
    float4 gg = ((const float4*)g)[t];
    float4 bb = ((const float4*)be)[t];
    float4 o;
    o.x = rtf(dx * rstd * gg.x + bb.x);
    o.y = rtf(dy * rstd * gg.y + bb.y);
    o.z = rtf(dz * rstd * gg.z + bb.z);
    o.w = rtf(dw * rstd * gg.w + bb.w);
    ((float4*)(out + (size_t)row * HH))[t] = o;
}

// ---------------- tf32 GEMM with cp.async double buffering -------------------
// Inputs A and W must already be tf32-rounded. EPI: 0 none, 1 GELU, 2 residual.
#define APAD 20
#define BPAD 136

template<int EPI, int ROUND>
__global__ void __launch_bounds__(256, 2)
gemm_tc(const float* __restrict__ A, const float* __restrict__ W,
        const float* __restrict__ bias, const float* __restrict__ res,
        float* __restrict__ C, int M, int N, int K) {
    __shared__ float As[2][128][APAD];
    __shared__ float Bs[2][16][BPAD];

    int tid = threadIdx.x;
    int warp = tid >> 5, lane = tid & 31;
    int g = lane >> 2, t4 = lane & 3;
    int wm = warp & 3, wn = warp >> 2;
    int m0 = blockIdx.y * 128, n0 = blockIdx.x * 128;

    float acc[2][8][4] = {};

    int nc = K >> 4;

    // stage 0
    {
        #pragma unroll
        for (int q = 0; q < 2; q++) {
            int fid = tid + q * 256;
            int ar = fid >> 2, ac = (fid & 3) * 4;
            cpasync16(&As[0][ar][ac], A + (size_t)(m0 + ar) * K + ac);
            int br = fid >> 5, bc = (fid & 31) * 4;
            cpasync16(&Bs[0][br][bc], W + (size_t)br * N + n0 + bc);
        }
        asm volatile("cp.async.commit_group;");
    }

    for (int c = 0; c < nc; c++) {
        if (c + 1 < nc) {
            int s = (c + 1) & 1, k0 = (c + 1) * 16;
            #pragma unroll
            for (int q = 0; q < 2; q++) {
                int fid = tid + q * 256;
                int ar = fid >> 2, ac = (fid & 3) * 4;
                cpasync16(&As[s][ar][ac], A + (size_t)(m0 + ar) * K + k0 + ac);
                int br = fid >> 5, bc = (fid & 31) * 4;
                cpasync16(&Bs[s][br][bc], W + (size_t)(k0 + br) * N + n0 + bc);
            }
        }
        asm volatile("cp.async.commit_group;");
        asm volatile("cp.async.wait_group 1;");
        __syncthreads();

        const float (*as)[APAD] = As[c & 1];
        const float (*bs)[BPAD] = Bs[c & 1];
        #pragma unroll
        for (int ks = 0; ks < 2; ks++) {
            int kk = ks * 8;
            unsigned a[2][4];
            #pragma unroll
            for (int mi = 0; mi < 2; mi++) {
                int rm = wm * 32 + mi * 16;
                a[mi][0] = __float_as_uint(as[rm + g    ][kk + t4]);
                a[mi][1] = __float_as_uint(as[rm + g + 8][kk + t4]);
                a[mi][2] = __float_as_uint(as[rm + g    ][kk + t4 + 4]);
                a[mi][3] = __float_as_uint(as[rm + g + 8][kk + t4 + 4]);
            }
            #pragma unroll
            for (int nj = 0; nj < 8; nj++) {
                int cn = wn * 64 + nj * 8 + g;
                unsigned b0 = __float_as_uint(bs[kk + t4    ][cn]);
                unsigned b1 = __float_as_uint(bs[kk + t4 + 4][cn]);
                mma_tf32(acc[0][nj], a[0], b0, b1);
                mma_tf32(acc[1][nj], a[1], b0, b1);
            }
        }
        __syncthreads();
    }

    // epilogue
    #pragma unroll
    for (int mi = 0; mi < 2; mi++) {
        int row = m0 + wm * 32 + mi * 16 + g;
        #pragma unroll
        for (int nj = 0; nj < 8; nj++) {
            int col = n0 + wn * 64 + nj * 8 + 2 * t4;
            float b0 = bias[col], b1 = bias[col + 1];
            float v0 = acc[mi][nj][0] + b0;
            float v1 = acc[mi][nj][1] + b1;
            float v2 = acc[mi][nj][2] + b0;
            float v3 = acc[mi][nj][3] + b1;
            if (EPI == 1) {
                v0 = gelu_exact(v0); v1 = gelu_exact(v1);
                v2 = gelu_exact(v2); v3 = gelu_exact(v3);
            }
            if (EPI == 2) {
                v0 += res[(size_t)row * N + col];
                v1 += res[(size_t)row * N + col + 1];
                v2 += res[(size_t)(row + 8) * N + col];
                v3 += res[(size_t)(row + 8) * N + col + 1];
            }
            if (ROUND) {
                v0 = rtf(v0); v1 = rtf(v1); v2 = rtf(v2); v3 = rtf(v3);
            }
            *(float2*)(C + (size_t)row * N + col)       = make_float2(v0, v1);
            *(float2*)(C + (size_t)(row + 8) * N + col) = make_float2(v2, v3);
        }
    }
}

// ---------------- tensor-core flash attention (causal) -----------------------
// Br=128 (8 warps x 16 rows each), Bc=64. Q/K/V pre-rounded to tf32.
__global__ void __launch_bounds__(256, 2)
flash_tc(const float* __restrict__ Q, const float* __restrict__ K,
         const float* __restrict__ V, float* __restrict__ O) {
    __shared__ float Ks[64][72];
    __shared__ float Vs[64][72];

    int tid = threadIdx.x, warp = tid >> 5, lane = tid & 31;
    int g = lane >> 2, t4 = lane & 3;
    int qt = gridDim.x - 1 - blockIdx.x;        // heavy tiles first
    int bh = blockIdx.y, b = bh >> 4, h = bh & 15;
    size_t headoff = (size_t)b * SS * HH + (size_t)h * DHH;
    int qbase = qt * 128 + warp * 16;           // this warp's 16 q-rows

    // Q fragments register-resident for the whole KV loop
    unsigned qf[8][4];
    #pragma unroll
    for (int kt = 0; kt < 8; kt++) {
        int kk = kt * 8;
        const float* q0 = Q + headoff + (size_t)(qbase + g)     * HH + kk + t4;
        const float* q1 = Q + headoff + (size_t)(qbase + g + 8) * HH + kk + t4;
        qf[kt][0] = __float_as_uint(__ldg(q0));
        qf[kt][1] = __float_as_uint(__ldg(q1));
        qf[kt][2] = __float_as_uint(__ldg(q0 + 4));
        qf[kt][3] = __float_as_uint(__ldg(q1 + 4));
    }

    float oacc[8][4] = {};
    float m0 = -1e30f, m1 = -1e30f, l0 = 0.0f, l1 = 0.0f;
    int row0 = qbase + g, row1 = qbase + g + 8;

    int jmax = 2 * qt + 1;
    for (int j = 0; j <= jmax; j++) {
        // load K/V tiles (coalesced float4)
        #pragma unroll
        for (int q = 0; q < 4; q++) {
            int fid = tid + q * 256;
            int r = fid >> 4, c4 = (fid & 15) * 4;
            *(float4*)&Ks[r][c4] = *(const float4*)(K + headoff + (size_t)(j*64 + r) * HH + c4);
            *(float4*)&Vs[r][c4] = *(const float4*)(V + headoff + (size_t)(j*64 + r) * HH + c4);
        }
        __syncthreads();

        if (j * 64 <= qbase + 15) {     // warp-uniform: any unmasked cols?
            // S = Q K^T  (16x64 per warp)
            float s[8][4] = {};
            #pragma unroll
            for (int kt = 0; kt < 8; kt++) {
                int kk = kt * 8;
                #pragma unroll
                for (int nj = 0; nj < 8; nj++) {
                    unsigned b0 = __float_as_uint(Ks[nj*8 + g][kk + t4]);
                    unsigned b1 = __float_as_uint(Ks[nj*8 + g][kk + t4 + 4]);
                    mma_tf32(s[nj], qf[kt], b0, b1);
                }
            }

            // scale + causal mask + row max
            float mt0 = -1e30f, mt1 = -1e30f;
            #pragma unroll
            for (int nj = 0; nj < 8; nj++) {
                int c0 = j*64 + nj*8 + 2*t4, c1 = c0 + 1;
                float v0 = s[nj][0] * 0.125f, v1 = s[nj][1] * 0.125f;
                float v2 = s[nj][2] * 0.125f, v3 = s[nj][3] * 0.125f;
                if (c0 > row0) v0 = -1e30f;
                if (c1 > row0) v1 = -1e30f;
                if (c0 > row1) v2 = -1e30f;
                if (c1 > row1) v3 = -1e30f;
                s[nj][0] = v0; s[nj][1] = v1; s[nj][2] = v2; s[nj][3] = v3;
                mt0 = fmaxf(mt0, fmaxf(v0, v1));
                mt1 = fmaxf(mt1, fmaxf(v2, v3));
            }
            mt0 = fmaxf(mt0, __shfl_xor_sync(0xffffffffu, mt0, 1));
            mt0 = fmaxf(mt0, __shfl_xor_sync(0xffffffffu, mt0, 2));
            mt1 = fmaxf(mt1, __shfl_xor_sync(0xffffffffu, mt1, 1));
            mt1 = fmaxf(mt1, __shfl_xor_sync(0xffffffffu, mt1, 2));

            float nm0 = fmaxf(m0, mt0), nm1 = fmaxf(m1, mt1);
            float co0 = __expf(m0 - nm0), co1 = __expf(m1 - nm1);
            m0 = nm0; m1 = nm1;

            float rs0 = 0.0f, rs1 = 0.0f;
            #pragma unroll
            for (int nj = 0; nj < 8; nj++) {
                float p0 = rtf(__expf(s[nj][0] - nm0));
                float p1 = rtf(__expf(s[nj][1] - nm0));
                float p2 = rtf(__expf(s[nj][2] - nm1));
                float p3 = rtf(__expf(s[nj][3] - nm1));
                s[nj][0] = p0; s[nj][1] = p1; s[nj][2] = p2; s[nj][3] = p3;
                rs0 += p0 + p1; rs1 += p2 + p3;
            }
            rs0 += __shfl_xor_sync(0xffffffffu, rs0, 1);
            rs0 += __shfl_xor_sync(0xffffffffu, rs0, 2);
            rs1 += __shfl_xor_sync(0xffffffffu, rs1, 1);
            rs1 += __shfl_xor_sync(0xffffffffu, rs1, 2);
            l0 = l0 * co0 + rs0;
            l1 = l1 * co1 + rs1;

            #pragma unroll
            for (int nd = 0; nd < 8; nd++) {
                oacc[nd][0] *= co0; oacc[nd][1] *= co0;
                oacc[nd][2] *= co1; oacc[nd][3] *= co1;
            }

            // O += P V : build A-frag of P from C-layout via intra-quad shuffles
            #pragma unroll
            for (int kt = 0; kt < 8; kt++) {
                int src = (lane & ~3) | (t4 >> 1);
                float lo0 = __shfl_sync(0xffffffffu, s[kt][0], src);
                float hi0 = __shfl_sync(0xffffffffu, s[kt][1], src);
                float lo1 = __shfl_sync(0xffffffffu, s[kt][2], src);
                float hi1 = __shfl_sync(0xffffffffu, s[kt][3], src);
                float lo2 = __shfl_sync(0xffffffffu, s[kt][0], src + 2);
                float hi2 = __shfl_sync(0xffffffffu, s[kt][1], src + 2);
                float lo3 = __shfl_sync(0xffffffffu, s[kt][2], src + 2);
                float hi3 = __shfl_sync(0xffffffffu, s[kt][3], src + 2);
                bool odd = (t4 & 1);
                unsigned pa[4];
                pa[0] = __float_as_uint(odd ? hi0 : lo0);
                pa[1] = __float_as_uint(odd ? hi1 : lo1);
                pa[2] = __float_as_uint(odd ? hi2 : lo2);
                pa[3] = __float_as_uint(odd ? hi3 : lo3);
                int kk = kt * 8;
                #pragma unroll
                for (int nd = 0; nd < 8; nd++) {
                    unsigned b0 = __float_as_uint(Vs[kk + t4    ][nd*8 + g]);
                    unsigned b1 = __float_as_uint(Vs[kk + t4 + 4][nd*8 + g]);
                    mma_tf32(oacc[nd], pa, b0, b1);
                }
            }
        }
        __syncthreads();
    }

    float inv0 = 1.0f / l0, inv1 = 1.0f / l1;
    #pragma unroll
    for (int nd = 0; nd < 8; nd++) {
        float2 o0 = make_float2(rtf(oacc[nd][0] * inv0), rtf(oacc[nd][1] * inv0));
        float2 o1 = make_float2(rtf(oacc[nd][2] * inv1), rtf(oacc[nd][3] * inv1));
        *(float2*)(O + headoff + (size_t)row0 * HH + nd*8 + 2*t4) = o0;
        *(float2*)(O + headoff + (size_t)row1 * HH + nd*8 + 2*t4) = o1;
    }
}

// ---------------- launch ----------------------------------------------------
extern "C" void kernel_launch(void* const* d_in, const int* in_sizes, int n_in,
                              void* d_out, int out_size) {
    const float* x   = (const float*)d_in[0];
    const float* Wq  = (const float*)d_in[1];
    const float* bq  = (const float*)d_in[2];
    const float* Wk  = (const float*)d_in[3];
    const float* bk  = (const float*)d_in[4];
    const float* Wv  = (const float*)d_in[5];
    const float* bv  = (const float*)d_in[6];
    const float* Wo  = (const float*)d_in[7];
    const float* bo  = (const float*)d_in[8];
    const float* W1  = (const float*)d_in[9];
    const float* b1  = (const float*)d_in[10];
    const float* W2  = (const float*)d_in[11];
    const float* b2  = (const float*)d_in[12];
    const float* g1  = (const float*)d_in[13];
    const float* be1 = (const float*)d_in[14];
    const float* g2  = (const float*)d_in[15];
    const float* be2 = (const float*)d_in[16];
    float* out = (float*)d_out;

    float *p_ln1, *p_q, *p_k, *p_v, *p_attn, *p_xatt, *p_ln2, *p_mid;
    float *p_wq, *p_wk, *p_wv, *p_wo, *p_w1, *p_w2;
    cudaGetSymbolAddress((void**)&p_ln1,  g_ln1);
    cudaGetSymbolAddress((void**)&p_q,    g_q);
    cudaGetSymbolAddress((void**)&p_k,    g_k);
    cudaGetSymbolAddress((void**)&p_v,    g_v);
    cudaGetSymbolAddress((void**)&p_attn, g_attn);
    cudaGetSymbolAddress((void**)&p_xatt, g_xatt);
    cudaGetSymbolAddress((void**)&p_ln2,  g_ln2);
    cudaGetSymbolAddress((void**)&p_mid,  g_mid);
    cudaGetSymbolAddress((void**)&p_wq,   g_wq);
    cudaGetSymbolAddress((void**)&p_wk,   g_wk);
    cudaGetSymbolAddress((void**)&p_wv,   g_wv);
    cudaGetSymbolAddress((void**)&p_wo,   g_wo);
    cudaGetSymbolAddress((void**)&p_w1,   g_w1);
    cudaGetSymbolAddress((void**)&p_w2,   g_w2);

    // 0) tf32-round weight copies
    int n4h = HH * HH / 4, n4f = HH * FFF / 4;
    round_w<<<(n4h + 255) / 256, 256>>>(Wq, p_wq, n4h);
    round_w<<<(n4h + 255) / 256, 256>>>(Wk, p_wk, n4h);
    round_w<<<(n4h + 255) / 256, 256>>>(Wv, p_wv, n4h);
    round_w<<<(n4h + 255) / 256, 256>>>(Wo, p_wo, n4h);
    round_w<<<(n4f + 255) / 256, 256>>>(W1, p_w1, n4f);
    round_w<<<(n4f + 255) / 256, 256>>>(W2, p_w2, n4f);

    // 1) LN1 (tf32-rounded output)
    ln_kernel<<<MM, 256>>>(x, g1, be1, p_ln1);

    // 2) QKV projections (rounded outputs feed attention MMAs)
    dim3 gqkv(HH/128, MM/128);
    gemm_tc<0,1><<<gqkv, 256>>>(p_ln1, p_wq, bq, nullptr, p_q, MM, HH, HH);
    gemm_tc<0,1><<<gqkv, 256>>>(p_ln1, p_wk, bk, nullptr, p_k, MM, HH, HH);
    gemm_tc<0,1><<<gqkv, 256>>>(p_ln1, p_wv, bv, nullptr, p_v, MM, HH, HH);

    // 3) tensor-core causal flash attention (rounded output feeds O-proj)
    flash_tc<<<dim3(SS/128, BB*NHH), 256>>>(p_q, p_k, p_v, p_attn);

    // 4) O projection + residual
    gemm_tc<2,0><<<gqkv, 256>>>(p_attn, p_wo, bo, x, p_xatt, MM, HH, HH);

    // 5) LN2
    ln_kernel<<<MM, 256>>>(p_xatt, g2, be2, p_ln2);

    // 6) FFN up + exact GELU (rounded output feeds FFN2)
    gemm_tc<1,1><<<dim3(FFF/128, MM/128), 256>>>(p_ln2, p_w1, b1, nullptr, p_mid, MM, FFF, HH);

    // 7) FFN down + residual
    gemm_tc<2,0><<<dim3(HH/128, MM/128), 256>>>(p_mid, p_w2, b2, p_xatt, out, MM, HH, FFF);
}

// round 5
// speedup vs baseline: 4.3933x; 1.5300x over previous
#include <cuda_runtime.h>
#include <cuda_fp16.h>
#include <math.h>
#include <stdint.h>

// Problem dims (fixed)
#define BB 2
#define SS 2048
#define HH 1024
#define NHH 16
#define DHH 64
#define FFF 4096
#define MM (BB*SS)   // 4096 tokens
#define H3 (3*HH)    // 3072

// ---------------- scratch (device globals; no allocation allowed) ----------
__device__ __half g_ln1h [MM*HH];
__device__ __half g_qkvh [MM*H3];
__device__ __half g_attnh[MM*HH];
__device__ float  g_xatt [MM*HH];
__device__ __half g_ln2h [MM*HH];
__device__ __half g_midh [MM*FFF];
// transposed fp16 weights, stored [N][K] (K-major)
__device__ __half g_wqkvh[H3*HH];
__device__ __half g_woh  [HH*HH];
__device__ __half g_w1h  [FFF*HH];
__device__ __half g_w2h  [HH*FFF];
__device__ float  g_bqkv [H3];

// ---------------- helpers ----------------------------------------------------
__device__ __forceinline__ float gelu_exact(float v) {
    return 0.5f * v * (1.0f + erff(v * 0.70710678118654752f));
}

__device__ __forceinline__ void mma_h(float* d, const unsigned* a,
                                      unsigned b0, unsigned b1) {
    asm volatile(
        "mma.sync.aligned.m16n8k16.row.col.f32.f16.f16.f32 "
        "{%0,%1,%2,%3}, {%4,%5,%6,%7}, {%8,%9}, {%0,%1,%2,%3};\n"
        : "+f"(d[0]), "+f"(d[1]), "+f"(d[2]), "+f"(d[3])
        : "r"(a[0]), "r"(a[1]), "r"(a[2]), "r"(a[3]), "r"(b0), "r"(b1));
}

__device__ __forceinline__ void cp16h(__half* dst, const __half* src) {
    unsigned s = (unsigned)__cvta_generic_to_shared(dst);
    asm volatile("cp.async.cg.shared.global [%0], [%1], 16;\n" :: "r"(s), "l"(src));
}

__device__ __forceinline__ unsigned packh2(float a, float b) {
    __half2 h = __floats2half2_rn(a, b);
    return *(unsigned*)&h;
}

// ---------------- one-shot weight prep --------------------------------------
// in: [K][N] fp32 row-major -> out: [N][K] fp16 row-major
__global__ void transpose_h(const float* __restrict__ in, __half* __restrict__ out,
                            int K, int N) {
    __shared__ float t[32][33];
    int n0 = blockIdx.x * 32, k0 = blockIdx.y * 32;
    int x = threadIdx.x, y = threadIdx.y;     // 32 x 8
    #pragma unroll
    for (int i = 0; i < 32; i += 8)
        t[y + i][x] = in[(size_t)(k0 + y + i) * N + n0 + x];
    __syncthreads();
    #pragma unroll
    for (int i = 0; i < 32; i += 8)
        out[(size_t)(n0 + y + i) * K + k0 + x] = __float2half_rn(t[x][y + i]);
}

__global__ void concat_bias(const float* __restrict__ bq, const float* __restrict__ bk,
                            const float* __restrict__ bv, float* __restrict__ out) {
    int i = blockIdx.x * 256 + threadIdx.x;
    if (i < H3) {
        const float* src = (i < HH) ? bq : (i < 2*HH) ? bk : bv;
        out[i] = src[i & (HH - 1)];
    }
}

// ---------------- layernorm (fp16 output) ------------------------------------
__device__ __forceinline__ float block_reduce_sum(float v) {
    __shared__ float sh[8];
    int lane = threadIdx.x & 31, w = threadIdx.x >> 5;
    #pragma unroll
    for (int o = 16; o > 0; o >>= 1) v += __shfl_xor_sync(0xffffffffu, v, o);
    if (lane == 0) sh[w] = v;
    __syncthreads();
    float t = (threadIdx.x < 8) ? sh[threadIdx.x] : 0.0f;
    if (w == 0) {
        #pragma unroll
        for (int o = 4; o > 0; o >>= 1) t += __shfl_xor_sync(0xffffffffu, t, o);
        if (lane == 0) sh[0] = t;
    }
    __syncthreads();
    float r = sh[0];
    __syncthreads();
    return r;
}

__global__ void ln_kernel(const float* __restrict__ x,
                          const float* __restrict__ g,
                          const float* __restrict__ be,
                          __half* __restrict__ out) {
    int row = blockIdx.x;
    int t = threadIdx.x;
    const float4* xr = (const float4*)(x + (size_t)row * HH);
    float4 v = xr[t];
    float s = v.x + v.y + v.z + v.w;
    float mu = block_reduce_sum(s) * (1.0f / HH);
    float dx = v.x - mu, dy = v.y - mu, dz = v.z - mu, dw = v.w - mu;
    float ss = dx*dx + dy*dy + dz*dz + dw*dw;
    float var = block_reduce_sum(ss) * (1.0f / HH);
    float rstd = rsqrtf(var + 1e-5f);
    float4 gg = ((const float4*)g)[t];
    float4 bb = ((const float4*)be)[t];
    __half2* orow = (__half2*)(out + (size_t)row * HH);
    orow[t*2]     = __floats2half2_rn(dx * rstd * gg.x + bb.x, dy * rstd * gg.y + bb.y);
    orow[t*2 + 1] = __floats2half2_rn(dz * rstd * gg.z + bb.z, dw * rstd * gg.w + bb.w);
}

// ---------------- fp16 tensor-core GEMM --------------------------------------
// C[M,N] = A[M,K] @ Bt[N,K]^T + bias (+epilogue).
// EPI: 0 none, 1 exact GELU, 2 residual.  OUTH: 1 = fp16 output, 0 = fp32.
#define AHS 40   // smem row stride in halfs (80B): conflict-free frag loads

template<int EPI, int OUTH>
__global__ void __launch_bounds__(256, 2)
gemmh(const __half* __restrict__ A, const __half* __restrict__ Bt,
      const float* __restrict__ bias, const float* __restrict__ res,
      void* __restrict__ Cv, int M, int N, int K) {
    __shared__ __half As[2][128][AHS];
    __shared__ __half Bs[2][128][AHS];

    int tid = threadIdx.x, warp = tid >> 5, lane = tid & 31;
    int g = lane >> 2, t4 = lane & 3;
    int wm = warp & 3, wn = warp >> 2;
    int m0 = blockIdx.y * 128, n0 = blockIdx.x * 128;

    float acc[2][8][4] = {};
    int NC = K >> 5;

    // prologue: chunk 0
    #pragma unroll
    for (int q = 0; q < 2; q++) {
        int fid = tid + q * 256;
        int row = fid >> 2, seg = fid & 3;
        cp16h(&As[0][row][seg*8], A  + (size_t)(m0 + row) * K + seg*8);
        cp16h(&Bs[0][row][seg*8], Bt + (size_t)(n0 + row) * K + seg*8);
    }
    asm volatile("cp.async.commit_group;");

    for (int c = 0; c < NC; c++) {
        if (c + 1 < NC) {
            int s = (c + 1) & 1, k0 = (c + 1) * 32;
            #pragma unroll
            for (int q = 0; q < 2; q++) {
                int fid = tid + q * 256;
                int row = fid >> 2, seg = fid & 3;
                cp16h(&As[s][row][seg*8], A  + (size_t)(m0 + row) * K + k0 + seg*8);
                cp16h(&Bs[s][row][seg*8], Bt + (size_t)(n0 + row) * K + k0 + seg*8);
            }
        }
        asm volatile("cp.async.commit_group;");
        asm volatile("cp.async.wait_group 1;");
        __syncthreads();

        const __half (*as)[AHS] = As[c & 1];
        const __half (*bs)[AHS] = Bs[c & 1];
        #pragma unroll
        for (int ks = 0; ks < 2; ks++) {
            int kk = ks * 16;
            unsigned a[2][4];
            #pragma unroll
            for (int mi = 0; mi < 2; mi++) {
                int rm = wm * 32 + mi * 16;
                a[mi][0] = *(const unsigned*)&as[rm + g    ][kk + 2*t4];
                a[mi][1] = *(const unsigned*)&as[rm + g + 8][kk + 2*t4];
                a[mi][2] = *(const unsigned*)&as[rm + g    ][kk + 8 + 2*t4];
                a[mi][3] = *(const unsigned*)&as[rm + g + 8][kk + 8 + 2*t4];
            }
            #pragma unroll
            for (int nj = 0; nj < 8; nj++) {
                int cn = wn * 64 + nj * 8 + g;
                unsigned b0 = *(const unsigned*)&bs[cn][kk + 2*t4];
                unsigned b1 = *(const unsigned*)&bs[cn][kk + 8 + 2*t4];
                mma_h(acc[0][nj], a[0], b0, b1);
                mma_h(acc[1][nj], a[1], b0, b1);
            }
        }
        __syncthreads();
    }

    // epilogue
    #pragma unroll
    for (int mi = 0; mi < 2; mi++) {
        int row = m0 + wm * 32 + mi * 16 + g;
        #pragma unroll
        for (int nj = 0; nj < 8; nj++) {
            int col = n0 + wn * 64 + nj * 8 + 2*t4;
            float b0 = bias[col], b1 = bias[col + 1];
            float v0 = acc[mi][nj][0] + b0;
            float v1 = acc[mi][nj][1] + b1;
            float v2 = acc[mi][nj][2] + b0;
            float v3 = acc[mi][nj][3] + b1;
            if (EPI == 1) {
                v0 = gelu_exact(v0); v1 = gelu_exact(v1);
                v2 = gelu_exact(v2); v3 = gelu_exact(v3);
            }
            if (EPI == 2) {
                v0 += res[(size_t)row * N + col];
                v1 += res[(size_t)row * N + col + 1];
                v2 += res[(size_t)(row + 8) * N + col];
                v3 += res[(size_t)(row + 8) * N + col + 1];
            }
            if (OUTH) {
                __half* C = (__half*)Cv;
                *(__half2*)(C + (size_t)row * N + col) = __floats2half2_rn(v0, v1);
                *(__half2*)(C + (size_t)(row + 8) * N + col) = __floats2half2_rn(v2, v3);
            } else {
                float* C = (float*)Cv;
                *(float2*)(C + (size_t)row * N + col)       = make_float2(v0, v1);
                *(float2*)(C + (size_t)(row + 8) * N + col) = make_float2(v2, v3);
            }
        }
    }
}

// ---------------- fp16 tensor-core flash attention (causal) ------------------
// Br=128 (8 warps x 16 rows), Bc=64. QKV packed [token][3072] fp16.
__global__ void __launch_bounds__(256, 2)
flash_h(const __half* __restrict__ QKV, __half* __restrict__ O) {
    __shared__ __half Ks[64][72];
    __shared__ __half Vt[64][72];   // V transposed: [d][kv]

    int tid = threadIdx.x, warp = tid >> 5, lane = tid & 31;
    int g = lane >> 2, t4 = lane & 3;
    int qt = gridDim.x - 1 - blockIdx.x;          // heavy tiles first
    int bh = blockIdx.y, b = bh >> 4, h = bh & 15;
    size_t rowbase = (size_t)b * SS * H3;
    int qoff = h * 64, koff = HH + h * 64, voff = 2 * HH + h * 64;
    int qbase = qt * 128 + warp * 16;

    // Q fragments register-resident (4 k-chunks of 16)
    unsigned qf[4][4];
    #pragma unroll
    for (int kc = 0; kc < 4; kc++) {
        const __half* q0 = QKV + rowbase + (size_t)(qbase + g)     * H3 + qoff + kc*16 + 2*t4;
        const __half* q1 = QKV + rowbase + (size_t)(qbase + g + 8) * H3 + qoff + kc*16 + 2*t4;
        qf[kc][0] = *(const unsigned*)q0;
        qf[kc][1] = *(const unsigned*)q1;
        qf[kc][2] = *(const unsigned*)(q0 + 8);
        qf[kc][3] = *(const unsigned*)(q1 + 8);
    }

    float oacc[8][4] = {};
    float m0 = -1e30f, m1 = -1e30f, l0 = 0.0f, l1 = 0.0f;
    int row0 = qbase + g, row1 = qbase + g + 8;

    int jmax = 2 * qt + 1;
    for (int j = 0; j <= jmax; j++) {
        // K tile [kv][d]
        #pragma unroll
        for (int it = 0; it < 2; it++) {
            int fid = tid + it * 256;
            int r = fid >> 3, sg = fid & 7;
            *(uint4*)&Ks[r][sg*8] =
                *(const uint4*)(QKV + rowbase + (size_t)(j*64 + r) * H3 + koff + sg*8);
        }
        // V transposed into Vt[d][kv]
        #pragma unroll
        for (int it = 0; it < 8; it++) {
            int idx = tid + it * 256;
            int d2 = idx >> 6, kv = idx & 63;
            __half2 v = *(const __half2*)(QKV + rowbase + (size_t)(j*64 + kv) * H3 + voff + d2*2);
            Vt[d2*2    ][kv] = __low2half(v);
            Vt[d2*2 + 1][kv] = __high2half(v);
        }
        __syncthreads();

        if (j * 64 <= qbase + 15) {
            // S = Q K^T (16x64 per warp)
            float s[8][4] = {};
            #pragma unroll
            for (int kc = 0; kc < 4; kc++) {
                #pragma unroll
                for (int nj = 0; nj < 8; nj++) {
                    unsigned b0 = *(const unsigned*)&Ks[nj*8 + g][kc*16 + 2*t4];
                    unsigned b1 = *(const unsigned*)&Ks[nj*8 + g][kc*16 + 8 + 2*t4];
                    mma_h(s[nj], qf[kc], b0, b1);
                }
            }

            // scale + causal mask + row max
            float mt0 = -1e30f, mt1 = -1e30f;
            #pragma unroll
            for (int nj = 0; nj < 8; nj++) {
                int c0 = j*64 + nj*8 + 2*t4, c1 = c0 + 1;
                float v0 = s[nj][0] * 0.125f, v1 = s[nj][1] * 0.125f;
                float v2 = s[nj][2] * 0.125f, v3 = s[nj][3] * 0.125f;
                if (c0 > row0) v0 = -1e30f;
                if (c1 > row0) v1 = -1e30f;
                if (c0 > row1) v2 = -1e30f;
                if (c1 > row1) v3 = -1e30f;
                s[nj][0] = v0; s[nj][1] = v1; s[nj][2] = v2; s[nj][3] = v3;
                mt0 = fmaxf(mt0, fmaxf(v0, v1));
                mt1 = fmaxf(mt1, fmaxf(v2, v3));
            }
            mt0 = fmaxf(mt0, __shfl_xor_sync(0xffffffffu, mt0, 1));
            mt0 = fmaxf(mt0, __shfl_xor_sync(0xffffffffu, mt0, 2));
            mt1 = fmaxf(mt1, __shfl_xor_sync(0xffffffffu, mt1, 1));
            mt1 = fmaxf(mt1, __shfl_xor_sync(0xffffffffu, mt1, 2));

            float nm0 = fmaxf(m0, mt0), nm1 = fmaxf(m1, mt1);
            float co0 = __expf(m0 - nm0), co1 = __expf(m1 - nm1);
            m0 = nm0; m1 = nm1;

            float rs0 = 0.0f, rs1 = 0.0f;
            #pragma unroll
            for (int nj = 0; nj < 8; nj++) {
                float p0 = __half2float(__float2half_rn(__expf(s[nj][0] - nm0)));
                float p1 = __half2float(__float2half_rn(__expf(s[nj][1] - nm0)));
                float p2 = __half2float(__float2half_rn(__expf(s[nj][2] - nm1)));
                float p3 = __half2float(__float2half_rn(__expf(s[nj][3] - nm1)));
                s[nj][0] = p0; s[nj][1] = p1; s[nj][2] = p2; s[nj][3] = p3;
                rs0 += p0 + p1; rs1 += p2 + p3;
            }
            rs0 += __shfl_xor_sync(0xffffffffu, rs0, 1);
            rs0 += __shfl_xor_sync(0xffffffffu, rs0, 2);
            rs1 += __shfl_xor_sync(0xffffffffu, rs1, 1);
            rs1 += __shfl_xor_sync(0xffffffffu, rs1, 2);
            l0 = l0 * co0 + rs0;
            l1 = l1 * co1 + rs1;

            #pragma unroll
            for (int nd = 0; nd < 8; nd++) {
                oacc[nd][0] *= co0; oacc[nd][1] *= co0;
                oacc[nd][2] *= co1; oacc[nd][3] *= co1;
            }

            // O += P V : C-layout of S == A-layout half2 pairs (no shuffles)
            #pragma unroll
            for (int kc = 0; kc < 4; kc++) {
                unsigned pa[4];
                pa[0] = packh2(s[2*kc][0],     s[2*kc][1]);
                pa[1] = packh2(s[2*kc][2],     s[2*kc][3]);
                pa[2] = packh2(s[2*kc + 1][0], s[2*kc + 1][1]);
                pa[3] = packh2(s[2*kc + 1][2], s[2*kc + 1][3]);
                #pragma unroll
                for (int nd = 0; nd < 8; nd++) {
                    unsigned b0 = *(const unsigned*)&Vt[nd*8 + g][kc*16 + 2*t4];
                    unsigned b1 = *(const unsigned*)&Vt[nd*8 + g][kc*16 + 8 + 2*t4];
                    mma_h(oacc[nd], pa, b0, b1);
                }
            }
        }
        __syncthreads();
    }

    float inv0 = 1.0f / l0, inv1 = 1.0f / l1;
    size_t obase = (size_t)(b * SS) * HH + h * 64;
    #pragma unroll
    for (int nd = 0; nd < 8; nd++) {
        *(__half2*)(O + obase + (size_t)row0 * HH + nd*8 + 2*t4) =
            __floats2half2_rn(oacc[nd][0] * inv0, oacc[nd][1] * inv0);
        *(__half2*)(O + obase + (size_t)row1 * HH + nd*8 + 2*t4) =
            __floats2half2_rn(oacc[nd][2] * inv1, oacc[nd][3] * inv1);
    }
}

// ---------------- launch ----------------------------------------------------
extern "C" void kernel_launch(void* const* d_in, const int* in_sizes, int n_in,
                              void* d_out, int out_size) {
    const float* x   = (const float*)d_in[0];
    const float* Wq  = (const float*)d_in[1];
    const float* bq  = (const float*)d_in[2];
    const float* Wk  = (const float*)d_in[3];
    const float* bk  = (const float*)d_in[4];
    const float* Wv  = (const float*)d_in[5];
    const float* bv  = (const float*)d_in[6];
    const float* Wo  = (const float*)d_in[7];
    const float* bo  = (const float*)d_in[8];
    const float* W1  = (const float*)d_in[9];
    const float* b1  = (const float*)d_in[10];
    const float* W2  = (const float*)d_in[11];
    const float* b2  = (const float*)d_in[12];
    const float* g1  = (const float*)d_in[13];
    const float* be1 = (const float*)d_in[14];
    const float* g2  = (const float*)d_in[15];
    const float* be2 = (const float*)d_in[16];
    float* out = (float*)d_out;

    __half *p_ln1h, *p_qkvh, *p_attnh, *p_ln2h, *p_midh;
    __half *p_wqkvh, *p_woh, *p_w1h, *p_w2h;
    float *p_xatt, *p_bqkv;
    cudaGetSymbolAddress((void**)&p_ln1h,  g_ln1h);
    cudaGetSymbolAddress((void**)&p_qkvh,  g_qkvh);
    cudaGetSymbolAddress((void**)&p_attnh, g_attnh);
    cudaGetSymbolAddress((void**)&p_xatt,  g_xatt);
    cudaGetSymbolAddress((void**)&p_ln2h,  g_ln2h);
    cudaGetSymbolAddress((void**)&p_midh,  g_midh);
    cudaGetSymbolAddress((void**)&p_wqkvh, g_wqkvh);
    cudaGetSymbolAddress((void**)&p_woh,   g_woh);
    cudaGetSymbolAddress((void**)&p_w1h,   g_w1h);
    cudaGetSymbolAddress((void**)&p_w2h,   g_w2h);
    cudaGetSymbolAddress((void**)&p_bqkv,  g_bqkv);

    // 0) weight prep: transpose + fp16 convert; bias concat
    dim3 tb(32, 8);
    transpose_h<<<dim3(HH/32,  HH/32),  tb>>>(Wq, p_wqkvh,             HH, HH);
    transpose_h<<<dim3(HH/32,  HH/32),  tb>>>(Wk, p_wqkvh + HH*HH,     HH, HH);
    transpose_h<<<dim3(HH/32,  HH/32),  tb>>>(Wv, p_wqkvh + 2*HH*HH,   HH, HH);
    transpose_h<<<dim3(HH/32,  HH/32),  tb>>>(Wo, p_woh,               HH, HH);
    transpose_h<<<dim3(FFF/32, HH/32),  tb>>>(W1, p_w1h,               HH, FFF);
    transpose_h<<<dim3(HH/32,  FFF/32), tb>>>(W2, p_w2h,               FFF, HH);
    concat_bias<<<(H3 + 255) / 256, 256>>>(bq, bk, bv, p_bqkv);

    // 1) LN1 -> fp16
    ln_kernel<<<MM, 256>>>(x, g1, be1, p_ln1h);

    // 2) fused QKV projection (fp16 tensor cores)
    gemmh<0,1><<<dim3(H3/128, MM/128), 256>>>(p_ln1h, p_wqkvh, p_bqkv, nullptr,
                                              p_qkvh, MM, H3, HH);

    // 3) fp16 causal flash attention
    flash_h<<<dim3(SS/128, BB*NHH), 256>>>(p_qkvh, p_attnh);

    // 4) O projection + residual (fp32 out)
    gemmh<2,0><<<dim3(HH/128, MM/128), 256>>>(p_attnh, p_woh, bo, x,
                                              p_xatt, MM, HH, HH);

    // 5) LN2 -> fp16
    ln_kernel<<<MM, 256>>>(p_xatt, g2, be2, p_ln2h);

    // 6) FFN up + exact GELU (fp16 out)
    gemmh<1,1><<<dim3(FFF/128, MM/128), 256>>>(p_ln2h, p_w1h, b1, nullptr,
                                               p_midh, MM, FFF, HH);

    // 7) FFN down + residual (fp32 out)
    gemmh<2,0><<<dim3(HH/128, MM/128), 256>>>(p_midh, p_w2h, b2, p_xatt,
                                              out, MM, HH, FFF);
}

// round 6
// speedup vs baseline: 5.6028x; 1.2753x over previous
#include <cuda_runtime.h>
#include <cuda_fp16.h>
#include <math.h>
#include <stdint.h>

// Problem dims (fixed)
#define BB 2
#define SS 2048
#define HH 1024
#define NHH 16
#define DHH 64
#define FFF 4096
#define MM (BB*SS)   // 4096 tokens
#define H3 (3*HH)    // 3072

// ---------------- scratch (device globals; no allocation allowed) ----------
__device__ __half g_ln1h [MM*HH];
__device__ __half g_qkvh [MM*H3];
__device__ __half g_attnh[MM*HH];
__device__ float  g_xatt [MM*HH];
__device__ __half g_ln2h [MM*HH];
__device__ __half g_midh [MM*FFF];
// transposed fp16 weights, stored [N][K] (K-major)
__device__ __half g_wqkvh[H3*HH];
__device__ __half g_woh  [HH*HH];
__device__ __half g_w1h  [FFF*HH];
__device__ __half g_w2h  [HH*FFF];
__device__ float  g_bqkv [H3];

// ---------------- helpers ----------------------------------------------------
__device__ __forceinline__ float gelu_exact(float v) {
    return 0.5f * v * (1.0f + erff(v * 0.70710678118654752f));
}

__device__ __forceinline__ void mma_h(float* d, const unsigned* a,
                                      unsigned b0, unsigned b1) {
    asm volatile(
        "mma.sync.aligned.m16n8k16.row.col.f32.f16.f16.f32 "
        "{%0,%1,%2,%3}, {%4,%5,%6,%7}, {%8,%9}, {%0,%1,%2,%3};\n"
        : "+f"(d[0]), "+f"(d[1]), "+f"(d[2]), "+f"(d[3])
        : "r"(a[0]), "r"(a[1]), "r"(a[2]), "r"(a[3]), "r"(b0), "r"(b1));
}

__device__ __forceinline__ void ldsm_x4(unsigned* r, uint32_t a) {
    asm volatile("ldmatrix.sync.aligned.m8n8.x4.shared.b16 {%0,%1,%2,%3}, [%4];"
        : "=r"(r[0]), "=r"(r[1]), "=r"(r[2]), "=r"(r[3]) : "r"(a));
}
__device__ __forceinline__ void ldsm_x4t(unsigned* r, uint32_t a) {
    asm volatile("ldmatrix.sync.aligned.m8n8.x4.trans.shared.b16 {%0,%1,%2,%3}, [%4];"
        : "=r"(r[0]), "=r"(r[1]), "=r"(r[2]), "=r"(r[3]) : "r"(a));
}

__device__ __forceinline__ void cp16h(__half* dst, const __half* src) {
    unsigned s = (unsigned)__cvta_generic_to_shared(dst);
    asm volatile("cp.async.cg.shared.global [%0], [%1], 16;\n" :: "r"(s), "l"(src));
}

__device__ __forceinline__ unsigned packh2(float a, float b) {
    __half2 h = __floats2half2_rn(a, b);
    return *(unsigned*)&h;
}

// ---------------- one-shot weight prep (single launch) -----------------------
__global__ void prep_weights(const float* __restrict__ Wq, const float* __restrict__ Wk,
                             const float* __restrict__ Wv, const float* __restrict__ Wo,
                             const float* __restrict__ W1, const float* __restrict__ W2,
                             __half* __restrict__ wqkv, __half* __restrict__ wo,
                             __half* __restrict__ w1,   __half* __restrict__ w2) {
    __shared__ float t[32][33];
    int bid = blockIdx.x;
    const float* src; __half* dst; int K, N, b0i;
    if      (bid < 1024) { src = Wq; dst = wqkv;           K = HH;  N = HH;  b0i = 0;    }
    else if (bid < 2048) { src = Wk; dst = wqkv + HH*HH;   K = HH;  N = HH;  b0i = 1024; }
    else if (bid < 3072) { src = Wv; dst = wqkv + 2*HH*HH; K = HH;  N = HH;  b0i = 2048; }
    else if (bid < 4096) { src = Wo; dst = wo;             K = HH;  N = HH;  b0i = 3072; }
    else if (bid < 8192) { src = W1; dst = w1;             K = HH;  N = FFF; b0i = 4096; }
    else                 { src = W2; dst = w2;             K = FFF; N = HH;  b0i = 8192; }
    int lb = bid - b0i;
    int gx = N / 32;
    int n0 = (lb % gx) * 32, k0 = (lb / gx) * 32;
    int x = threadIdx.x, y = threadIdx.y;     // 32 x 8
    #pragma unroll
    for (int i = 0; i < 32; i += 8)
        t[y + i][x] = src[(size_t)(k0 + y + i) * N + n0 + x];
    __syncthreads();
    #pragma unroll
    for (int i = 0; i < 32; i += 8)
        dst[(size_t)(n0 + y + i) * K + k0 + x] = __float2half_rn(t[x][y + i]);
}

__global__ void concat_bias(const float* __restrict__ bq, const float* __restrict__ bk,
                            const float* __restrict__ bv, float* __restrict__ out) {
    int i = blockIdx.x * 256 + threadIdx.x;
    if (i < H3) {
        const float* src = (i < HH) ? bq : (i < 2*HH) ? bk : bv;
        out[i] = src[i & (HH - 1)];
    }
}

// ---------------- layernorm (fp16 output) ------------------------------------
__device__ __forceinline__ float block_reduce_sum(float v) {
    __shared__ float sh[8];
    int lane = threadIdx.x & 31, w = threadIdx.x >> 5;
    #pragma unroll
    for (int o = 16; o > 0; o >>= 1) v += __shfl_xor_sync(0xffffffffu, v, o);
    if (lane == 0) sh[w] = v;
    __syncthreads();
    float t = (threadIdx.x < 8) ? sh[threadIdx.x] : 0.0f;
    if (w == 0) {
        #pragma unroll
        for (int o = 4; o > 0; o >>= 1) t += __shfl_xor_sync(0xffffffffu, t, o);
        if (lane == 0) sh[0] = t;
    }
    __syncthreads();
    float r = sh[0];
    __syncthreads();
    return r;
}

__global__ void ln_kernel(const float* __restrict__ x,
                          const float* __restrict__ g,
                          const float* __restrict__ be,
                          __half* __restrict__ out) {
    int row = blockIdx.x;
    int t = threadIdx.x;
    const float4* xr = (const float4*)(x + (size_t)row * HH);
    float4 v = xr[t];
    float s = v.x + v.y + v.z + v.w;
    float mu = block_reduce_sum(s) * (1.0f / HH);
    float dx = v.x - mu, dy = v.y - mu, dz = v.z - mu, dw = v.w - mu;
    float ss = dx*dx + dy*dy + dz*dz + dw*dw;
    float var = block_reduce_sum(ss) * (1.0f / HH);
    float rstd = rsqrtf(var + 1e-5f);
    float4 gg = ((const float4*)g)[t];
    float4 bb = ((const float4*)be)[t];
    __half2* orow = (__half2*)(out + (size_t)row * HH);
    orow[t*2]     = __floats2half2_rn(dx * rstd * gg.x + bb.x, dy * rstd * gg.y + bb.y);
    orow[t*2 + 1] = __floats2half2_rn(dz * rstd * gg.z + bb.z, dw * rstd * gg.w + bb.w);
}

// ---------------- fp16 tensor-core GEMM (ldmatrix fragments) ------------------
// C[M,N] = A[M,K] @ Bt[N,K]^T + bias (+epilogue).
// EPI: 0 none, 1 exact GELU, 2 residual.  OUTH: 1 = fp16 output, 0 = fp32.
#define AHS 40   // smem row stride in halfs (80B): conflict-free ldmatrix phases

template<int EPI, int OUTH>
__global__ void __launch_bounds__(256, 2)
gemmh(const __half* __restrict__ A, const __half* __restrict__ Bt,
      const float* __restrict__ bias, const float* __restrict__ res,
      void* __restrict__ Cv, int M, int N, int K) {
    __shared__ __half As[2][128][AHS];
    __shared__ __half Bs[2][128][AHS];

    int tid = threadIdx.x, warp = tid >> 5, lane = tid & 31;
    int g = lane >> 3 ? 0 : 0; (void)g;  // placeholder to keep structure clear
    int l8 = lane & 7;
    int gq = lane >> 2, t4 = lane & 3;
    int wm = warp & 3, wn = warp >> 2;
    int m0 = blockIdx.y * 128, n0 = blockIdx.x * 128;

    float acc[2][8][4] = {};
    int NC = K >> 5;

    uint32_t asb = (uint32_t)__cvta_generic_to_shared(&As[0][0][0]);
    uint32_t bsb = (uint32_t)__cvta_generic_to_shared(&Bs[0][0][0]);
    const uint32_t stgB = 128 * AHS * 2;   // bytes per stage

    // ldmatrix lane-address components
    int a_r  = l8 + ((lane >> 3) & 1) * 8;     // row within 16 (A/B/K tiles)
    int a_c8 = (lane >> 4) * 8;                // k-col half offset for A
    int b_n  = ((lane >> 4)) * 8 + l8;         // n-row offset within nj pair for B
    int b_c8 = ((lane >> 3) & 1) * 8;          // k-col half offset for B

    // prologue: chunk 0
    #pragma unroll
    for (int q = 0; q < 2; q++) {
        int fid = tid + q * 256;
        int row = fid >> 2, seg = fid & 3;
        cp16h(&As[0][row][seg*8], A  + (size_t)(m0 + row) * K + seg*8);
        cp16h(&Bs[0][row][seg*8], Bt + (size_t)(n0 + row) * K + seg*8);
    }
    asm volatile("cp.async.commit_group;");

    for (int c = 0; c < NC; c++) {
        if (c + 1 < NC) {
            int s = (c + 1) & 1, k0 = (c + 1) * 32;
            #pragma unroll
            for (int q = 0; q < 2; q++) {
                int fid = tid + q * 256;
                int row = fid >> 2, seg = fid & 3;
                cp16h(&As[s][row][seg*8], A  + (size_t)(m0 + row) * K + k0 + seg*8);
                cp16h(&Bs[s][row][seg*8], Bt + (size_t)(n0 + row) * K + k0 + seg*8);
            }
        }
        asm volatile("cp.async.commit_group;");
        asm volatile("cp.async.wait_group 1;");
        __syncthreads();

        uint32_t asc = asb + (c & 1) * stgB;
        uint32_t bsc = bsb + (c & 1) * stgB;
        #pragma unroll
        for (int ks = 0; ks < 2; ks++) {
            int kk = ks * 16;
            unsigned a[2][4];
            #pragma unroll
            for (int mi = 0; mi < 2; mi++) {
                int row = wm * 32 + mi * 16 + a_r;
                ldsm_x4(a[mi], asc + (uint32_t)(row * AHS + kk + a_c8) * 2);
            }
            #pragma unroll
            for (int p = 0; p < 4; p++) {
                unsigned bfrag[4];
                int row = wn * 64 + p * 16 + b_n;
                ldsm_x4(bfrag, bsc + (uint32_t)(row * AHS + kk + b_c8) * 2);
                mma_h(acc[0][2*p],     a[0], bfrag[0], bfrag[1]);
                mma_h(acc[1][2*p],     a[1], bfrag[0], bfrag[1]);
                mma_h(acc[0][2*p + 1], a[0], bfrag[2], bfrag[3]);
                mma_h(acc[1][2*p + 1], a[1], bfrag[2], bfrag[3]);
            }
        }
        __syncthreads();
    }

    // epilogue
    #pragma unroll
    for (int mi = 0; mi < 2; mi++) {
        int row = m0 + wm * 32 + mi * 16 + gq;
        #pragma unroll
        for (int nj = 0; nj < 8; nj++) {
            int col = n0 + wn * 64 + nj * 8 + 2*t4;
            float b0 = bias[col], b1 = bias[col + 1];
            float v0 = acc[mi][nj][0] + b0;
            float v1 = acc[mi][nj][1] + b1;
            float v2 = acc[mi][nj][2] + b0;
            float v3 = acc[mi][nj][3] + b1;
            if (EPI == 1) {
                v0 = gelu_exact(v0); v1 = gelu_exact(v1);
                v2 = gelu_exact(v2); v3 = gelu_exact(v3);
            }
            if (EPI == 2) {
                v0 += res[(size_t)row * N + col];
                v1 += res[(size_t)row * N + col + 1];
                v2 += res[(size_t)(row + 8) * N + col];
                v3 += res[(size_t)(row + 8) * N + col + 1];
            }
            if (OUTH) {
                __half* C = (__half*)Cv;
                *(__half2*)(C + (size_t)row * N + col) = __floats2half2_rn(v0, v1);
                *(__half2*)(C + (size_t)(row + 8) * N + col) = __floats2half2_rn(v2, v3);
            } else {
                float* C = (float*)Cv;
                *(float2*)(C + (size_t)row * N + col)       = make_float2(v0, v1);
                *(float2*)(C + (size_t)(row + 8) * N + col) = make_float2(v2, v3);
            }
        }
    }
}

// ---------------- fp16 tensor-core flash attention (causal, ldmatrix) --------
// Br=128 (8 warps x 16 rows), Bc=64. QKV packed [token][3072] fp16.
#define FVS 72

__global__ void __launch_bounds__(256, 2)
flash_h(const __half* __restrict__ QKV, __half* __restrict__ O) {
    __shared__ __half Ks[64][FVS];
    __shared__ __half Vs[64][FVS];   // [kv][d]; transposed at use via ldmatrix.trans

    int tid = threadIdx.x, warp = tid >> 5, lane = tid & 31;
    int l8 = lane & 7;
    int gq = lane >> 2, t4 = lane & 3;
    int qt = gridDim.x - 1 - blockIdx.x;          // heavy tiles first
    int bh = blockIdx.y, b = bh >> 4, h = bh & 15;
    size_t rowbase = (size_t)b * SS * H3;
    int qoff = h * 64, koff = HH + h * 64, voff = 2 * HH + h * 64;
    int qbase = qt * 128 + warp * 16;

    uint32_t ksb = (uint32_t)__cvta_generic_to_shared(&Ks[0][0]);
    uint32_t vsb = (uint32_t)__cvta_generic_to_shared(&Vs[0][0]);

    // ldmatrix address components (same derivation as GEMM B)
    int b_n  = (lane >> 4) * 8 + l8;
    int b_c8 = ((lane >> 3) & 1) * 8;
    // V-trans: rows = kv, col-block = d
    int v_r  = ((lane >> 3) & 1) * 8 + l8;
    int v_d  = (lane >> 4) * 8;

    // Q fragments register-resident (4 k-chunks of 16)
    unsigned qf[4][4];
    #pragma unroll
    for (int kc = 0; kc < 4; kc++) {
        const __half* q0 = QKV + rowbase + (size_t)(qbase + gq)     * H3 + qoff + kc*16 + 2*t4;
        const __half* q1 = QKV + rowbase + (size_t)(qbase + gq + 8) * H3 + qoff + kc*16 + 2*t4;
        qf[kc][0] = *(const unsigned*)q0;
        qf[kc][1] = *(const unsigned*)q1;
        qf[kc][2] = *(const unsigned*)(q0 + 8);
        qf[kc][3] = *(const unsigned*)(q1 + 8);
    }

    float oacc[8][4] = {};
    float m0 = -1e30f, m1 = -1e30f, l0 = 0.0f, l1 = 0.0f;
    int row0 = qbase + gq, row1 = qbase + gq + 8;

    int jmax = 2 * qt + 1;
    for (int j = 0; j <= jmax; j++) {
        // K and V tiles [kv][d], coalesced uint4
        #pragma unroll
        for (int it = 0; it < 2; it++) {
            int fid = tid + it * 256;
            int r = fid >> 3, sg = fid & 7;
            *(uint4*)&Ks[r][sg*8] =
                *(const uint4*)(QKV + rowbase + (size_t)(j*64 + r) * H3 + koff + sg*8);
            *(uint4*)&Vs[r][sg*8] =
                *(const uint4*)(QKV + rowbase + (size_t)(j*64 + r) * H3 + voff + sg*8);
        }
        __syncthreads();

        if (j * 64 <= qbase + 15) {
            // S = Q K^T (16x64 per warp)
            float s[8][4] = {};
            #pragma unroll
            for (int kc = 0; kc < 4; kc++) {
                #pragma unroll
                for (int p = 0; p < 4; p++) {
                    unsigned kb[4];
                    int row = p * 16 + b_n;
                    ldsm_x4(kb, ksb + (uint32_t)(row * FVS + kc*16 + b_c8) * 2);
                    mma_h(s[2*p],     qf[kc], kb[0], kb[1]);
                    mma_h(s[2*p + 1], qf[kc], kb[2], kb[3]);
                }
            }

            // scale + causal mask + row max
            float mt0 = -1e30f, mt1 = -1e30f;
            #pragma unroll
            for (int nj = 0; nj < 8; nj++) {
                int c0 = j*64 + nj*8 + 2*t4, c1 = c0 + 1;
                float v0 = s[nj][0] * 0.125f, v1 = s[nj][1] * 0.125f;
                float v2 = s[nj][2] * 0.125f, v3 = s[nj][3] * 0.125f;
                if (c0 > row0) v0 = -1e30f;
                if (c1 > row0) v1 = -1e30f;
                if (c0 > row1) v2 = -1e30f;
                if (c1 > row1) v3 = -1e30f;
                s[nj][0] = v0; s[nj][1] = v1; s[nj][2] = v2; s[nj][3] = v3;
                mt0 = fmaxf(mt0, fmaxf(v0, v1));
                mt1 = fmaxf(mt1, fmaxf(v2, v3));
            }
            mt0 = fmaxf(mt0, __shfl_xor_sync(0xffffffffu, mt0, 1));
            mt0 = fmaxf(mt0, __shfl_xor_sync(0xffffffffu, mt0, 2));
            mt1 = fmaxf(mt1, __shfl_xor_sync(0xffffffffu, mt1, 1));
            mt1 = fmaxf(mt1, __shfl_xor_sync(0xffffffffu, mt1, 2));

            float nm0 = fmaxf(m0, mt0), nm1 = fmaxf(m1, mt1);
            float co0 = __expf(m0 - nm0), co1 = __expf(m1 - nm1);
            m0 = nm0; m1 = nm1;

            float rs0 = 0.0f, rs1 = 0.0f;
            #pragma unroll
            for (int nj = 0; nj < 8; nj++) {
                float p0 = __half2float(__float2half_rn(__expf(s[nj][0] - nm0)));
                float p1 = __half2float(__float2half_rn(__expf(s[nj][1] - nm0)));
                float p2 = __half2float(__float2half_rn(__expf(s[nj][2] - nm1)));
                float p3 = __half2float(__float2half_rn(__expf(s[nj][3] - nm1)));
                s[nj][0] = p0; s[nj][1] = p1; s[nj][2] = p2; s[nj][3] = p3;
                rs0 += p0 + p1; rs1 += p2 + p3;
            }
            rs0 += __shfl_xor_sync(0xffffffffu, rs0, 1);
            rs0 += __shfl_xor_sync(0xffffffffu, rs0, 2);
            rs1 += __shfl_xor_sync(0xffffffffu, rs1, 1);
            rs1 += __shfl_xor_sync(0xffffffffu, rs1, 2);
            l0 = l0 * co0 + rs0;
            l1 = l1 * co1 + rs1;

            #pragma unroll
            for (int nd = 0; nd < 8; nd++) {
                oacc[nd][0] *= co0; oacc[nd][1] *= co0;
                oacc[nd][2] *= co1; oacc[nd][3] *= co1;
            }

            // O += P V : A-frag of P by register repack; V^T via ldmatrix.trans
            #pragma unroll
            for (int kc = 0; kc < 4; kc++) {
                unsigned pa[4];
                pa[0] = packh2(s[2*kc][0],     s[2*kc][1]);
                pa[1] = packh2(s[2*kc][2],     s[2*kc][3]);
                pa[2] = packh2(s[2*kc + 1][0], s[2*kc + 1][1]);
                pa[3] = packh2(s[2*kc + 1][2], s[2*kc + 1][3]);
                #pragma unroll
                for (int p = 0; p < 4; p++) {
                    unsigned vb[4];
                    int row = kc * 16 + v_r;
                    ldsm_x4t(vb, vsb + (uint32_t)(row * FVS + p * 16 + v_d) * 2);
                    mma_h(oacc[2*p],     pa, vb[0], vb[1]);
                    mma_h(oacc[2*p + 1], pa, vb[2], vb[3]);
                }
            }
        }
        __syncthreads();
    }

    float inv0 = 1.0f / l0, inv1 = 1.0f / l1;
    size_t obase = (size_t)(b * SS) * HH + h * 64;
    #pragma unroll
    for (int nd = 0; nd < 8; nd++) {
        *(__half2*)(O + obase + (size_t)row0 * HH + nd*8 + 2*t4) =
            __floats2half2_rn(oacc[nd][0] * inv0, oacc[nd][1] * inv0);
        *(__half2*)(O + obase + (size_t)row1 * HH + nd*8 + 2*t4) =
            __floats2half2_rn(oacc[nd][2] * inv1, oacc[nd][3] * inv1);
    }
}

// ---------------- launch ----------------------------------------------------
extern "C" void kernel_launch(void* const* d_in, const int* in_sizes, int n_in,
                              void* d_out, int out_size) {
    const float* x   = (const float*)d_in[0];
    const float* Wq  = (const float*)d_in[1];
    const float* bq  = (const float*)d_in[2];
    const float* Wk  = (const float*)d_in[3];
    const float* bk  = (const float*)d_in[4];
    const float* Wv  = (const float*)d_in[5];
    const float* bv  = (const float*)d_in[6];
    const float* Wo  = (const float*)d_in[7];
    const float* bo  = (const float*)d_in[8];
    const float* W1  = (const float*)d_in[9];
    const float* b1  = (const float*)d_in[10];
    const float* W2  = (const float*)d_in[11];
    const float* b2  = (const float*)d_in[12];
    const float* g1  = (const float*)d_in[13];
    const float* be1 = (const float*)d_in[14];
    const float* g2  = (const float*)d_in[15];
    const float* be2 = (const float*)d_in[16];
    float* out = (float*)d_out;

    __half *p_ln1h, *p_qkvh, *p_attnh, *p_ln2h, *p_midh;
    __half *p_wqkvh, *p_woh, *p_w1h, *p_w2h;
    float *p_xatt, *p_bqkv;
    cudaGetSymbolAddress((void**)&p_ln1h,  g_ln1h);
    cudaGetSymbolAddress((void**)&p_qkvh,  g_qkvh);
    cudaGetSymbolAddress((void**)&p_attnh, g_attnh);
    cudaGetSymbolAddress((void**)&p_xatt,  g_xatt);
    cudaGetSymbolAddress((void**)&p_ln2h,  g_ln2h);
    cudaGetSymbolAddress((void**)&p_midh,  g_midh);
    cudaGetSymbolAddress((void**)&p_wqkvh, g_wqkvh);
    cudaGetSymbolAddress((void**)&p_woh,   g_woh);
    cudaGetSymbolAddress((void**)&p_w1h,   g_w1h);
    cudaGetSymbolAddress((void**)&p_w2h,   g_w2h);
    cudaGetSymbolAddress((void**)&p_bqkv,  g_bqkv);

    // 0) weight prep: one batched transpose launch + bias concat
    prep_weights<<<12288, dim3(32, 8)>>>(Wq, Wk, Wv, Wo, W1, W2,
                                         p_wqkvh, p_woh, p_w1h, p_w2h);
    concat_bias<<<(H3 + 255) / 256, 256>>>(bq, bk, bv, p_bqkv);

    // 1) LN1 -> fp16
    ln_kernel<<<MM, 256>>>(x, g1, be1, p_ln1h);

    // 2) fused QKV projection (fp16 tensor cores)
    gemmh<0,1><<<dim3(H3/128, MM/128), 256>>>(p_ln1h, p_wqkvh, p_bqkv, nullptr,
                                              p_qkvh, MM, H3, HH);

    // 3) fp16 causal flash attention
    flash_h<<<dim3(SS/128, BB*NHH), 256>>>(p_qkvh, p_attnh);

    // 4) O projection + residual (fp32 out)
    gemmh<2,0><<<dim3(HH/128, MM/128), 256>>>(p_attnh, p_woh, bo, x,
                                              p_xatt, MM, HH, HH);

    // 5) LN2 -> fp16
    ln_kernel<<<MM, 256>>>(p_xatt, g2, be2, p_ln2h);

    // 6) FFN up + exact GELU (fp16 out)
    gemmh<1,1><<<dim3(FFF/128, MM/128), 256>>>(p_ln2h, p_w1h, b1, nullptr,
                                               p_midh, MM, FFF, HH);

    // 7) FFN down + residual (fp32 out)
    gemmh<2,0><<<dim3(HH/128, MM/128), 256>>>(p_midh, p_w2h, b2, p_xatt,
                                              out, MM, HH, FFF);
}

// round 7
// speedup vs baseline: 6.0001x; 1.0709x over previous
#include <cuda_runtime.h>
#include <cuda_fp16.h>
#include <math.h>
#include <stdint.h>

// Problem dims (fixed)
#define BB 2
#define SS 2048
#define HH 1024
#define NHH 16
#define DHH 64
#define FFF 4096
#define MM (BB*SS)   // 4096 tokens
#define H3 (3*HH)    // 3072

// ---------------- scratch (device globals; no allocation allowed) ----------
__device__ __half g_ln1h [MM*HH];
__device__ __half g_qkvh [MM*H3];
__device__ __half g_attnh[MM*HH];
__device__ float  g_xatt [MM*HH];
__device__ __half g_ln2h [MM*HH];
__device__ __half g_midh [MM*FFF];
// transposed fp16 weights, stored [N][K] (K-major)
__device__ __half g_wqkvh[H3*HH];
__device__ __half g_woh  [HH*HH];
__device__ __half g_w1h  [FFF*HH];
__device__ __half g_w2h  [HH*FFF];
__device__ float  g_bqkv [H3];

// ---------------- helpers ----------------------------------------------------
__device__ __forceinline__ float gelu_exact(float v) {
    return 0.5f * v * (1.0f + erff(v * 0.70710678118654752f));
}

__device__ __forceinline__ void mma_h(float* d, const unsigned* a,
                                      unsigned b0, unsigned b1) {
    asm volatile(
        "mma.sync.aligned.m16n8k16.row.col.f32.f16.f16.f32 "
        "{%0,%1,%2,%3}, {%4,%5,%6,%7}, {%8,%9}, {%0,%1,%2,%3};\n"
        : "+f"(d[0]), "+f"(d[1]), "+f"(d[2]), "+f"(d[3])
        : "r"(a[0]), "r"(a[1]), "r"(a[2]), "r"(a[3]), "r"(b0), "r"(b1));
}

__device__ __forceinline__ void ldsm_x4(unsigned* r, uint32_t a) {
    asm volatile("ldmatrix.sync.aligned.m8n8.x4.shared.b16 {%0,%1,%2,%3}, [%4];"
        : "=r"(r[0]), "=r"(r[1]), "=r"(r[2]), "=r"(r[3]) : "r"(a));
}
__device__ __forceinline__ void ldsm_x4t(unsigned* r, uint32_t a) {
    asm volatile("ldmatrix.sync.aligned.m8n8.x4.trans.shared.b16 {%0,%1,%2,%3}, [%4];"
        : "=r"(r[0]), "=r"(r[1]), "=r"(r[2]), "=r"(r[3]) : "r"(a));
}

__device__ __forceinline__ void cp16h(__half* dst, const __half* src) {
    unsigned s = (unsigned)__cvta_generic_to_shared(dst);
    asm volatile("cp.async.cg.shared.global [%0], [%1], 16;\n" :: "r"(s), "l"(src));
}

__device__ __forceinline__ unsigned packh2(float a, float b) {
    __half2 h = __floats2half2_rn(a, b);
    return *(unsigned*)&h;
}

// ---------------- one-shot weight prep (single launch) -----------------------
__global__ void prep_weights(const float* __restrict__ Wq, const float* __restrict__ Wk,
                             const float* __restrict__ Wv, const float* __restrict__ Wo,
                             const float* __restrict__ W1, const float* __restrict__ W2,
                             __half* __restrict__ wqkv, __half* __restrict__ wo,
                             __half* __restrict__ w1,   __half* __restrict__ w2) {
    __shared__ float t[32][33];
    int bid = blockIdx.x;
    const float* src; __half* dst; int K, N, b0i;
    if      (bid < 1024) { src = Wq; dst = wqkv;           K = HH;  N = HH;  b0i = 0;    }
    else if (bid < 2048) { src = Wk; dst = wqkv + HH*HH;   K = HH;  N = HH;  b0i = 1024; }
    else if (bid < 3072) { src = Wv; dst = wqkv + 2*HH*HH; K = HH;  N = HH;  b0i = 2048; }
    else if (bid < 4096) { src = Wo; dst = wo;             K = HH;  N = HH;  b0i = 3072; }
    else if (bid < 8192) { src = W1; dst = w1;             K = HH;  N = FFF; b0i = 4096; }
    else                 { src = W2; dst = w2;             K = FFF; N = HH;  b0i = 8192; }
    int lb = bid - b0i;
    int gx = N / 32;
    int n0 = (lb % gx) * 32, k0 = (lb / gx) * 32;
    int x = threadIdx.x, y = threadIdx.y;     // 32 x 8
    #pragma unroll
    for (int i = 0; i < 32; i += 8)
        t[y + i][x] = src[(size_t)(k0 + y + i) * N + n0 + x];
    __syncthreads();
    #pragma unroll
    for (int i = 0; i < 32; i += 8)
        dst[(size_t)(n0 + y + i) * K + k0 + x] = __float2half_rn(t[x][y + i]);
}

__global__ void concat_bias(const float* __restrict__ bq, const float* __restrict__ bk,
                            const float* __restrict__ bv, float* __restrict__ out) {
    int i = blockIdx.x * 256 + threadIdx.x;
    if (i < H3) {
        const float* src = (i < HH) ? bq : (i < 2*HH) ? bk : bv;
        out[i] = src[i & (HH - 1)];
    }
}

// ---------------- layernorm (fp16 output) ------------------------------------
__device__ __forceinline__ float block_reduce_sum(float v) {
    __shared__ float sh[8];
    int lane = threadIdx.x & 31, w = threadIdx.x >> 5;
    #pragma unroll
    for (int o = 16; o > 0; o >>= 1) v += __shfl_xor_sync(0xffffffffu, v, o);
    if (lane == 0) sh[w] = v;
    __syncthreads();
    float t = (threadIdx.x < 8) ? sh[threadIdx.x] : 0.0f;
    if (w == 0) {
        #pragma unroll
        for (int o = 4; o > 0; o >>= 1) t += __shfl_xor_sync(0xffffffffu, t, o);
        if (lane == 0) sh[0] = t;
    }
    __syncthreads();
    float r = sh[0];
    __syncthreads();
    return r;
}

__global__ void ln_kernel(const float* __restrict__ x,
                          const float* __restrict__ g,
                          const float* __restrict__ be,
                          __half* __restrict__ out) {
    int row = blockIdx.x;
    int t = threadIdx.x;
    const float4* xr = (const float4*)(x + (size_t)row * HH);
    float4 v = xr[t];
    float s = v.x + v.y + v.z + v.w;
    float mu = block_reduce_sum(s) * (1.0f / HH);
    float dx = v.x - mu, dy = v.y - mu, dz = v.z - mu, dw = v.w - mu;
    float ss = dx*dx + dy*dy + dz*dz + dw*dw;
    float var = block_reduce_sum(ss) * (1.0f / HH);
    float rstd = rsqrtf(var + 1e-5f);
    float4 gg = ((const float4*)g)[t];
    float4 bb = ((const float4*)be)[t];
    __half2* orow = (__half2*)(out + (size_t)row * HH);
    orow[t*2]     = __floats2half2_rn(dx * rstd * gg.x + bb.x, dy * rstd * gg.y + bb.y);
    orow[t*2 + 1] = __floats2half2_rn(dz * rstd * gg.z + bb.z, dw * rstd * gg.w + bb.w);
}

// ---------------- fp16 tensor-core GEMM (4-stage multistage) ------------------
// C[M,N] = A[M,K] @ Bt[N,K]^T + bias (+epilogue).
// EPI: 0 none, 1 exact GELU, 2 residual.  OUTH: 1 = fp16 output, 0 = fp32.
#define AHS 40                 // smem row stride in halfs (80B): conflict-free
#define NSTG 4
#define OPHS (128 * AHS)       // halfs per operand per stage
#define SMEMG (NSTG * 2 * OPHS * 2)   // bytes = 81920

template<int EPI, int OUTH>
__global__ void __launch_bounds__(256, 2)
gemmh(const __half* __restrict__ A, const __half* __restrict__ Bt,
      const float* __restrict__ bias, const float* __restrict__ res,
      void* __restrict__ Cv, int M, int N, int K) {
    extern __shared__ __half dsm[];
    __half* As = dsm;                 // [NSTG][128][AHS]
    __half* Bs = dsm + NSTG * OPHS;   // [NSTG][128][AHS]

    int tid = threadIdx.x, warp = tid >> 5, lane = tid & 31;
    int l8 = lane & 7;
    int gq = lane >> 2, t4 = lane & 3;
    int wm = warp & 3, wn = warp >> 2;
    int m0 = blockIdx.y * 128, n0 = blockIdx.x * 128;

    float acc[2][8][4] = {};
    int NC = K >> 5;

    uint32_t asb = (uint32_t)__cvta_generic_to_shared(As);
    uint32_t bsb = (uint32_t)__cvta_generic_to_shared(Bs);
    const uint32_t stgB = OPHS * 2;   // bytes per operand-stage

    // ldmatrix lane-address components
    int a_r  = l8 + ((lane >> 3) & 1) * 8;
    int a_c8 = (lane >> 4) * 8;
    int b_n  = (lane >> 4) * 8 + l8;
    int b_c8 = ((lane >> 3) & 1) * 8;

    // loader: chunk ch -> stage ch%NSTG; each thread covers 2 rows x 1 seg per operand
    #define LOAD_CHUNK(ch) do {                                                 \
        int _s = (ch) % NSTG; int _k0 = (ch) * 32;                              \
        __half* _as = As + _s * OPHS; __half* _bs = Bs + _s * OPHS;             \
        _Pragma("unroll")                                                       \
        for (int _q = 0; _q < 2; _q++) {                                        \
            int _fid = tid + _q * 256;                                          \
            int _row = _fid >> 2, _seg = _fid & 3;                              \
            cp16h(_as + _row * AHS + _seg*8, A  + (size_t)(m0 + _row) * K + _k0 + _seg*8); \
            cp16h(_bs + _row * AHS + _seg*8, Bt + (size_t)(n0 + _row) * K + _k0 + _seg*8); \
        }                                                                       \
    } while (0)

    // prologue: stages 0..NSTG-2
    #pragma unroll
    for (int c = 0; c < NSTG - 1; c++) {
        LOAD_CHUNK(c);
        asm volatile("cp.async.commit_group;");
    }

    for (int c = 0; c < NC; c++) {
        asm volatile("cp.async.wait_group %0;" :: "n"(NSTG - 2));
        __syncthreads();

        // issue loads for chunk c+NSTG-1 (writes stage (c-1)%NSTG, safe past sync)
        if (c + NSTG - 1 < NC) LOAD_CHUNK(c + NSTG - 1);
        asm volatile("cp.async.commit_group;");

        uint32_t asc = asb + (uint32_t)(c % NSTG) * stgB;
        uint32_t bsc = bsb + (uint32_t)(c % NSTG) * stgB;
        #pragma unroll
        for (int ks = 0; ks < 2; ks++) {
            int kk = ks * 16;
            unsigned a[2][4];
            #pragma unroll
            for (int mi = 0; mi < 2; mi++) {
                int row = wm * 32 + mi * 16 + a_r;
                ldsm_x4(a[mi], asc + (uint32_t)(row * AHS + kk + a_c8) * 2);
            }
            #pragma unroll
            for (int p = 0; p < 4; p++) {
                unsigned bfrag[4];
                int row = wn * 64 + p * 16 + b_n;
                ldsm_x4(bfrag, bsc + (uint32_t)(row * AHS + kk + b_c8) * 2);
                mma_h(acc[0][2*p],     a[0], bfrag[0], bfrag[1]);
                mma_h(acc[1][2*p],     a[1], bfrag[0], bfrag[1]);
                mma_h(acc[0][2*p + 1], a[0], bfrag[2], bfrag[3]);
                mma_h(acc[1][2*p + 1], a[1], bfrag[2], bfrag[3]);
            }
        }
    }
    #undef LOAD_CHUNK

    // epilogue
    #pragma unroll
    for (int mi = 0; mi < 2; mi++) {
        int row = m0 + wm * 32 + mi * 16 + gq;
        #pragma unroll
        for (int nj = 0; nj < 8; nj++) {
            int col = n0 + wn * 64 + nj * 8 + 2*t4;
            float b0 = bias[col], b1 = bias[col + 1];
            float v0 = acc[mi][nj][0] + b0;
            float v1 = acc[mi][nj][1] + b1;
            float v2 = acc[mi][nj][2] + b0;
            float v3 = acc[mi][nj][3] + b1;
            if (EPI == 1) {
                v0 = gelu_exact(v0); v1 = gelu_exact(v1);
                v2 = gelu_exact(v2); v3 = gelu_exact(v3);
            }
            if (EPI == 2) {
                v0 += res[(size_t)row * N + col];
                v1 += res[(size_t)row * N + col + 1];
                v2 += res[(size_t)(row + 8) * N + col];
                v3 += res[(size_t)(row + 8) * N + col + 1];
            }
            if (OUTH) {
                __half* C = (__half*)Cv;
                *(__half2*)(C + (size_t)row * N + col) = __floats2half2_rn(v0, v1);
                *(__half2*)(C + (size_t)(row + 8) * N + col) = __floats2half2_rn(v2, v3);
            } else {
                float* C = (float*)Cv;
                *(float2*)(C + (size_t)row * N + col)       = make_float2(v0, v1);
                *(float2*)(C + (size_t)(row + 8) * N + col) = make_float2(v2, v3);
            }
        }
    }
}

// ---------------- fp16 tensor-core flash attention (causal, ldmatrix) --------
// Br=128 (8 warps x 16 rows), Bc=64. QKV packed [token][3072] fp16.
#define FVS 72

__global__ void __launch_bounds__(256, 2)
flash_h(const __half* __restrict__ QKV, __half* __restrict__ O) {
    __shared__ __half Ks[64][FVS];
    __shared__ __half Vs[64][FVS];   // [kv][d]; transposed at use via ldmatrix.trans

    int tid = threadIdx.x, warp = tid >> 5, lane = tid & 31;
    int l8 = lane & 7;
    int gq = lane >> 2, t4 = lane & 3;
    int qt = gridDim.x - 1 - blockIdx.x;          // heavy tiles first
    int bh = blockIdx.y, b = bh >> 4, h = bh & 15;
    size_t rowbase = (size_t)b * SS * H3;
    int qoff = h * 64, koff = HH + h * 64, voff = 2 * HH + h * 64;
    int qbase = qt * 128 + warp * 16;

    uint32_t ksb = (uint32_t)__cvta_generic_to_shared(&Ks[0][0]);
    uint32_t vsb = (uint32_t)__cvta_generic_to_shared(&Vs[0][0]);

    int b_n  = (lane >> 4) * 8 + l8;
    int b_c8 = ((lane >> 3) & 1) * 8;
    int v_r  = ((lane >> 3) & 1) * 8 + l8;
    int v_d  = (lane >> 4) * 8;

    unsigned qf[4][4];
    #pragma unroll
    for (int kc = 0; kc < 4; kc++) {
        const __half* q0 = QKV + rowbase + (size_t)(qbase + gq)     * H3 + qoff + kc*16 + 2*t4;
        const __half* q1 = QKV + rowbase + (size_t)(qbase + gq + 8) * H3 + qoff + kc*16 + 2*t4;
        qf[kc][0] = *(const unsigned*)q0;
        qf[kc][1] = *(const unsigned*)q1;
        qf[kc][2] = *(const unsigned*)(q0 + 8);
        qf[kc][3] = *(const unsigned*)(q1 + 8);
    }

    float oacc[8][4] = {};
    float m0 = -1e30f, m1 = -1e30f, l0 = 0.0f, l1 = 0.0f;
    int row0 = qbase + gq, row1 = qbase + gq + 8;

    int jmax = 2 * qt + 1;
    for (int j = 0; j <= jmax; j++) {
        #pragma unroll
        for (int it = 0; it < 2; it++) {
            int fid = tid + it * 256;
            int r = fid >> 3, sg = fid & 7;
            *(uint4*)&Ks[r][sg*8] =
                *(const uint4*)(QKV + rowbase + (size_t)(j*64 + r) * H3 + koff + sg*8);
            *(uint4*)&Vs[r][sg*8] =
                *(const uint4*)(QKV + rowbase + (size_t)(j*64 + r) * H3 + voff + sg*8);
        }
        __syncthreads();

        if (j * 64 <= qbase + 15) {
            float s[8][4] = {};
            #pragma unroll
            for (int kc = 0; kc < 4; kc++) {
                #pragma unroll
                for (int p = 0; p < 4; p++) {
                    unsigned kb[4];
                    int row = p * 16 + b_n;
                    ldsm_x4(kb, ksb + (uint32_t)(row * FVS + kc*16 + b_c8) * 2);
                    mma_h(s[2*p],     qf[kc], kb[0], kb[1]);
                    mma_h(s[2*p + 1], qf[kc], kb[2], kb[3]);
                }
            }

            float mt0 = -1e30f, mt1 = -1e30f;
            #pragma unroll
            for (int nj = 0; nj < 8; nj++) {
                int c0 = j*64 + nj*8 + 2*t4, c1 = c0 + 1;
                float v0 = s[nj][0] * 0.125f, v1 = s[nj][1] * 0.125f;
                float v2 = s[nj][2] * 0.125f, v3 = s[nj][3] * 0.125f;
                if (c0 > row0) v0 = -1e30f;
                if (c1 > row0) v1 = -1e30f;
                if (c0 > row1) v2 = -1e30f;
                if (c1 > row1) v3 = -1e30f;
                s[nj][0] = v0; s[nj][1] = v1; s[nj][2] = v2; s[nj][3] = v3;
                mt0 = fmaxf(mt0, fmaxf(v0, v1));
                mt1 = fmaxf(mt1, fmaxf(v2, v3));
            }
            mt0 = fmaxf(mt0, __shfl_xor_sync(0xffffffffu, mt0, 1));
            mt0 = fmaxf(mt0, __shfl_xor_sync(0xffffffffu, mt0, 2));
            mt1 = fmaxf(mt1, __shfl_xor_sync(0xffffffffu, mt1, 1));
            mt1 = fmaxf(mt1, __shfl_xor_sync(0xffffffffu, mt1, 2));

            float nm0 = fmaxf(m0, mt0), nm1 = fmaxf(m1, mt1);
            float co0 = __expf(m0 - nm0), co1 = __expf(m1 - nm1);
            m0 = nm0; m1 = nm1;

            float rs0 = 0.0f, rs1 = 0.0f;
            #pragma unroll
            for (int nj = 0; nj < 8; nj++) {
                float p0 = __half2float(__float2half_rn(__expf(s[nj][0] - nm0)));
                float p1 = __half2float(__float2half_rn(__expf(s[nj][1] - nm0)));
                float p2 = __half2float(__float2half_rn(__expf(s[nj][2] - nm1)));
                float p3 = __half2float(__float2half_rn(__expf(s[nj][3] - nm1)));
                s[nj][0] = p0; s[nj][1] = p1; s[nj][2] = p2; s[nj][3] = p3;
                rs0 += p0 + p1; rs1 += p2 + p3;
            }
            rs0 += __shfl_xor_sync(0xffffffffu, rs0, 1);
            rs0 += __shfl_xor_sync(0xffffffffu, rs0, 2);
            rs1 += __shfl_xor_sync(0xffffffffu, rs1, 1);
            rs1 += __shfl_xor_sync(0xffffffffu, rs1, 2);
            l0 = l0 * co0 + rs0;
            l1 = l1 * co1 + rs1;

            #pragma unroll
            for (int nd = 0; nd < 8; nd++) {
                oacc[nd][0] *= co0; oacc[nd][1] *= co0;
                oacc[nd][2] *= co1; oacc[nd][3] *= co1;
            }

            #pragma unroll
            for (int kc = 0; kc < 4; kc++) {
                unsigned pa[4];
                pa[0] = packh2(s[2*kc][0],     s[2*kc][1]);
                pa[1] = packh2(s[2*kc][2],     s[2*kc][3]);
                pa[2] = packh2(s[2*kc + 1][0], s[2*kc + 1][1]);
                pa[3] = packh2(s[2*kc + 1][2], s[2*kc + 1][3]);
                #pragma unroll
                for (int p = 0; p < 4; p++) {
                    unsigned vb[4];
                    int row = kc * 16 + v_r;
                    ldsm_x4t(vb, vsb + (uint32_t)(row * FVS + p * 16 + v_d) * 2);
                    mma_h(oacc[2*p],     pa, vb[0], vb[1]);
                    mma_h(oacc[2*p + 1], pa, vb[2], vb[3]);
                }
            }
        }
        __syncthreads();
    }

    float inv0 = 1.0f / l0, inv1 = 1.0f / l1;
    size_t obase = (size_t)(b * SS) * HH + h * 64;
    #pragma unroll
    for (int nd = 0; nd < 8; nd++) {
        *(__half2*)(O + obase + (size_t)row0 * HH + nd*8 + 2*t4) =
            __floats2half2_rn(oacc[nd][0] * inv0, oacc[nd][1] * inv0);
        *(__half2*)(O + obase + (size_t)row1 * HH + nd*8 + 2*t4) =
            __floats2half2_rn(oacc[nd][2] * inv1, oacc[nd][3] * inv1);
    }
}

// ---------------- launch ----------------------------------------------------
extern "C" void kernel_launch(void* const* d_in, const int* in_sizes, int n_in,
                              void* d_out, int out_size) {
    const float* x   = (const float*)d_in[0];
    const float* Wq  = (const float*)d_in[1];
    const float* bq  = (const float*)d_in[2];
    const float* Wk  = (const float*)d_in[3];
    const float* bk  = (const float*)d_in[4];
    const float* Wv  = (const float*)d_in[5];
    const float* bv  = (const float*)d_in[6];
    const float* Wo  = (const float*)d_in[7];
    const float* bo  = (const float*)d_in[8];
    const float* W1  = (const float*)d_in[9];
    const float* b1  = (const float*)d_in[10];
    const float* W2  = (const float*)d_in[11];
    const float* b2  = (const float*)d_in[12];
    const float* g1  = (const float*)d_in[13];
    const float* be1 = (const float*)d_in[14];
    const float* g2  = (const float*)d_in[15];
    const float* be2 = (const float*)d_in[16];
    float* out = (float*)d_out;

    __half *p_ln1h, *p_qkvh, *p_attnh, *p_ln2h, *p_midh;
    __half *p_wqkvh, *p_woh, *p_w1h, *p_w2h;
    float *p_xatt, *p_bqkv;
    cudaGetSymbolAddress((void**)&p_ln1h,  g_ln1h);
    cudaGetSymbolAddress((void**)&p_qkvh,  g_qkvh);
    cudaGetSymbolAddress((void**)&p_attnh, g_attnh);
    cudaGetSymbolAddress((void**)&p_xatt,  g_xatt);
    cudaGetSymbolAddress((void**)&p_ln2h,  g_ln2h);
    cudaGetSymbolAddress((void**)&p_midh,  g_midh);
    cudaGetSymbolAddress((void**)&p_wqkvh, g_wqkvh);
    cudaGetSymbolAddress((void**)&p_woh,   g_woh);
    cudaGetSymbolAddress((void**)&p_w1h,   g_w1h);
    cudaGetSymbolAddress((void**)&p_w2h,   g_w2h);
    cudaGetSymbolAddress((void**)&p_bqkv,  g_bqkv);

    // allow 80KB dynamic smem for gemmh instantiations (host-side, idempotent)
    cudaFuncSetAttribute(gemmh<0,1>, cudaFuncAttributeMaxDynamicSharedMemorySize, SMEMG);
    cudaFuncSetAttribute(gemmh<1,1>, cudaFuncAttributeMaxDynamicSharedMemorySize, SMEMG);
    cudaFuncSetAttribute(gemmh<2,0>, cudaFuncAttributeMaxDynamicSharedMemorySize, SMEMG);

    // 0) weight prep: one batched transpose launch + bias concat
    prep_weights<<<12288, dim3(32, 8)>>>(Wq, Wk, Wv, Wo, W1, W2,
                                         p_wqkvh, p_woh, p_w1h, p_w2h);
    concat_bias<<<(H3 + 255) / 256, 256>>>(bq, bk, bv, p_bqkv);

    // 1) LN1 -> fp16
    ln_kernel<<<MM, 256>>>(x, g1, be1, p_ln1h);

    // 2) fused QKV projection (fp16 tensor cores)
    gemmh<0,1><<<dim3(H3/128, MM/128), 256, SMEMG>>>(p_ln1h, p_wqkvh, p_bqkv, nullptr,
                                                     p_qkvh, MM, H3, HH);

    // 3) fp16 causal flash attention
    flash_h<<<dim3(SS/128, BB*NHH), 256>>>(p_qkvh, p_attnh);

    // 4) O projection + residual (fp32 out)
    gemmh<2,0><<<dim3(HH/128, MM/128), 256, SMEMG>>>(p_attnh, p_woh, bo, x,
                                                     p_xatt, MM, HH, HH);

    // 5) LN2 -> fp16
    ln_kernel<<<MM, 256>>>(p_xatt, g2, be2, p_ln2h);

    // 6) FFN up + exact GELU (fp16 out)
    gemmh<1,1><<<dim3(FFF/128, MM/128), 256, SMEMG>>>(p_ln2h, p_w1h, b1, nullptr,
                                                      p_midh, MM, FFF, HH);

    // 7) FFN down + residual (fp32 out)
    gemmh<2,0><<<dim3(HH/128, MM/128), 256, SMEMG>>>(p_midh, p_w2h, b2, p_xatt,
                                                     out, MM, HH, FFF);
}

// round 8
// speedup vs baseline: 6.0910x; 1.0152x over previous
#include <cuda_runtime.h>
#include <cuda_fp16.h>
#include <math.h>
#include <stdint.h>

// Problem dims (fixed)
#define BB 2
#define SS 2048
#define HH 1024
#define NHH 16
#define DHH 64
#define FFF 4096
#define MM (BB*SS)   // 4096 tokens
#define H3 (3*HH)    // 3072

// ---------------- scratch (device globals; no allocation allowed) ----------
__device__ __half g_ln1h [MM*HH];
__device__ __half g_qkvh [MM*H3];
__device__ __half g_attnh[MM*HH];
__device__ float  g_xatt [MM*HH];
__device__ __half g_ln2h [MM*HH];
__device__ __half g_midh [MM*FFF];
// transposed fp16 weights, stored [N][K] (K-major)
__device__ __half g_wqkvh[H3*HH];
__device__ __half g_woh  [HH*HH];
__device__ __half g_w1h  [FFF*HH];
__device__ __half g_w2h  [HH*FFF];
__device__ float  g_bqkv [H3];

// ---------------- helpers ----------------------------------------------------
__device__ __forceinline__ float gelu_exact(float v) {
    return 0.5f * v * (1.0f + erff(v * 0.70710678118654752f));
}

__device__ __forceinline__ void mma_h(float* d, const unsigned* a,
                                      unsigned b0, unsigned b1) {
    asm volatile(
        "mma.sync.aligned.m16n8k16.row.col.f32.f16.f16.f32 "
        "{%0,%1,%2,%3}, {%4,%5,%6,%7}, {%8,%9}, {%0,%1,%2,%3};\n"
        : "+f"(d[0]), "+f"(d[1]), "+f"(d[2]), "+f"(d[3])
        : "r"(a[0]), "r"(a[1]), "r"(a[2]), "r"(a[3]), "r"(b0), "r"(b1));
}

__device__ __forceinline__ void ldsm_x4(unsigned* r, uint32_t a) {
    asm volatile("ldmatrix.sync.aligned.m8n8.x4.shared.b16 {%0,%1,%2,%3}, [%4];"
        : "=r"(r[0]), "=r"(r[1]), "=r"(r[2]), "=r"(r[3]) : "r"(a));
}
__device__ __forceinline__ void ldsm_x4t(unsigned* r, uint32_t a) {
    asm volatile("ldmatrix.sync.aligned.m8n8.x4.trans.shared.b16 {%0,%1,%2,%3}, [%4];"
        : "=r"(r[0]), "=r"(r[1]), "=r"(r[2]), "=r"(r[3]) : "r"(a));
}

__device__ __forceinline__ void cp16h(__half* dst, const __half* src) {
    unsigned s = (unsigned)__cvta_generic_to_shared(dst);
    asm volatile("cp.async.cg.shared.global [%0], [%1], 16;\n" :: "r"(s), "l"(src));
}

__device__ __forceinline__ unsigned packh2(float a, float b) {
    __half2 h = __floats2half2_rn(a, b);
    return *(unsigned*)&h;
}

// ---------------- one-shot weight + bias prep (single launch) ----------------
__global__ void prep_weights(const float* __restrict__ Wq, const float* __restrict__ Wk,
                             const float* __restrict__ Wv, const float* __restrict__ Wo,
                             const float* __restrict__ W1, const float* __restrict__ W2,
                             const float* __restrict__ bq, const float* __restrict__ bk,
                             const float* __restrict__ bv,
                             __half* __restrict__ wqkv, __half* __restrict__ wo,
                             __half* __restrict__ w1,   __half* __restrict__ w2,
                             float* __restrict__ bqkv) {
    int bid = blockIdx.x;
    if (bid >= 12288) {   // bias concat blocks
        int i = (bid - 12288) * 256 + threadIdx.y * 32 + threadIdx.x;
        if (i < H3) {
            const float* src = (i < HH) ? bq : (i < 2*HH) ? bk : bv;
            bqkv[i] = src[i & (HH - 1)];
        }
        return;
    }
    __shared__ float t[32][33];
    const float* src; __half* dst; int K, N, b0i;
    if      (bid < 1024) { src = Wq; dst = wqkv;           K = HH;  N = HH;  b0i = 0;    }
    else if (bid < 2048) { src = Wk; dst = wqkv + HH*HH;   K = HH;  N = HH;  b0i = 1024; }
    else if (bid < 3072) { src = Wv; dst = wqkv + 2*HH*HH; K = HH;  N = HH;  b0i = 2048; }
    else if (bid < 4096) { src = Wo; dst = wo;             K = HH;  N = HH;  b0i = 3072; }
    else if (bid < 8192) { src = W1; dst = w1;             K = HH;  N = FFF; b0i = 4096; }
    else                 { src = W2; dst = w2;             K = FFF; N = HH;  b0i = 8192; }
    int lb = bid - b0i;
    int gx = N / 32;
    int n0 = (lb % gx) * 32, k0 = (lb / gx) * 32;
    int x = threadIdx.x, y = threadIdx.y;     // 32 x 8
    #pragma unroll
    for (int i = 0; i < 32; i += 8)
        t[y + i][x] = src[(size_t)(k0 + y + i) * N + n0 + x];
    __syncthreads();
    #pragma unroll
    for (int i = 0; i < 32; i += 8)
        dst[(size_t)(n0 + y + i) * K + k0 + x] = __float2half_rn(t[x][y + i]);
}

// ---------------- layernorm (fp16 output) ------------------------------------
__device__ __forceinline__ float block_reduce_sum(float v) {
    __shared__ float sh[8];
    int lane = threadIdx.x & 31, w = threadIdx.x >> 5;
    #pragma unroll
    for (int o = 16; o > 0; o >>= 1) v += __shfl_xor_sync(0xffffffffu, v, o);
    if (lane == 0) sh[w] = v;
    __syncthreads();
    float t = (threadIdx.x < 8) ? sh[threadIdx.x] : 0.0f;
    if (w == 0) {
        #pragma unroll
        for (int o = 4; o > 0; o >>= 1) t += __shfl_xor_sync(0xffffffffu, t, o);
        if (lane == 0) sh[0] = t;
    }
    __syncthreads();
    float r = sh[0];
    __syncthreads();
    return r;
}

__global__ void ln_kernel(const float* __restrict__ x,
                          const float* __restrict__ g,
                          const float* __restrict__ be,
                          __half* __restrict__ out) {
    int row = blockIdx.x;
    int t = threadIdx.x;
    const float4* xr = (const float4*)(x + (size_t)row * HH);
    float4 v = xr[t];
    float s = v.x + v.y + v.z + v.w;
    float mu = block_reduce_sum(s) * (1.0f / HH);
    float dx = v.x - mu, dy = v.y - mu, dz = v.z - mu, dw = v.w - mu;
    float ss = dx*dx + dy*dy + dz*dz + dw*dw;
    float var = block_reduce_sum(ss) * (1.0f / HH);
    float rstd = rsqrtf(var + 1e-5f);
    float4 gg = ((const float4*)g)[t];
    float4 bb = ((const float4*)be)[t];
    __half2* orow = (__half2*)(out + (size_t)row * HH);
    orow[t*2]     = __floats2half2_rn(dx * rstd * gg.x + bb.x, dy * rstd * gg.y + bb.y);
    orow[t*2 + 1] = __floats2half2_rn(dz * rstd * gg.z + bb.z, dw * rstd * gg.w + bb.w);
}

// ---------------- fp16 tensor-core GEMM (4-stage, burst fragments) -----------
// C[M,N] = A[M,K] @ Bt[N,K]^T + bias (+epilogue).
// EPI: 0 none, 1 exact GELU, 2 residual.  OUTH: 1 = fp16 output, 0 = fp32.
#define AHS 40                 // smem row stride in halfs (80B): conflict-free
#define NSTG 4
#define OPHS (128 * AHS)       // halfs per operand per stage
#define SMEMG (NSTG * 2 * OPHS * 2)   // bytes = 81920

template<int EPI, int OUTH>
__global__ void __launch_bounds__(256, 2)
gemmh(const __half* __restrict__ A, const __half* __restrict__ Bt,
      const float* __restrict__ bias, const float* __restrict__ res,
      void* __restrict__ Cv, int M, int N, int K) {
    extern __shared__ __half dsm[];
    __half* As = dsm;                 // [NSTG][128][AHS]
    __half* Bs = dsm + NSTG * OPHS;   // [NSTG][128][AHS]

    int tid = threadIdx.x, warp = tid >> 5, lane = tid & 31;
    int l8 = lane & 7;
    int gq = lane >> 2, t4 = lane & 3;
    int wm = warp & 3, wn = warp >> 2;
    int m0 = blockIdx.y * 128, n0 = blockIdx.x * 128;

    float acc[2][8][4] = {};
    int NC = K >> 5;

    uint32_t asb = (uint32_t)__cvta_generic_to_shared(As);
    uint32_t bsb = (uint32_t)__cvta_generic_to_shared(Bs);
    const uint32_t stgB = OPHS * 2;   // bytes per operand-stage

    // ldmatrix lane-address components
    int a_r  = l8 + ((lane >> 3) & 1) * 8;
    int a_c8 = (lane >> 4) * 8;
    int b_n  = (lane >> 4) * 8 + l8;
    int b_c8 = ((lane >> 3) & 1) * 8;

    #define LOAD_CHUNK(ch) do {                                                 \
        int _s = (ch) % NSTG; int _k0 = (ch) * 32;                              \
        __half* _as = As + _s * OPHS; __half* _bs = Bs + _s * OPHS;             \
        _Pragma("unroll")                                                       \
        for (int _q = 0; _q < 2; _q++) {                                        \
            int _fid = tid + _q * 256;                                          \
            int _row = _fid >> 2, _seg = _fid & 3;                              \
            cp16h(_as + _row * AHS + _seg*8, A  + (size_t)(m0 + _row) * K + _k0 + _seg*8); \
            cp16h(_bs + _row * AHS + _seg*8, Bt + (size_t)(n0 + _row) * K + _k0 + _seg*8); \
        }                                                                       \
    } while (0)

    // prologue: stages 0..NSTG-2
    #pragma unroll
    for (int c = 0; c < NSTG - 1; c++) {
        LOAD_CHUNK(c);
        asm volatile("cp.async.commit_group;");
    }

    for (int c = 0; c < NC; c++) {
        asm volatile("cp.async.wait_group %0;" :: "n"(NSTG - 2));
        __syncthreads();

        if (c + NSTG - 1 < NC) LOAD_CHUNK(c + NSTG - 1);
        asm volatile("cp.async.commit_group;");

        uint32_t asc = asb + (uint32_t)(c % NSTG) * stgB;
        uint32_t bsc = bsb + (uint32_t)(c % NSTG) * stgB;
        #pragma unroll
        for (int ks = 0; ks < 2; ks++) {
            int kk = ks * 16;
            // burst ALL fragment loads for this k-step first ...
            unsigned a[2][4], bf[4][4];
            #pragma unroll
            for (int mi = 0; mi < 2; mi++) {
                int row = wm * 32 + mi * 16 + a_r;
                ldsm_x4(a[mi], asc + (uint32_t)(row * AHS + kk + a_c8) * 2);
            }
            #pragma unroll
            for (int p = 0; p < 4; p++) {
                int row = wn * 64 + p * 16 + b_n;
                ldsm_x4(bf[p], bsc + (uint32_t)(row * AHS + kk + b_c8) * 2);
            }
            // ... then run 32 MMAs back-to-back
            #pragma unroll
            for (int p = 0; p < 4; p++) {
                mma_h(acc[0][2*p],     a[0], bf[p][0], bf[p][1]);
                mma_h(acc[1][2*p],     a[1], bf[p][0], bf[p][1]);
                mma_h(acc[0][2*p + 1], a[0], bf[p][2], bf[p][3]);
                mma_h(acc[1][2*p + 1], a[1], bf[p][2], bf[p][3]);
            }
        }
    }
    #undef LOAD_CHUNK

    // epilogue
    #pragma unroll
    for (int mi = 0; mi < 2; mi++) {
        int row = m0 + wm * 32 + mi * 16 + gq;
        #pragma unroll
        for (int nj = 0; nj < 8; nj++) {
            int col = n0 + wn * 64 + nj * 8 + 2*t4;
            float b0 = bias[col], b1 = bias[col + 1];
            float v0 = acc[mi][nj][0] + b0;
            float v1 = acc[mi][nj][1] + b1;
            float v2 = acc[mi][nj][2] + b0;
            float v3 = acc[mi][nj][3] + b1;
            if (EPI == 1) {
                v0 = gelu_exact(v0); v1 = gelu_exact(v1);
                v2 = gelu_exact(v2); v3 = gelu_exact(v3);
            }
            if (EPI == 2) {
                v0 += res[(size_t)row * N + col];
                v1 += res[(size_t)row * N + col + 1];
                v2 += res[(size_t)(row + 8) * N + col];
                v3 += res[(size_t)(row + 8) * N + col + 1];
            }
            if (OUTH) {
                __half* C = (__half*)Cv;
                *(__half2*)(C + (size_t)row * N + col) = __floats2half2_rn(v0, v1);
                *(__half2*)(C + (size_t)(row + 8) * N + col) = __floats2half2_rn(v2, v3);
            } else {
                float* C = (float*)Cv;
                *(float2*)(C + (size_t)row * N + col)       = make_float2(v0, v1);
                *(float2*)(C + (size_t)(row + 8) * N + col) = make_float2(v2, v3);
            }
        }
    }
}

// ---------------- fp16 flash attention (causal, double-buffered) -------------
// Br=128 (8 warps x 16 rows), Bc=64. QKV packed [token][3072] fp16.
#define FVS 72

__global__ void __launch_bounds__(256, 2)
flash_h(const __half* __restrict__ QKV, __half* __restrict__ O) {
    __shared__ __half Ks[2][64][FVS];
    __shared__ __half Vs[2][64][FVS];

    int tid = threadIdx.x, warp = tid >> 5, lane = tid & 31;
    int l8 = lane & 7;
    int gq = lane >> 2, t4 = lane & 3;
    int qt = gridDim.x - 1 - blockIdx.x;          // heavy tiles first
    int bh = blockIdx.y, b = bh >> 4, h = bh & 15;
    size_t rowbase = (size_t)b * SS * H3;
    int qoff = h * 64, koff = HH + h * 64, voff = 2 * HH + h * 64;
    int qbase = qt * 128 + warp * 16;

    uint32_t ksb = (uint32_t)__cvta_generic_to_shared(&Ks[0][0][0]);
    uint32_t vsb = (uint32_t)__cvta_generic_to_shared(&Vs[0][0][0]);
    const uint32_t fstgB = 64 * FVS * 2;

    int b_n  = (lane >> 4) * 8 + l8;
    int b_c8 = ((lane >> 3) & 1) * 8;
    int v_r  = ((lane >> 3) & 1) * 8 + l8;
    int v_d  = (lane >> 4) * 8;

    // KV tile loader: cp.async, 2 iters x 2 ops per thread
    #define FLOAD(j) do {                                                        \
        int _s = (j) & 1;                                                        \
        _Pragma("unroll")                                                        \
        for (int _it = 0; _it < 2; _it++) {                                      \
            int _fid = tid + _it * 256;                                          \
            int _r = _fid >> 3, _sg = _fid & 7;                                  \
            cp16h(&Ks[_s][_r][_sg*8],                                            \
                  QKV + rowbase + (size_t)((j)*64 + _r) * H3 + koff + _sg*8);    \
            cp16h(&Vs[_s][_r][_sg*8],                                            \
                  QKV + rowbase + (size_t)((j)*64 + _r) * H3 + voff + _sg*8);    \
        }                                                                        \
    } while (0)

    unsigned qf[4][4];
    #pragma unroll
    for (int kc = 0; kc < 4; kc++) {
        const __half* q0 = QKV + rowbase + (size_t)(qbase + gq)     * H3 + qoff + kc*16 + 2*t4;
        const __half* q1 = QKV + rowbase + (size_t)(qbase + gq + 8) * H3 + qoff + kc*16 + 2*t4;
        qf[kc][0] = *(const unsigned*)q0;
        qf[kc][1] = *(const unsigned*)q1;
        qf[kc][2] = *(const unsigned*)(q0 + 8);
        qf[kc][3] = *(const unsigned*)(q1 + 8);
    }

    float oacc[8][4] = {};
    float m0 = -1e30f, m1 = -1e30f, l0 = 0.0f, l1 = 0.0f;
    int row0 = qbase + gq, row1 = qbase + gq + 8;

    int jmax = 2 * qt + 1;
    // prologue: load j=0
    FLOAD(0);
    asm volatile("cp.async.commit_group;");

    for (int j = 0; j <= jmax; j++) {
        asm volatile("cp.async.wait_group 0;");
        __syncthreads();                     // j's tiles visible; buf (j+1)&1 free

        if (j < jmax) FLOAD(j + 1);          // overlap next loads with compute
        asm volatile("cp.async.commit_group;");

        if (j * 64 <= qbase + 15) {
            uint32_t ksj = ksb + (uint32_t)(j & 1) * fstgB;
            uint32_t vsj = vsb + (uint32_t)(j & 1) * fstgB;

            float s[8][4] = {};
            #pragma unroll
            for (int kc = 0; kc < 4; kc++) {
                #pragma unroll
                for (int p = 0; p < 4; p++) {
                    unsigned kb[4];
                    int row = p * 16 + b_n;
                    ldsm_x4(kb, ksj + (uint32_t)(row * FVS + kc*16 + b_c8) * 2);
                    mma_h(s[2*p],     qf[kc], kb[0], kb[1]);
                    mma_h(s[2*p + 1], qf[kc], kb[2], kb[3]);
                }
            }

            float mt0 = -1e30f, mt1 = -1e30f;
            #pragma unroll
            for (int nj = 0; nj < 8; nj++) {
                int c0 = j*64 + nj*8 + 2*t4, c1 = c0 + 1;
                float v0 = s[nj][0] * 0.125f, v1 = s[nj][1] * 0.125f;
                float v2 = s[nj][2] * 0.125f, v3 = s[nj][3] * 0.125f;
                if (c0 > row0) v0 = -1e30f;
                if (c1 > row0) v1 = -1e30f;
                if (c0 > row1) v2 = -1e30f;
                if (c1 > row1) v3 = -1e30f;
                s[nj][0] = v0; s[nj][1] = v1; s[nj][2] = v2; s[nj][3] = v3;
                mt0 = fmaxf(mt0, fmaxf(v0, v1));
                mt1 = fmaxf(mt1, fmaxf(v2, v3));
            }
            mt0 = fmaxf(mt0, __shfl_xor_sync(0xffffffffu, mt0, 1));
            mt0 = fmaxf(mt0, __shfl_xor_sync(0xffffffffu, mt0, 2));
            mt1 = fmaxf(mt1, __shfl_xor_sync(0xffffffffu, mt1, 1));
            mt1 = fmaxf(mt1, __shfl_xor_sync(0xffffffffu, mt1, 2));

            float nm0 = fmaxf(m0, mt0), nm1 = fmaxf(m1, mt1);
            float co0 = __expf(m0 - nm0), co1 = __expf(m1 - nm1);
            m0 = nm0; m1 = nm1;

            float rs0 = 0.0f, rs1 = 0.0f;
            #pragma unroll
            for (int nj = 0; nj < 8; nj++) {
                float p0 = __half2float(__float2half_rn(__expf(s[nj][0] - nm0)));
                float p1 = __half2float(__float2half_rn(__expf(s[nj][1] - nm0)));
                float p2 = __half2float(__float2half_rn(__expf(s[nj][2] - nm1)));
                float p3 = __half2float(__float2half_rn(__expf(s[nj][3] - nm1)));
                s[nj][0] = p0; s[nj][1] = p1; s[nj][2] = p2; s[nj][3] = p3;
                rs0 += p0 + p1; rs1 += p2 + p3;
            }
            rs0 += __shfl_xor_sync(0xffffffffu, rs0, 1);
            rs0 += __shfl_xor_sync(0xffffffffu, rs0, 2);
            rs1 += __shfl_xor_sync(0xffffffffu, rs1, 1);
            rs1 += __shfl_xor_sync(0xffffffffu, rs1, 2);
            l0 = l0 * co0 + rs0;
            l1 = l1 * co1 + rs1;

            #pragma unroll
            for (int nd = 0; nd < 8; nd++) {
                oacc[nd][0] *= co0; oacc[nd][1] *= co0;
                oacc[nd][2] *= co1; oacc[nd][3] *= co1;
            }

            #pragma unroll
            for (int kc = 0; kc < 4; kc++) {
                unsigned pa[4];
                pa[0] = packh2(s[2*kc][0],     s[2*kc][1]);
                pa[1] = packh2(s[2*kc][2],     s[2*kc][3]);
                pa[2] = packh2(s[2*kc + 1][0], s[2*kc + 1][1]);
                pa[3] = packh2(s[2*kc + 1][2], s[2*kc + 1][3]);
                #pragma unroll
                for (int p = 0; p < 4; p++) {
                    unsigned vb[4];
                    int row = kc * 16 + v_r;
                    ldsm_x4t(vb, vsj + (uint32_t)(row * FVS + p * 16 + v_d) * 2);
                    mma_h(oacc[2*p],     pa, vb[0], vb[1]);
                    mma_h(oacc[2*p + 1], pa, vb[2], vb[3]);
                }
            }
        }
    }
    #undef FLOAD

    float inv0 = 1.0f / l0, inv1 = 1.0f / l1;
    size_t obase = (size_t)(b * SS) * HH + h * 64;
    #pragma unroll
    for (int nd = 0; nd < 8; nd++) {
        *(__half2*)(O + obase + (size_t)row0 * HH + nd*8 + 2*t4) =
            __floats2half2_rn(oacc[nd][0] * inv0, oacc[nd][1] * inv0);
        *(__half2*)(O + obase + (size_t)row1 * HH + nd*8 + 2*t4) =
            __floats2half2_rn(oacc[nd][2] * inv1, oacc[nd][3] * inv1);
    }
}

// ---------------- launch ----------------------------------------------------
extern "C" void kernel_launch(void* const* d_in, const int* in_sizes, int n_in,
                              void* d_out, int out_size) {
    const float* x   = (const float*)d_in[0];
    const float* Wq  = (const float*)d_in[1];
    const float* bq  = (const float*)d_in[2];
    const float* Wk  = (const float*)d_in[3];
    const float* bk  = (const float*)d_in[4];
    const float* Wv  = (const float*)d_in[5];
    const float* bv  = (const float*)d_in[6];
    const float* Wo  = (const float*)d_in[7];
    const float* bo  = (const float*)d_in[8];
    const float* W1  = (const float*)d_in[9];
    const float* b1  = (const float*)d_in[10];
    const float* W2  = (const float*)d_in[11];
    const float* b2  = (const float*)d_in[12];
    const float* g1  = (const float*)d_in[13];
    const float* be1 = (const float*)d_in[14];
    const float* g2  = (const float*)d_in[15];
    const float* be2 = (const float*)d_in[16];
    float* out = (float*)d_out;

    __half *p_ln1h, *p_qkvh, *p_attnh, *p_ln2h, *p_midh;
    __half *p_wqkvh, *p_woh, *p_w1h, *p_w2h;
    float *p_xatt, *p_bqkv;
    cudaGetSymbolAddress((void**)&p_ln1h,  g_ln1h);
    cudaGetSymbolAddress((void**)&p_qkvh,  g_qkvh);
    cudaGetSymbolAddress((void**)&p_attnh, g_attnh);
    cudaGetSymbolAddress((void**)&p_xatt,  g_xatt);
    cudaGetSymbolAddress((void**)&p_ln2h,  g_ln2h);
    cudaGetSymbolAddress((void**)&p_midh,  g_midh);
    cudaGetSymbolAddress((void**)&p_wqkvh, g_wqkvh);
    cudaGetSymbolAddress((void**)&p_woh,   g_woh);
    cudaGetSymbolAddress((void**)&p_w1h,   g_w1h);
    cudaGetSymbolAddress((void**)&p_w2h,   g_w2h);
    cudaGetSymbolAddress((void**)&p_bqkv,  g_bqkv);

    // allow 80KB dynamic smem for gemmh instantiations (host-side, idempotent)
    cudaFuncSetAttribute(gemmh<0,1>, cudaFuncAttributeMaxDynamicSharedMemorySize, SMEMG);
    cudaFuncSetAttribute(gemmh<1,1>, cudaFuncAttributeMaxDynamicSharedMemorySize, SMEMG);
    cudaFuncSetAttribute(gemmh<2,0>, cudaFuncAttributeMaxDynamicSharedMemorySize, SMEMG);

    // 0) weight + bias prep in one launch (12288 transpose blocks + 12 bias)
    prep_weights<<<12300, dim3(32, 8)>>>(Wq, Wk, Wv, Wo, W1, W2, bq, bk, bv,
                                         p_wqkvh, p_woh, p_w1h, p_w2h, p_bqkv);

    // 1) LN1 -> fp16
    ln_kernel<<<MM, 256>>>(x, g1, be1, p_ln1h);

    // 2) fused QKV projection (fp16 tensor cores)
    gemmh<0,1><<<dim3(H3/128, MM/128), 256, SMEMG>>>(p_ln1h, p_wqkvh, p_bqkv, nullptr,
                                                     p_qkvh, MM, H3, HH);

    // 3) fp16 causal flash attention (double-buffered)
    flash_h<<<dim3(SS/128, BB*NHH), 256>>>(p_qkvh, p_attnh);

    // 4) O projection + residual (fp32 out)
    gemmh<2,0><<<dim3(HH/128, MM/128), 256, SMEMG>>>(p_attnh, p_woh, bo, x,
                                                     p_xatt, MM, HH, HH);

    // 5) LN2 -> fp16
    ln_kernel<<<MM, 256>>>(p_xatt, g2, be2, p_ln2h);

    // 6) FFN up + exact GELU (fp16 out)
    gemmh<1,1><<<dim3(FFF/128, MM/128), 256, SMEMG>>>(p_ln2h, p_w1h, b1, nullptr,
                                                      p_midh, MM, FFF, HH);

    // 7) FFN down + residual (fp32 out)
    gemmh<2,0><<<dim3(HH/128, MM/128), 256, SMEMG>>>(p_midh, p_w2h, b2, p_xatt,
                                                     out, MM, HH, FFF);
}

// round 9
// speedup vs baseline: 6.3308x; 1.0394x over previous
#include <cuda_runtime.h>
#include <cuda_fp16.h>
#include <math.h>
#include <stdint.h>

// Problem dims (fixed)
#define BB 2
#define SS 2048
#define HH 1024
#define NHH 16
#define DHH 64
#define FFF 4096
#define MM (BB*SS)   // 4096 tokens
#define H3 (3*HH)    // 3072

// ---------------- scratch (device globals; no allocation allowed) ----------
__device__ __half g_ln1h [MM*HH];
__device__ __half g_qkvh [MM*H3];
__device__ __half g_attnh[MM*HH];
__device__ float  g_xatt [MM*HH];
__device__ __half g_ln2h [MM*HH];
__device__ __half g_midh [MM*FFF];
// transposed fp16 weights, stored [N][K] (K-major)
__device__ __half g_wqkvh[H3*HH];
__device__ __half g_woh  [HH*HH];
__device__ __half g_w1h  [FFF*HH];
__device__ __half g_w2h  [HH*FFF];
__device__ float  g_bqkv [H3];

// ---------------- helpers ----------------------------------------------------
__device__ __forceinline__ float gelu_exact(float v) {
    return 0.5f * v * (1.0f + erff(v * 0.70710678118654752f));
}

__device__ __forceinline__ void mma_h(float* d, const unsigned* a,
                                      unsigned b0, unsigned b1) {
    asm volatile(
        "mma.sync.aligned.m16n8k16.row.col.f32.f16.f16.f32 "
        "{%0,%1,%2,%3}, {%4,%5,%6,%7}, {%8,%9}, {%0,%1,%2,%3};\n"
        : "+f"(d[0]), "+f"(d[1]), "+f"(d[2]), "+f"(d[3])
        : "r"(a[0]), "r"(a[1]), "r"(a[2]), "r"(a[3]), "r"(b0), "r"(b1));
}

__device__ __forceinline__ void ldsm_x4(unsigned* r, uint32_t a) {
    asm volatile("ldmatrix.sync.aligned.m8n8.x4.shared.b16 {%0,%1,%2,%3}, [%4];"
        : "=r"(r[0]), "=r"(r[1]), "=r"(r[2]), "=r"(r[3]) : "r"(a));
}
__device__ __forceinline__ void ldsm_x4t(unsigned* r, uint32_t a) {
    asm volatile("ldmatrix.sync.aligned.m8n8.x4.trans.shared.b16 {%0,%1,%2,%3}, [%4];"
        : "=r"(r[0]), "=r"(r[1]), "=r"(r[2]), "=r"(r[3]) : "r"(a));
}

__device__ __forceinline__ void cp16h(__half* dst, const __half* src) {
    unsigned s = (unsigned)__cvta_generic_to_shared(dst);
    asm volatile("cp.async.cg.shared.global [%0], [%1], 16;\n" :: "r"(s), "l"(src));
}

__device__ __forceinline__ unsigned packh2(float a, float b) {
    __half2 h = __floats2half2_rn(a, b);
    return *(unsigned*)&h;
}

// ---------------- one-shot weight + bias prep (single launch) ----------------
__global__ void prep_weights(const float* __restrict__ Wq, const float* __restrict__ Wk,
                             const float* __restrict__ Wv, const float* __restrict__ Wo,
                             const float* __restrict__ W1, const float* __restrict__ W2,
                             const float* __restrict__ bq, const float* __restrict__ bk,
                             const float* __restrict__ bv,
                             __half* __restrict__ wqkv, __half* __restrict__ wo,
                             __half* __restrict__ w1,   __half* __restrict__ w2,
                             float* __restrict__ bqkv) {
    int bid = blockIdx.x;
    if (bid >= 12288) {   // bias concat blocks
        int i = (bid - 12288) * 256 + threadIdx.y * 32 + threadIdx.x;
        if (i < H3) {
            const float* src = (i < HH) ? bq : (i < 2*HH) ? bk : bv;
            bqkv[i] = src[i & (HH - 1)];
        }
        return;
    }
    __shared__ float t[32][33];
    const float* src; __half* dst; int K, N, b0i;
    if      (bid < 1024) { src = Wq; dst = wqkv;           K = HH;  N = HH;  b0i = 0;    }
    else if (bid < 2048) { src = Wk; dst = wqkv + HH*HH;   K = HH;  N = HH;  b0i = 1024; }
    else if (bid < 3072) { src = Wv; dst = wqkv + 2*HH*HH; K = HH;  N = HH;  b0i = 2048; }
    else if (bid < 4096) { src = Wo; dst = wo;             K = HH;  N = HH;  b0i = 3072; }
    else if (bid < 8192) { src = W1; dst = w1;             K = HH;  N = FFF; b0i = 4096; }
    else                 { src = W2; dst = w2;             K = FFF; N = HH;  b0i = 8192; }
    int lb = bid - b0i;
    int gx = N / 32;
    int n0 = (lb % gx) * 32, k0 = (lb / gx) * 32;
    int x = threadIdx.x, y = threadIdx.y;     // 32 x 8
    #pragma unroll
    for (int i = 0; i < 32; i += 8)
        t[y + i][x] = src[(size_t)(k0 + y + i) * N + n0 + x];
    __syncthreads();
    #pragma unroll
    for (int i = 0; i < 32; i += 8)
        dst[(size_t)(n0 + y + i) * K + k0 + x] = __float2half_rn(t[x][y + i]);
}

// ---------------- layernorm (fp16 output) ------------------------------------
__device__ __forceinline__ float block_reduce_sum(float v) {
    __shared__ float sh[8];
    int lane = threadIdx.x & 31, w = threadIdx.x >> 5;
    #pragma unroll
    for (int o = 16; o > 0; o >>= 1) v += __shfl_xor_sync(0xffffffffu, v, o);
    if (lane == 0) sh[w] = v;
    __syncthreads();
    float t = (threadIdx.x < 8) ? sh[threadIdx.x] : 0.0f;
    if (w == 0) {
        #pragma unroll
        for (int o = 4; o > 0; o >>= 1) t += __shfl_xor_sync(0xffffffffu, t, o);
        if (lane == 0) sh[0] = t;
    }
    __syncthreads();
    float r = sh[0];
    __syncthreads();
    return r;
}

__global__ void ln_kernel(const float* __restrict__ x,
                          const float* __restrict__ g,
                          const float* __restrict__ be,
                          __half* __restrict__ out) {
    int row = blockIdx.x;
    int t = threadIdx.x;
    const float4* xr = (const float4*)(x + (size_t)row * HH);
    float4 v = xr[t];
    float s = v.x + v.y + v.z + v.w;
    float mu = block_reduce_sum(s) * (1.0f / HH);
    float dx = v.x - mu, dy = v.y - mu, dz = v.z - mu, dw = v.w - mu;
    float ss = dx*dx + dy*dy + dz*dz + dw*dw;
    float var = block_reduce_sum(ss) * (1.0f / HH);
    float rstd = rsqrtf(var + 1e-5f);
    float4 gg = ((const float4*)g)[t];
    float4 bb = ((const float4*)be)[t];
    __half2* orow = (__half2*)(out + (size_t)row * HH);
    orow[t*2]     = __floats2half2_rn(dx * rstd * gg.x + bb.x, dy * rstd * gg.y + bb.y);
    orow[t*2 + 1] = __floats2half2_rn(dz * rstd * gg.z + bb.z, dw * rstd * gg.w + bb.w);
}

// ---------------- fp16 tensor-core GEMM (4-stage, burst fragments) -----------
#define AHS 40                 // smem row stride in halfs (80B): conflict-free
#define NSTG 4
#define OPHS (128 * AHS)       // halfs per operand per stage
#define SMEMG (NSTG * 2 * OPHS * 2)   // bytes = 81920

template<int EPI, int OUTH>
__global__ void __launch_bounds__(256, 2)
gemmh(const __half* __restrict__ A, const __half* __restrict__ Bt,
      const float* __restrict__ bias, const float* __restrict__ res,
      void* __restrict__ Cv, int M, int N, int K) {
    extern __shared__ __half dsm[];
    __half* As = dsm;                 // [NSTG][128][AHS]
    __half* Bs = dsm + NSTG * OPHS;   // [NSTG][128][AHS]

    int tid = threadIdx.x, warp = tid >> 5, lane = tid & 31;
    int l8 = lane & 7;
    int gq = lane >> 2, t4 = lane & 3;
    int wm = warp & 3, wn = warp >> 2;
    int m0 = blockIdx.y * 128, n0 = blockIdx.x * 128;

    float acc[2][8][4] = {};
    int NC = K >> 5;

    uint32_t asb = (uint32_t)__cvta_generic_to_shared(As);
    uint32_t bsb = (uint32_t)__cvta_generic_to_shared(Bs);
    const uint32_t stgB = OPHS * 2;

    int a_r  = l8 + ((lane >> 3) & 1) * 8;
    int a_c8 = (lane >> 4) * 8;
    int b_n  = (lane >> 4) * 8 + l8;
    int b_c8 = ((lane >> 3) & 1) * 8;

    #define LOAD_CHUNK(ch) do {                                                 \
        int _s = (ch) % NSTG; int _k0 = (ch) * 32;                              \
        __half* _as = As + _s * OPHS; __half* _bs = Bs + _s * OPHS;             \
        _Pragma("unroll")                                                       \
        for (int _q = 0; _q < 2; _q++) {                                        \
            int _fid = tid + _q * 256;                                          \
            int _row = _fid >> 2, _seg = _fid & 3;                              \
            cp16h(_as + _row * AHS + _seg*8, A  + (size_t)(m0 + _row) * K + _k0 + _seg*8); \
            cp16h(_bs + _row * AHS + _seg*8, Bt + (size_t)(n0 + _row) * K + _k0 + _seg*8); \
        }                                                                       \
    } while (0)

    #pragma unroll
    for (int c = 0; c < NSTG - 1; c++) {
        LOAD_CHUNK(c);
        asm volatile("cp.async.commit_group;");
    }

    for (int c = 0; c < NC; c++) {
        asm volatile("cp.async.wait_group %0;" :: "n"(NSTG - 2));
        __syncthreads();

        if (c + NSTG - 1 < NC) LOAD_CHUNK(c + NSTG - 1);
        asm volatile("cp.async.commit_group;");

        uint32_t asc = asb + (uint32_t)(c % NSTG) * stgB;
        uint32_t bsc = bsb + (uint32_t)(c % NSTG) * stgB;
        #pragma unroll
        for (int ks = 0; ks < 2; ks++) {
            int kk = ks * 16;
            unsigned a[2][4], bf[4][4];
            #pragma unroll
            for (int mi = 0; mi < 2; mi++) {
                int row = wm * 32 + mi * 16 + a_r;
                ldsm_x4(a[mi], asc + (uint32_t)(row * AHS + kk + a_c8) * 2);
            }
            #pragma unroll
            for (int p = 0; p < 4; p++) {
                int row = wn * 64 + p * 16 + b_n;
                ldsm_x4(bf[p], bsc + (uint32_t)(row * AHS + kk + b_c8) * 2);
            }
            #pragma unroll
            for (int p = 0; p < 4; p++) {
                mma_h(acc[0][2*p],     a[0], bf[p][0], bf[p][1]);
                mma_h(acc[1][2*p],     a[1], bf[p][0], bf[p][1]);
                mma_h(acc[0][2*p + 1], a[0], bf[p][2], bf[p][3]);
                mma_h(acc[1][2*p + 1], a[1], bf[p][2], bf[p][3]);
            }
        }
    }
    #undef LOAD_CHUNK

    // epilogue
    #pragma unroll
    for (int mi = 0; mi < 2; mi++) {
        int row = m0 + wm * 32 + mi * 16 + gq;
        #pragma unroll
        for (int nj = 0; nj < 8; nj++) {
            int col = n0 + wn * 64 + nj * 8 + 2*t4;
            float b0 = bias[col], b1 = bias[col + 1];
            float v0 = acc[mi][nj][0] + b0;
            float v1 = acc[mi][nj][1] + b1;
            float v2 = acc[mi][nj][2] + b0;
            float v3 = acc[mi][nj][3] + b1;
            if (EPI == 1) {
                v0 = gelu_exact(v0); v1 = gelu_exact(v1);
                v2 = gelu_exact(v2); v3 = gelu_exact(v3);
            }
            if (EPI == 2) {
                float2 r0 = *(const float2*)(res + (size_t)row * N + col);
                float2 r1 = *(const float2*)(res + (size_t)(row + 8) * N + col);
                v0 += r0.x; v1 += r0.y; v2 += r1.x; v3 += r1.y;
            }
            if (OUTH) {
                __half* C = (__half*)Cv;
                *(__half2*)(C + (size_t)row * N + col) = __floats2half2_rn(v0, v1);
                *(__half2*)(C + (size_t)(row + 8) * N + col) = __floats2half2_rn(v2, v3);
            } else {
                float* C = (float*)Cv;
                *(float2*)(C + (size_t)row * N + col)       = make_float2(v0, v1);
                *(float2*)(C + (size_t)(row + 8) * N + col) = make_float2(v2, v3);
            }
        }
    }
}

// ---------------- fp16 flash attention (causal, double-buffered) -------------
// Br=128 (8 warps x 16 rows), Bc=64. Q pre-scaled by 1/8 (exact in fp16).
#define FVS 72

__global__ void __launch_bounds__(256, 2)
flash_h(const __half* __restrict__ QKV, __half* __restrict__ O) {
    __shared__ __half Ks[2][64][FVS];
    __shared__ __half Vs[2][64][FVS];

    int tid = threadIdx.x, warp = tid >> 5, lane = tid & 31;
    int l8 = lane & 7;
    int gq = lane >> 2, t4 = lane & 3;
    int qt = gridDim.x - 1 - blockIdx.x;          // heavy tiles first
    int bh = blockIdx.y, b = bh >> 4, h = bh & 15;
    size_t rowbase = (size_t)b * SS * H3;
    int qoff = h * 64, koff = HH + h * 64, voff = 2 * HH + h * 64;
    int qbase = qt * 128 + warp * 16;

    uint32_t ksb = (uint32_t)__cvta_generic_to_shared(&Ks[0][0][0]);
    uint32_t vsb = (uint32_t)__cvta_generic_to_shared(&Vs[0][0][0]);
    const uint32_t fstgB = 64 * FVS * 2;

    int b_n  = (lane >> 4) * 8 + l8;
    int b_c8 = ((lane >> 3) & 1) * 8;
    int v_r  = ((lane >> 3) & 1) * 8 + l8;
    int v_d  = (lane >> 4) * 8;

    #define FLOAD(j) do {                                                        \
        int _s = (j) & 1;                                                        \
        _Pragma("unroll")                                                        \
        for (int _it = 0; _it < 2; _it++) {                                      \
            int _fid = tid + _it * 256;                                          \
            int _r = _fid >> 3, _sg = _fid & 7;                                  \
            cp16h(&Ks[_s][_r][_sg*8],                                            \
                  QKV + rowbase + (size_t)((j)*64 + _r) * H3 + koff + _sg*8);    \
            cp16h(&Vs[_s][_r][_sg*8],                                            \
                  QKV + rowbase + (size_t)((j)*64 + _r) * H3 + voff + _sg*8);    \
        }                                                                        \
    } while (0)

    // Q fragments, pre-scaled by 1/8 (exponent shift; exact in fp16)
    const __half2 hscale = __float2half2_rn(0.125f);
    unsigned qf[4][4];
    #pragma unroll
    for (int kc = 0; kc < 4; kc++) {
        const __half* q0 = QKV + rowbase + (size_t)(qbase + gq)     * H3 + qoff + kc*16 + 2*t4;
        const __half* q1 = QKV + rowbase + (size_t)(qbase + gq + 8) * H3 + qoff + kc*16 + 2*t4;
        __half2 h0 = __hmul2(*(const __half2*)q0,       hscale);
        __half2 h1 = __hmul2(*(const __half2*)q1,       hscale);
        __half2 h2 = __hmul2(*(const __half2*)(q0 + 8), hscale);
        __half2 h3 = __hmul2(*(const __half2*)(q1 + 8), hscale);
        qf[kc][0] = *(unsigned*)&h0;
        qf[kc][1] = *(unsigned*)&h1;
        qf[kc][2] = *(unsigned*)&h2;
        qf[kc][3] = *(unsigned*)&h3;
    }

    float oacc[8][4] = {};
    float m0 = -1e30f, m1 = -1e30f, l0 = 0.0f, l1 = 0.0f;
    int row0 = qbase + gq, row1 = qbase + gq + 8;

    int jmax = 2 * qt + 1;
    FLOAD(0);
    asm volatile("cp.async.commit_group;");

    for (int j = 0; j <= jmax; j++) {
        asm volatile("cp.async.wait_group 0;");
        __syncthreads();

        if (j < jmax) FLOAD(j + 1);
        asm volatile("cp.async.commit_group;");

        if (j * 64 <= qbase + 15) {
            uint32_t ksj = ksb + (uint32_t)(j & 1) * fstgB;
            uint32_t vsj = vsb + (uint32_t)(j & 1) * fstgB;

            float s[8][4] = {};
            #pragma unroll
            for (int kc = 0; kc < 4; kc++) {
                #pragma unroll
                for (int p = 0; p < 4; p++) {
                    unsigned kb[4];
                    int row = p * 16 + b_n;
                    ldsm_x4(kb, ksj + (uint32_t)(row * FVS + kc*16 + b_c8) * 2);
                    mma_h(s[2*p],     qf[kc], kb[0], kb[1]);
                    mma_h(s[2*p + 1], qf[kc], kb[2], kb[3]);
                }
            }

            float mt0 = -1e30f, mt1 = -1e30f;
            if (j * 64 + 63 > qbase) {
                // diagonal tile (at most one per warp): element mask
                #pragma unroll
                for (int nj = 0; nj < 8; nj++) {
                    int c0 = j*64 + nj*8 + 2*t4, c1 = c0 + 1;
                    if (c0 > row0) s[nj][0] = -1e30f;
                    if (c1 > row0) s[nj][1] = -1e30f;
                    if (c0 > row1) s[nj][2] = -1e30f;
                    if (c1 > row1) s[nj][3] = -1e30f;
                    mt0 = fmaxf(mt0, fmaxf(s[nj][0], s[nj][1]));
                    mt1 = fmaxf(mt1, fmaxf(s[nj][2], s[nj][3]));
                }
            } else {
                // fully-unmasked tile: branch-free max
                #pragma unroll
                for (int nj = 0; nj < 8; nj++) {
                    mt0 = fmaxf(mt0, fmaxf(s[nj][0], s[nj][1]));
                    mt1 = fmaxf(mt1, fmaxf(s[nj][2], s[nj][3]));
                }
            }
            mt0 = fmaxf(mt0, __shfl_xor_sync(0xffffffffu, mt0, 1));
            mt0 = fmaxf(mt0, __shfl_xor_sync(0xffffffffu, mt0, 2));
            mt1 = fmaxf(mt1, __shfl_xor_sync(0xffffffffu, mt1, 1));
            mt1 = fmaxf(mt1, __shfl_xor_sync(0xffffffffu, mt1, 2));

            float nm0 = fmaxf(m0, mt0), nm1 = fmaxf(m1, mt1);
            float co0 = __expf(m0 - nm0), co1 = __expf(m1 - nm1);
            m0 = nm0; m1 = nm1;

            float rs0 = 0.0f, rs1 = 0.0f;
            #pragma unroll
            for (int nj = 0; nj < 8; nj++) {
                float p0 = __expf(s[nj][0] - nm0);
                float p1 = __expf(s[nj][1] - nm0);
                float p2 = __expf(s[nj][2] - nm1);
                float p3 = __expf(s[nj][3] - nm1);
                s[nj][0] = p0; s[nj][1] = p1; s[nj][2] = p2; s[nj][3] = p3;
                rs0 += p0 + p1; rs1 += p2 + p3;
            }
            rs0 += __shfl_xor_sync(0xffffffffu, rs0, 1);
            rs0 += __shfl_xor_sync(0xffffffffu, rs0, 2);
            rs1 += __shfl_xor_sync(0xffffffffu, rs1, 1);
            rs1 += __shfl_xor_sync(0xffffffffu, rs1, 2);
            l0 = l0 * co0 + rs0;
            l1 = l1 * co1 + rs1;

            #pragma unroll
            for (int nd = 0; nd < 8; nd++) {
                oacc[nd][0] *= co0; oacc[nd][1] *= co0;
                oacc[nd][2] *= co1; oacc[nd][3] *= co1;
            }

            #pragma unroll
            for (int kc = 0; kc < 4; kc++) {
                unsigned pa[4];
                pa[0] = packh2(s[2*kc][0],     s[2*kc][1]);
                pa[1] = packh2(s[2*kc][2],     s[2*kc][3]);
                pa[2] = packh2(s[2*kc + 1][0], s[2*kc + 1][1]);
                pa[3] = packh2(s[2*kc + 1][2], s[2*kc + 1][3]);
                #pragma unroll
                for (int p = 0; p < 4; p++) {
                    unsigned vb[4];
                    int row = kc * 16 + v_r;
                    ldsm_x4t(vb, vsj + (uint32_t)(row * FVS + p * 16 + v_d) * 2);
                    mma_h(oacc[2*p],     pa, vb[0], vb[1]);
                    mma_h(oacc[2*p + 1], pa, vb[2], vb[3]);
                }
            }
        }
    }
    #undef FLOAD

    float inv0 = 1.0f / l0, inv1 = 1.0f / l1;
    size_t obase = (size_t)(b * SS) * HH + h * 64;
    #pragma unroll
    for (int nd = 0; nd < 8; nd++) {
        *(__half2*)(O + obase + (size_t)row0 * HH + nd*8 + 2*t4) =
            __floats2half2_rn(oacc[nd][0] * inv0, oacc[nd][1] * inv0);
        *(__half2*)(O + obase + (size_t)row1 * HH + nd*8 + 2*t4) =
            __floats2half2_rn(oacc[nd][2] * inv1, oacc[nd][3] * inv1);
    }
}

// ---------------- launch ----------------------------------------------------
extern "C" void kernel_launch(void* const* d_in, const int* in_sizes, int n_in,
                              void* d_out, int out_size) {
    const float* x   = (const float*)d_in[0];
    const float* Wq  = (const float*)d_in[1];
    const float* bq  = (const float*)d_in[2];
    const float* Wk  = (const float*)d_in[3];
    const float* bk  = (const float*)d_in[4];
    const float* Wv  = (const float*)d_in[5];
    const float* bv  = (const float*)d_in[6];
    const float* Wo  = (const float*)d_in[7];
    const float* bo  = (const float*)d_in[8];
    const float* W1  = (const float*)d_in[9];
    const float* b1  = (const float*)d_in[10];
    const float* W2  = (const float*)d_in[11];
    const float* b2  = (const float*)d_in[12];
    const float* g1  = (const float*)d_in[13];
    const float* be1 = (const float*)d_in[14];
    const float* g2  = (const float*)d_in[15];
    const float* be2 = (const float*)d_in[16];
    float* out = (float*)d_out;

    __half *p_ln1h, *p_qkvh, *p_attnh, *p_ln2h, *p_midh;
    __half *p_wqkvh, *p_woh, *p_w1h, *p_w2h;
    float *p_xatt, *p_bqkv;
    cudaGetSymbolAddress((void**)&p_ln1h,  g_ln1h);
    cudaGetSymbolAddress((void**)&p_qkvh,  g_qkvh);
    cudaGetSymbolAddress((void**)&p_attnh, g_attnh);
    cudaGetSymbolAddress((void**)&p_xatt,  g_xatt);
    cudaGetSymbolAddress((void**)&p_ln2h,  g_ln2h);
    cudaGetSymbolAddress((void**)&p_midh,  g_midh);
    cudaGetSymbolAddress((void**)&p_wqkvh, g_wqkvh);
    cudaGetSymbolAddress((void**)&p_woh,   g_woh);
    cudaGetSymbolAddress((void**)&p_w1h,   g_w1h);
    cudaGetSymbolAddress((void**)&p_w2h,   g_w2h);
    cudaGetSymbolAddress((void**)&p_bqkv,  g_bqkv);

    cudaFuncSetAttribute(gemmh<0,1>, cudaFuncAttributeMaxDynamicSharedMemorySize, SMEMG);
    cudaFuncSetAttribute(gemmh<1,1>, cudaFuncAttributeMaxDynamicSharedMemorySize, SMEMG);
    cudaFuncSetAttribute(gemmh<2,0>, cudaFuncAttributeMaxDynamicSharedMemorySize, SMEMG);

    // 0) weight + bias prep in one launch
    prep_weights<<<12300, dim3(32, 8)>>>(Wq, Wk, Wv, Wo, W1, W2, bq, bk, bv,
                                         p_wqkvh, p_woh, p_w1h, p_w2h, p_bqkv);

    // 1) LN1 -> fp16
    ln_kernel<<<MM, 256>>>(x, g1, be1, p_ln1h);

    // 2) fused QKV projection
    gemmh<0,1><<<dim3(H3/128, MM/128), 256, SMEMG>>>(p_ln1h, p_wqkvh, p_bqkv, nullptr,
                                                     p_qkvh, MM, H3, HH);

    // 3) fp16 causal flash attention
    flash_h<<<dim3(SS/128, BB*NHH), 256>>>(p_qkvh, p_attnh);

    // 4) O projection + residual (fp32 out)
    gemmh<2,0><<<dim3(HH/128, MM/128), 256, SMEMG>>>(p_attnh, p_woh, bo, x,
                                                     p_xatt, MM, HH, HH);

    // 5) LN2 -> fp16
    ln_kernel<<<MM, 256>>>(p_xatt, g2, be2, p_ln2h);

    // 6) FFN up + exact GELU (fp16 out)
    gemmh<1,1><<<dim3(FFF/128, MM/128), 256, SMEMG>>>(p_ln2h, p_w1h, b1, nullptr,
                                                      p_midh, MM, FFF, HH);

    // 7) FFN down + residual (fp32 out)
    gemmh<2,0><<<dim3(HH/128, MM/128), 256, SMEMG>>>(p_midh, p_w2h, b2, p_xatt,
                                                     out, MM, HH, FFF);
}

// round 10
// speedup vs baseline: 6.7916x; 1.0728x over previous
#include <cuda_runtime.h>
#include <cuda_fp16.h>
#include <math.h>
#include <stdint.h>

// Problem dims (fixed)
#define BB 2
#define SS 2048
#define HH 1024
#define NHH 16
#define DHH 64
#define FFF 4096
#define MM (BB*SS)   // 4096 tokens
#define H3 (3*HH)    // 3072

// ---------------- scratch (device globals; no allocation allowed) ----------
__device__ __half g_ln1h [MM*HH];
__device__ __half g_qkvh [MM*H3];
__device__ __half g_attnh[MM*HH];
__device__ float  g_xatt [MM*HH];
__device__ __half g_ln2h [MM*HH];
__device__ __half g_midh [MM*FFF];
// transposed fp16 weights, stored [N][K] (K-major)
__device__ __half g_wqkvh[H3*HH];
__device__ __half g_woh  [HH*HH];
__device__ __half g_w1h  [FFF*HH];
__device__ __half g_w2h  [HH*FFF];
__device__ float  g_bqkv [H3];

// ---------------- helpers ----------------------------------------------------
__device__ __forceinline__ float gelu_exact(float v) {
    return 0.5f * v * (1.0f + erff(v * 0.70710678118654752f));
}

__device__ __forceinline__ void mma_h(float* d, const unsigned* a,
                                      unsigned b0, unsigned b1) {
    asm volatile(
        "mma.sync.aligned.m16n8k16.row.col.f32.f16.f16.f32 "
        "{%0,%1,%2,%3}, {%4,%5,%6,%7}, {%8,%9}, {%0,%1,%2,%3};\n"
        : "+f"(d[0]), "+f"(d[1]), "+f"(d[2]), "+f"(d[3])
        : "r"(a[0]), "r"(a[1]), "r"(a[2]), "r"(a[3]), "r"(b0), "r"(b1));
}

__device__ __forceinline__ void ldsm_x4(unsigned* r, uint32_t a) {
    asm volatile("ldmatrix.sync.aligned.m8n8.x4.shared.b16 {%0,%1,%2,%3}, [%4];"
        : "=r"(r[0]), "=r"(r[1]), "=r"(r[2]), "=r"(r[3]) : "r"(a));
}
__device__ __forceinline__ void ldsm_x4t(unsigned* r, uint32_t a) {
    asm volatile("ldmatrix.sync.aligned.m8n8.x4.trans.shared.b16 {%0,%1,%2,%3}, [%4];"
        : "=r"(r[0]), "=r"(r[1]), "=r"(r[2]), "=r"(r[3]) : "r"(a));
}

__device__ __forceinline__ void cp16h(__half* dst, const __half* src) {
    unsigned s = (unsigned)__cvta_generic_to_shared(dst);
    asm volatile("cp.async.cg.shared.global [%0], [%1], 16;\n" :: "r"(s), "l"(src));
}

__device__ __forceinline__ unsigned packh2(float a, float b) {
    __half2 h = __floats2half2_rn(a, b);
    return *(unsigned*)&h;
}

// ---------------- one-shot weight + bias prep (single launch) ----------------
__global__ void prep_weights(const float* __restrict__ Wq, const float* __restrict__ Wk,
                             const float* __restrict__ Wv, const float* __restrict__ Wo,
                             const float* __restrict__ W1, const float* __restrict__ W2,
                             const float* __restrict__ bq, const float* __restrict__ bk,
                             const float* __restrict__ bv,
                             __half* __restrict__ wqkv, __half* __restrict__ wo,
                             __half* __restrict__ w1,   __half* __restrict__ w2,
                             float* __restrict__ bqkv) {
    int bid = blockIdx.x;
    if (bid >= 12288) {   // bias concat blocks
        int i = (bid - 12288) * 256 + threadIdx.y * 32 + threadIdx.x;
        if (i < H3) {
            const float* src = (i < HH) ? bq : (i < 2*HH) ? bk : bv;
            bqkv[i] = src[i & (HH - 1)];
        }
        return;
    }
    __shared__ float t[32][33];
    const float* src; __half* dst; int K, N, b0i;
    if      (bid < 1024) { src = Wq; dst = wqkv;           K = HH;  N = HH;  b0i = 0;    }
    else if (bid < 2048) { src = Wk; dst = wqkv + HH*HH;   K = HH;  N = HH;  b0i = 1024; }
    else if (bid < 3072) { src = Wv; dst = wqkv + 2*HH*HH; K = HH;  N = HH;  b0i = 2048; }
    else if (bid < 4096) { src = Wo; dst = wo;             K = HH;  N = HH;  b0i = 3072; }
    else if (bid < 8192) { src = W1; dst = w1;             K = HH;  N = FFF; b0i = 4096; }
    else                 { src = W2; dst = w2;             K = FFF; N = HH;  b0i = 8192; }
    int lb = bid - b0i;
    int gx = N / 32;
    int n0 = (lb % gx) * 32, k0 = (lb / gx) * 32;
    int x = threadIdx.x, y = threadIdx.y;     // 32 x 8
    #pragma unroll
    for (int i = 0; i < 32; i += 8)
        t[y + i][x] = src[(size_t)(k0 + y + i) * N + n0 + x];
    __syncthreads();
    #pragma unroll
    for (int i = 0; i < 32; i += 8)
        dst[(size_t)(n0 + y + i) * K + k0 + x] = __float2half_rn(t[x][y + i]);
}

// ---------------- layernorm (fp16 output) ------------------------------------
__device__ __forceinline__ float block_reduce_sum(float v) {
    __shared__ float sh[8];
    int lane = threadIdx.x & 31, w = threadIdx.x >> 5;
    #pragma unroll
    for (int o = 16; o > 0; o >>= 1) v += __shfl_xor_sync(0xffffffffu, v, o);
    if (lane == 0) sh[w] = v;
    __syncthreads();
    float t = (threadIdx.x < 8) ? sh[threadIdx.x] : 0.0f;
    if (w == 0) {
        #pragma unroll
        for (int o = 4; o > 0; o >>= 1) t += __shfl_xor_sync(0xffffffffu, t, o);
        if (lane == 0) sh[0] = t;
    }
    __syncthreads();
    float r = sh[0];
    __syncthreads();
    return r;
}

__global__ void ln_kernel(const float* __restrict__ x,
                          const float* __restrict__ g,
                          const float* __restrict__ be,
                          __half* __restrict__ out) {
    int row = blockIdx.x;
    int t = threadIdx.x;
    const float4* xr = (const float4*)(x + (size_t)row * HH);
    float4 v = xr[t];
    float s = v.x + v.y + v.z + v.w;
    float mu = block_reduce_sum(s) * (1.0f / HH);
    float dx = v.x - mu, dy = v.y - mu, dz = v.z - mu, dw = v.w - mu;
    float ss = dx*dx + dy*dy + dz*dz + dw*dw;
    float var = block_reduce_sum(ss) * (1.0f / HH);
    float rstd = rsqrtf(var + 1e-5f);
    float4 gg = ((const float4*)g)[t];
    float4 bb = ((const float4*)be)[t];
    __half2* orow = (__half2*)(out + (size_t)row * HH);
    orow[t*2]     = __floats2half2_rn(dx * rstd * gg.x + bb.x, dy * rstd * gg.y + bb.y);
    orow[t*2 + 1] = __floats2half2_rn(dz * rstd * gg.z + bb.z, dw * rstd * gg.w + bb.w);
}

// ---------------- fp16 tensor-core GEMM (64x64 warp tiles, 3-stage) ----------
// C[M,N] = A[M,K] @ Bt[N,K]^T + bias (+epilogue). 128 threads, 4 warps (2x2).
// EPI: 0 none, 1 exact GELU, 2 residual.  OUTH: 1 = fp16 output, 0 = fp32.
#define AHS 40                 // smem row stride in halfs (80B): conflict-free
#define NSTG 3
#define OPHS (128 * AHS)       // halfs per operand per stage
#define SMEMG (NSTG * 2 * OPHS * 2)   // bytes = 61440

template<int EPI, int OUTH>
__global__ void __launch_bounds__(128, 2)
gemmh(const __half* __restrict__ A, const __half* __restrict__ Bt,
      const float* __restrict__ bias, const float* __restrict__ res,
      void* __restrict__ Cv, int M, int N, int K) {
    extern __shared__ __half dsm[];
    __half* As = dsm;                 // [NSTG][128][AHS]
    __half* Bs = dsm + NSTG * OPHS;   // [NSTG][128][AHS]

    int tid = threadIdx.x, warp = tid >> 5, lane = tid & 31;
    int l8 = lane & 7;
    int gq = lane >> 2, t4 = lane & 3;
    int wmb = (warp >> 1) * 64, wnb = (warp & 1) * 64;   // warp origin in tile
    int m0 = blockIdx.y * 128, n0 = blockIdx.x * 128;

    float acc[4][8][4] = {};      // 4 m-frags x 8 n-frags x 4
    int NC = K >> 5;

    uint32_t asb = (uint32_t)__cvta_generic_to_shared(As);
    uint32_t bsb = (uint32_t)__cvta_generic_to_shared(Bs);
    const uint32_t stgB = OPHS * 2;

    int a_r  = l8 + ((lane >> 3) & 1) * 8;
    int a_c8 = (lane >> 4) * 8;
    int b_n  = (lane >> 4) * 8 + l8;
    int b_c8 = ((lane >> 3) & 1) * 8;

    // loader: 128 rows x 4 segs per operand, 128 threads -> 4 iters each
    #define LOAD_CHUNK(ch) do {                                                 \
        int _s = (ch) % NSTG; int _k0 = (ch) * 32;                              \
        __half* _as = As + _s * OPHS; __half* _bs = Bs + _s * OPHS;             \
        _Pragma("unroll")                                                       \
        for (int _q = 0; _q < 4; _q++) {                                        \
            int _fid = tid + _q * 128;                                          \
            int _row = _fid >> 2, _seg = _fid & 3;                              \
            cp16h(_as + _row * AHS + _seg*8, A  + (size_t)(m0 + _row) * K + _k0 + _seg*8); \
            cp16h(_bs + _row * AHS + _seg*8, Bt + (size_t)(n0 + _row) * K + _k0 + _seg*8); \
        }                                                                       \
    } while (0)

    // prologue: stages 0..NSTG-2
    #pragma unroll
    for (int c = 0; c < NSTG - 1; c++) {
        LOAD_CHUNK(c);
        asm volatile("cp.async.commit_group;");
    }

    for (int c = 0; c < NC; c++) {
        asm volatile("cp.async.wait_group %0;" :: "n"(NSTG - 2));
        __syncthreads();

        if (c + NSTG - 1 < NC) LOAD_CHUNK(c + NSTG - 1);
        asm volatile("cp.async.commit_group;");

        uint32_t asc = asb + (uint32_t)(c % NSTG) * stgB;
        uint32_t bsc = bsb + (uint32_t)(c % NSTG) * stgB;
        #pragma unroll
        for (int ks = 0; ks < 2; ks++) {
            int kk = ks * 16;
            // burst all 8 ldsm for this k-step ...
            unsigned a[4][4], bf[4][4];
            #pragma unroll
            for (int mi = 0; mi < 4; mi++) {
                int row = wmb + mi * 16 + a_r;
                ldsm_x4(a[mi], asc + (uint32_t)(row * AHS + kk + a_c8) * 2);
            }
            #pragma unroll
            for (int p = 0; p < 4; p++) {
                int row = wnb + p * 16 + b_n;
                ldsm_x4(bf[p], bsc + (uint32_t)(row * AHS + kk + b_c8) * 2);
            }
            // ... then 32 MMAs back-to-back
            #pragma unroll
            for (int p = 0; p < 4; p++) {
                #pragma unroll
                for (int mi = 0; mi < 4; mi++) {
                    mma_h(acc[mi][2*p],     a[mi], bf[p][0], bf[p][1]);
                    mma_h(acc[mi][2*p + 1], a[mi], bf[p][2], bf[p][3]);
                }
            }
        }
    }
    #undef LOAD_CHUNK

    // epilogue: warp writes its 64x64 block
    #pragma unroll
    for (int mi = 0; mi < 4; mi++) {
        int row = m0 + wmb + mi * 16 + gq;
        #pragma unroll
        for (int nj = 0; nj < 8; nj++) {
            int col = n0 + wnb + nj * 8 + 2*t4;
            float b0 = bias[col], b1 = bias[col + 1];
            float v0 = acc[mi][nj][0] + b0;
            float v1 = acc[mi][nj][1] + b1;
            float v2 = acc[mi][nj][2] + b0;
            float v3 = acc[mi][nj][3] + b1;
            if (EPI == 1) {
                v0 = gelu_exact(v0); v1 = gelu_exact(v1);
                v2 = gelu_exact(v2); v3 = gelu_exact(v3);
            }
            if (EPI == 2) {
                float2 r0 = *(const float2*)(res + (size_t)row * N + col);
                float2 r1 = *(const float2*)(res + (size_t)(row + 8) * N + col);
                v0 += r0.x; v1 += r0.y; v2 += r1.x; v3 += r1.y;
            }
            if (OUTH) {
                __half* C = (__half*)Cv;
                *(__half2*)(C + (size_t)row * N + col) = __floats2half2_rn(v0, v1);
                *(__half2*)(C + (size_t)(row + 8) * N + col) = __floats2half2_rn(v2, v3);
            } else {
                float* C = (float*)Cv;
                *(float2*)(C + (size_t)row * N + col)       = make_float2(v0, v1);
                *(float2*)(C + (size_t)(row + 8) * N + col) = make_float2(v2, v3);
            }
        }
    }
}

// ---------------- fp16 flash attention (causal, double-buffered) -------------
// Br=128 (8 warps x 16 rows), Bc=64. Q pre-scaled by 1/8 (exact in fp16).
#define FVS 72

__global__ void __launch_bounds__(256, 2)
flash_h(const __half* __restrict__ QKV, __half* __restrict__ O) {
    __shared__ __half Ks[2][64][FVS];
    __shared__ __half Vs[2][64][FVS];

    int tid = threadIdx.x, warp = tid >> 5, lane = tid & 31;
    int l8 = lane & 7;
    int gq = lane >> 2, t4 = lane & 3;
    int qt = gridDim.x - 1 - blockIdx.x;          // heavy tiles first
    int bh = blockIdx.y, b = bh >> 4, h = bh & 15;
    size_t rowbase = (size_t)b * SS * H3;
    int qoff = h * 64, koff = HH + h * 64, voff = 2 * HH + h * 64;
    int qbase = qt * 128 + warp * 16;

    uint32_t ksb = (uint32_t)__cvta_generic_to_shared(&Ks[0][0][0]);
    uint32_t vsb = (uint32_t)__cvta_generic_to_shared(&Vs[0][0][0]);
    const uint32_t fstgB = 64 * FVS * 2;

    int b_n  = (lane >> 4) * 8 + l8;
    int b_c8 = ((lane >> 3) & 1) * 8;
    int v_r  = ((lane >> 3) & 1) * 8 + l8;
    int v_d  = (lane >> 4) * 8;

    #define FLOAD(j) do {                                                        \
        int _s = (j) & 1;                                                        \
        _Pragma("unroll")                                                        \
        for (int _it = 0; _it < 2; _it++) {                                      \
            int _fid = tid + _it * 256;                                          \
            int _r = _fid >> 3, _sg = _fid & 7;                                  \
            cp16h(&Ks[_s][_r][_sg*8],                                            \
                  QKV + rowbase + (size_t)((j)*64 + _r) * H3 + koff + _sg*8);    \
            cp16h(&Vs[_s][_r][_sg*8],                                            \
                  QKV + rowbase + (size_t)((j)*64 + _r) * H3 + voff + _sg*8);    \
        }                                                                        \
    } while (0)

    const __half2 hscale = __float2half2_rn(0.125f);
    unsigned qf[4][4];
    #pragma unroll
    for (int kc = 0; kc < 4; kc++) {
        const __half* q0 = QKV + rowbase + (size_t)(qbase + gq)     * H3 + qoff + kc*16 + 2*t4;
        const __half* q1 = QKV + rowbase + (size_t)(qbase + gq + 8) * H3 + qoff + kc*16 + 2*t4;
        __half2 h0 = __hmul2(*(const __half2*)q0,       hscale);
        __half2 h1 = __hmul2(*(const __half2*)q1,       hscale);
        __half2 h2 = __hmul2(*(const __half2*)(q0 + 8), hscale);
        __half2 h3 = __hmul2(*(const __half2*)(q1 + 8), hscale);
        qf[kc][0] = *(unsigned*)&h0;
        qf[kc][1] = *(unsigned*)&h1;
        qf[kc][2] = *(unsigned*)&h2;
        qf[kc][3] = *(unsigned*)&h3;
    }

    float oacc[8][4] = {};
    float m0 = -1e30f, m1 = -1e30f, l0 = 0.0f, l1 = 0.0f;
    int row0 = qbase + gq, row1 = qbase + gq + 8;

    int jmax = 2 * qt + 1;
    FLOAD(0);
    asm volatile("cp.async.commit_group;");

    for (int j = 0; j <= jmax; j++) {
        asm volatile("cp.async.wait_group 0;");
        __syncthreads();

        if (j < jmax) FLOAD(j + 1);
        asm volatile("cp.async.commit_group;");

        if (j * 64 <= qbase + 15) {
            uint32_t ksj = ksb + (uint32_t)(j & 1) * fstgB;
            uint32_t vsj = vsb + (uint32_t)(j & 1) * fstgB;

            float s[8][4] = {};
            #pragma unroll
            for (int kc = 0; kc < 4; kc++) {
                #pragma unroll
                for (int p = 0; p < 4; p++) {
                    unsigned kb[4];
                    int row = p * 16 + b_n;
                    ldsm_x4(kb, ksj + (uint32_t)(row * FVS + kc*16 + b_c8) * 2);
                    mma_h(s[2*p],     qf[kc], kb[0], kb[1]);
                    mma_h(s[2*p + 1], qf[kc], kb[2], kb[3]);
                }
            }

            float mt0 = -1e30f, mt1 = -1e30f;
            if (j * 64 + 63 > qbase) {
                #pragma unroll
                for (int nj = 0; nj < 8; nj++) {
                    int c0 = j*64 + nj*8 + 2*t4, c1 = c0 + 1;
                    if (c0 > row0) s[nj][0] = -1e30f;
                    if (c1 > row0) s[nj][1] = -1e30f;
                    if (c0 > row1) s[nj][2] = -1e30f;
                    if (c1 > row1) s[nj][3] = -1e30f;
                    mt0 = fmaxf(mt0, fmaxf(s[nj][0], s[nj][1]));
                    mt1 = fmaxf(mt1, fmaxf(s[nj][2], s[nj][3]));
                }
            } else {
                #pragma unroll
                for (int nj = 0; nj < 8; nj++) {
                    mt0 = fmaxf(mt0, fmaxf(s[nj][0], s[nj][1]));
                    mt1 = fmaxf(mt1, fmaxf(s[nj][2], s[nj][3]));
                }
            }
            mt0 = fmaxf(mt0, __shfl_xor_sync(0xffffffffu, mt0, 1));
            mt0 = fmaxf(mt0, __shfl_xor_sync(0xffffffffu, mt0, 2));
            mt1 = fmaxf(mt1, __shfl_xor_sync(0xffffffffu, mt1, 1));
            mt1 = fmaxf(mt1, __shfl_xor_sync(0xffffffffu, mt1, 2));

            float nm0 = fmaxf(m0, mt0), nm1 = fmaxf(m1, mt1);
            float co0 = __expf(m0 - nm0), co1 = __expf(m1 - nm1);
            m0 = nm0; m1 = nm1;

            float rs0 = 0.0f, rs1 = 0.0f;
            #pragma unroll
            for (int nj = 0; nj < 8; nj++) {
                float p0 = __expf(s[nj][0] - nm0);
                float p1 = __expf(s[nj][1] - nm0);
                float p2 = __expf(s[nj][2] - nm1);
                float p3 = __expf(s[nj][3] - nm1);
                s[nj][0] = p0; s[nj][1] = p1; s[nj][2] = p2; s[nj][3] = p3;
                rs0 += p0 + p1; rs1 += p2 + p3;
            }
            rs0 += __shfl_xor_sync(0xffffffffu, rs0, 1);
            rs0 += __shfl_xor_sync(0xffffffffu, rs0, 2);
            rs1 += __shfl_xor_sync(0xffffffffu, rs1, 1);
            rs1 += __shfl_xor_sync(0xffffffffu, rs1, 2);
            l0 = l0 * co0 + rs0;
            l1 = l1 * co1 + rs1;

            #pragma unroll
            for (int nd = 0; nd < 8; nd++) {
                oacc[nd][0] *= co0; oacc[nd][1] *= co0;
                oacc[nd][2] *= co1; oacc[nd][3] *= co1;
            }

            #pragma unroll
            for (int kc = 0; kc < 4; kc++) {
                unsigned pa[4];
                pa[0] = packh2(s[2*kc][0],     s[2*kc][1]);
                pa[1] = packh2(s[2*kc][2],     s[2*kc][3]);
                pa[2] = packh2(s[2*kc + 1][0], s[2*kc + 1][1]);
                pa[3] = packh2(s[2*kc + 1][2], s[2*kc + 1][3]);
                #pragma unroll
                for (int p = 0; p < 4; p++) {
                    unsigned vb[4];
                    int row = kc * 16 + v_r;
                    ldsm_x4t(vb, vsj + (uint32_t)(row * FVS + p * 16 + v_d) * 2);
                    mma_h(oacc[2*p],     pa, vb[0], vb[1]);
                    mma_h(oacc[2*p + 1], pa, vb[2], vb[3]);
                }
            }
        }
    }
    #undef FLOAD

    float inv0 = 1.0f / l0, inv1 = 1.0f / l1;
    size_t obase = (size_t)(b * SS) * HH + h * 64;
    #pragma unroll
    for (int nd = 0; nd < 8; nd++) {
        *(__half2*)(O + obase + (size_t)row0 * HH + nd*8 + 2*t4) =
            __floats2half2_rn(oacc[nd][0] * inv0, oacc[nd][1] * inv0);
        *(__half2*)(O + obase + (size_t)row1 * HH + nd*8 + 2*t4) =
            __floats2half2_rn(oacc[nd][2] * inv1, oacc[nd][3] * inv1);
    }
}

// ---------------- launch ----------------------------------------------------
extern "C" void kernel_launch(void* const* d_in, const int* in_sizes, int n_in,
                              void* d_out, int out_size) {
    const float* x   = (const float*)d_in[0];
    const float* Wq  = (const float*)d_in[1];
    const float* bq  = (const float*)d_in[2];
    const float* Wk  = (const float*)d_in[3];
    const float* bk  = (const float*)d_in[4];
    const float* Wv  = (const float*)d_in[5];
    const float* bv  = (const float*)d_in[6];
    const float* Wo  = (const float*)d_in[7];
    const float* bo  = (const float*)d_in[8];
    const float* W1  = (const float*)d_in[9];
    const float* b1  = (const float*)d_in[10];
    const float* W2  = (const float*)d_in[11];
    const float* b2  = (const float*)d_in[12];
    const float* g1  = (const float*)d_in[13];
    const float* be1 = (const float*)d_in[14];
    const float* g2  = (const float*)d_in[15];
    const float* be2 = (const float*)d_in[16];
    float* out = (float*)d_out;

    __half *p_ln1h, *p_qkvh, *p_attnh, *p_ln2h, *p_midh;
    __half *p_wqkvh, *p_woh, *p_w1h, *p_w2h;
    float *p_xatt, *p_bqkv;
    cudaGetSymbolAddress((void**)&p_ln1h,  g_ln1h);
    cudaGetSymbolAddress((void**)&p_qkvh,  g_qkvh);
    cudaGetSymbolAddress((void**)&p_attnh, g_attnh);
    cudaGetSymbolAddress((void**)&p_xatt,  g_xatt);
    cudaGetSymbolAddress((void**)&p_ln2h,  g_ln2h);
    cudaGetSymbolAddress((void**)&p_midh,  g_midh);
    cudaGetSymbolAddress((void**)&p_wqkvh, g_wqkvh);
    cudaGetSymbolAddress((void**)&p_woh,   g_woh);
    cudaGetSymbolAddress((void**)&p_w1h,   g_w1h);
    cudaGetSymbolAddress((void**)&p_w2h,   g_w2h);
    cudaGetSymbolAddress((void**)&p_bqkv,  g_bqkv);

    cudaFuncSetAttribute(gemmh<0,1>, cudaFuncAttributeMaxDynamicSharedMemorySize, SMEMG);
    cudaFuncSetAttribute(gemmh<1,1>, cudaFuncAttributeMaxDynamicSharedMemorySize, SMEMG);
    cudaFuncSetAttribute(gemmh<2,0>, cudaFuncAttributeMaxDynamicSharedMemorySize, SMEMG);

    // 0) weight + bias prep in one launch
    prep_weights<<<12300, dim3(32, 8)>>>(Wq, Wk, Wv, Wo, W1, W2, bq, bk, bv,
                                         p_wqkvh, p_woh, p_w1h, p_w2h, p_bqkv);

    // 1) LN1 -> fp16
    ln_kernel<<<MM, 256>>>(x, g1, be1, p_ln1h);

    // 2) fused QKV projection
    gemmh<0,1><<<dim3(H3/128, MM/128), 128, SMEMG>>>(p_ln1h, p_wqkvh, p_bqkv, nullptr,
                                                     p_qkvh, MM, H3, HH);

    // 3) fp16 causal flash attention
    flash_h<<<dim3(SS/128, BB*NHH), 256>>>(p_qkvh, p_attnh);

    // 4) O projection + residual (fp32 out)
    gemmh<2,0><<<dim3(HH/128, MM/128), 128, SMEMG>>>(p_attnh, p_woh, bo, x,
                                                     p_xatt, MM, HH, HH);

    // 5) LN2 -> fp16
    ln_kernel<<<MM, 256>>>(p_xatt, g2, be2, p_ln2h);

    // 6) FFN up + exact GELU (fp16 out)
    gemmh<1,1><<<dim3(FFF/128, MM/128), 128, SMEMG>>>(p_ln2h, p_w1h, b1, nullptr,
                                                      p_midh, MM, FFF, HH);

    // 7) FFN down + residual (fp32 out)
    gemmh<2,0><<<dim3(HH/128, MM/128), 128, SMEMG>>>(p_midh, p_w2h, b2, p_xatt,
                                                     out, MM, HH, FFF);
}